// round 5
// baseline (speedup 1.0000x reference)
#include <cuda_runtime.h>
#include <cuda_bf16.h>
#include <cstdint>

// ---------------- problem constants ----------------
#define NNODE 16000
#define NEDGE 128000
#define GATD 768          // GAT dim
#define XD 800            // meta-in dim (768 gat + 32 node)
#define XDP 832           // padded K for GEMM2 (26 x 32)
#define MD 128            // meta out dim
#define PD 384            // P1(dst part) | P2(src part) | Xself

// ---------------- device scratch (no allocs allowed) ----------------
__device__ float    g_h[NNODE * GATD];       // 49 MB
__device__ float    g_P[NNODE * PD];         // 24.6 MB
__device__ float    g_ea[NEDGE * 16];        // 8.2 MB
__device__ float    g_asrc[NNODE];
__device__ float    g_adst[NNODE];
__device__ unsigned g_amax[NNODE];           // ordered-float bits
__device__ float    g_denom[NNODE];
__device__ float    g_alphaE[NEDGE];
__device__ float    g_exE[NEDGE];
__device__ int      g_deg[NNODE];
__device__ int      g_rowstart[NNODE];
__device__ int      g_pos[NNODE];
__device__ int      g_csr_src[NEDGE];
__device__ int      g_csr_eid[NEDGE];
// bf16 split operands for tensor-core GEMMs
__device__ __nv_bfloat16 g_A1h[NNODE * GATD];
__device__ __nv_bfloat16 g_A1l[NNODE * GATD];
__device__ __nv_bfloat16 g_Xh[NNODE * XDP];
__device__ __nv_bfloat16 g_Xl[NNODE * XDP];
__device__ __nv_bfloat16 g_W1h[GATD * GATD];   // W_gat^T  [n,k]
__device__ __nv_bfloat16 g_W1l[GATD * GATD];
__device__ __nv_bfloat16 g_W2h[PD * XDP];      // Wcat^T   [n,k]
__device__ __nv_bfloat16 g_W2l[PD * XDP];

// ---------------- helpers ----------------
__device__ __forceinline__ float lrelu(float x) { return x >= 0.f ? x : 0.2f * x; }
__device__ __forceinline__ unsigned f2o(float f) {
    unsigned b = __float_as_uint(f);
    return (b & 0x80000000u) ? ~b : (b | 0x80000000u);
}
__device__ __forceinline__ float o2f(unsigned b) {
    b = (b & 0x80000000u) ? (b & 0x7fffffffu) : ~b;
    return __uint_as_float(b);
}
__device__ __forceinline__ void bsplit(float v, __nv_bfloat16& h, __nv_bfloat16& l) {
    h = __float2bfloat16(v);
    l = __float2bfloat16(v - __bfloat162float(h));
}
__device__ __forceinline__ uint32_t smem_u32(const void* p) {
    uint32_t a;
    asm("{ .reg .u64 t; cvta.to.shared.u64 t, %1; cvt.u32.u64 %0, t; }" : "=r"(a) : "l"(p));
    return a;
}
__device__ __forceinline__ void ldm_x4(uint32_t& r0, uint32_t& r1, uint32_t& r2, uint32_t& r3,
                                       uint32_t addr) {
    asm volatile("ldmatrix.sync.aligned.m8n8.x4.shared.b16 {%0,%1,%2,%3}, [%4];"
                 : "=r"(r0), "=r"(r1), "=r"(r2), "=r"(r3) : "r"(addr));
}
__device__ __forceinline__ void mma16816(float* c, const uint32_t* a, uint32_t b0, uint32_t b1) {
    asm volatile(
        "mma.sync.aligned.m16n8k16.row.col.f32.bf16.bf16.f32 "
        "{%0,%1,%2,%3}, {%4,%5,%6,%7}, {%8,%9}, {%0,%1,%2,%3};"
        : "+f"(c[0]), "+f"(c[1]), "+f"(c[2]), "+f"(c[3])
        : "r"(a[0]), "r"(a[1]), "r"(a[2]), "r"(a[3]), "r"(b0), "r"(b1));
}
__device__ __forceinline__ void cp16(uint32_t dst, const void* src) {
    asm volatile("cp.async.cg.shared.global [%0], [%1], 16;" :: "r"(dst), "l"(src));
}
#define CP_COMMIT() asm volatile("cp.async.commit_group;" ::: "memory")
#define CP_WAIT1()  asm volatile("cp.async.wait_group 1;" ::: "memory")
#define CP_WAIT0()  asm volatile("cp.async.wait_group 0;" ::: "memory")

// ---------------- tiny learners ----------------
__global__ void k_nodeL(const float* __restrict__ nf, const float* __restrict__ W,
                        const float* __restrict__ b) {
    int idx = blockIdx.x * blockDim.x + threadIdx.x;
    if (idx >= NNODE * 32) return;
    int i = idx >> 5, j = idx & 31;
    const float* r = nf + i * 32;
    float s = b[j];
#pragma unroll
    for (int k = 0; k < 32; k++) s += r[k] * W[k * 32 + j];
    __nv_bfloat16 hh, ll;
    bsplit(s, hh, ll);
    size_t base = (size_t)i * XDP;
    g_Xh[base + 768 + j] = hh;
    g_Xl[base + 768 + j] = ll;
    // zero pad cols 800:832 (one pad element per thread)
    g_Xh[base + 800 + j] = __float2bfloat16(0.f);
    g_Xl[base + 800 + j] = __float2bfloat16(0.f);
}

__global__ void k_edgeL(const float* __restrict__ ea, const float* __restrict__ W,
                        const float* __restrict__ b) {
    int idx = blockIdx.x * blockDim.x + threadIdx.x;
    if (idx >= NEDGE * 16) return;
    int e = idx >> 4, j = idx & 15;
    const float* r = ea + e * 16;
    float s = b[j];
#pragma unroll
    for (int k = 0; k < 16; k++) s += r[k] * W[k * 16 + j];
    g_ea[e * 16 + j] = s;
}

// ---------------- split / transpose prep kernels ----------------
__global__ void k_splitA1(const float* __restrict__ src) {
    int idx = blockIdx.x * blockDim.x + threadIdx.x;
    if (idx >= NNODE * GATD) return;
    bsplit(src[idx], g_A1h[idx], g_A1l[idx]);
}
__global__ void k_splitW1(const float* __restrict__ Wg) {
    int idx = blockIdx.x * blockDim.x + threadIdx.x;
    if (idx >= GATD * GATD) return;
    int n = idx / GATD, k = idx % GATD;
    bsplit(Wg[k * GATD + n], g_W1h[idx], g_W1l[idx]);
}
__global__ void k_splitW2(const float* __restrict__ Wn, const float* __restrict__ Ws) {
    int idx = blockIdx.x * blockDim.x + threadIdx.x;
    if (idx >= PD * XDP) return;
    int n = idx / XDP, k = idx % XDP;
    float v = 0.f;
    if (k < XD) {
        if (n < 128)      v = Wn[k * 128 + n];
        else if (n < 256) v = Wn[(800 + k) * 128 + (n - 128)];
        else              v = Ws[k * 128 + (n - 256)];
    }
    bsplit(v, g_W2h[idx], g_W2l[idx]);
}

// ---------------- warp-MMA bf16-split GEMM (cp.async double-buffered) ----------------
// C[M,CN] = (Ah+Al) @ (Bh+Bl)^T, A:[M,KPAD] K-major, B:[CN,KPAD] K-major.
// Block tile 128x128, 8 warps (2x4), warp tile 64x32, K chunk 32.
// smem row stride 40 bf16 (80B) -> conflict-free ldmatrix phases.
#define ASTRIDE 40
#define TILE_BYTES 10240                  // 128*40*2
#define STAGE_BYTES (4 * TILE_BYTES)      // Ah|Al|Bh|Bl

template <int CN, int KPAD, int NCH>
__device__ __forceinline__ void mma_gemm_body(const __nv_bfloat16* __restrict__ Ah,
                                              const __nv_bfloat16* __restrict__ Al,
                                              const __nv_bfloat16* __restrict__ Bh,
                                              const __nv_bfloat16* __restrict__ Bl,
                                              float* __restrict__ C) {
    extern __shared__ char smem[];
    const uint32_t sb = smem_u32(smem);

    const int t = threadIdx.x;
    const int lane = t & 31;
    const int wid = t >> 5;
    const int m0 = (wid >> 2) * 64;
    const int n0 = (wid & 3) * 32;
    const int bm = blockIdx.y * 128;
    const int bn = blockIdx.x * 128;

    // ldmatrix per-lane offsets (bytes)
    const uint32_t aoff = (uint32_t)(((lane & 15) * ASTRIDE + (lane >> 4) * 8) * 2);
    const uint32_t boff = (uint32_t)((((lane & 7) + ((lane >> 4) << 3)) * ASTRIDE +
                                     (((lane >> 3) & 1) << 3)) * 2);

    float acc[4][4][4];
#pragma unroll
    for (int i = 0; i < 4; i++)
#pragma unroll
        for (int j = 0; j < 4; j++)
#pragma unroll
            for (int q = 0; q < 4; q++) acc[i][j][q] = 0.f;

    auto issue_chunk = [&](int c, int s) {
        const int c0 = c * 32;
        const uint32_t dst = sb + (uint32_t)s * STAGE_BYTES;
#pragma unroll
        for (int it = 0; it < 2; it++) {
            int idx = it * 256 + t;
            int r = idx >> 2, j = idx & 3;
            size_t ga = (size_t)(bm + r) * KPAD + c0 + j * 8;
            size_t gb = (size_t)(bn + r) * KPAD + c0 + j * 8;
            uint32_t doff = (uint32_t)((r * ASTRIDE + j * 8) * 2);
            cp16(dst + doff, Ah + ga);
            cp16(dst + TILE_BYTES + doff, Al + ga);
            cp16(dst + 2 * TILE_BYTES + doff, Bh + gb);
            cp16(dst + 3 * TILE_BYTES + doff, Bl + gb);
        }
    };

    issue_chunk(0, 0);
    CP_COMMIT();

    for (int c = 0; c < NCH; c++) {
        const int s = c & 1;
        if (c + 1 < NCH) {
            issue_chunk(c + 1, s ^ 1);
            CP_COMMIT();
            CP_WAIT1();
        } else {
            CP_WAIT0();
        }
        __syncthreads();

        const uint32_t baseAh = sb + (uint32_t)s * STAGE_BYTES;
        const uint32_t baseAl = baseAh + TILE_BYTES;
        const uint32_t baseBh = baseAh + 2 * TILE_BYTES;
        const uint32_t baseBl = baseAh + 3 * TILE_BYTES;

#pragma unroll
        for (int ks = 0; ks < 2; ks++) {
            const uint32_t kb = (uint32_t)(ks * 16 * 2);
            uint32_t bh[2][4], bl[2][4];
#pragma unroll
            for (int p = 0; p < 2; p++) {
                uint32_t off = boff + (uint32_t)((n0 + p * 16) * ASTRIDE * 2) + kb;
                ldm_x4(bh[p][0], bh[p][1], bh[p][2], bh[p][3], baseBh + off);
                ldm_x4(bl[p][0], bl[p][1], bl[p][2], bl[p][3], baseBl + off);
            }
#pragma unroll
            for (int tm = 0; tm < 4; tm++) {
                uint32_t off = aoff + (uint32_t)((m0 + tm * 16) * ASTRIDE * 2) + kb;
                uint32_t ah[4], al[4];
                ldm_x4(ah[0], ah[1], ah[2], ah[3], baseAh + off);
                ldm_x4(al[0], al[1], al[2], al[3], baseAl + off);
#pragma unroll
                for (int tn = 0; tn < 4; tn++) {
                    int p = tn >> 1, q = tn & 1;
                    uint32_t B0h = bh[p][q * 2], B1h = bh[p][q * 2 + 1];
                    uint32_t B0l = bl[p][q * 2], B1l = bl[p][q * 2 + 1];
                    mma16816(acc[tm][tn], ah, B0h, B1h);
                    mma16816(acc[tm][tn], ah, B0l, B1l);
                    mma16816(acc[tm][tn], al, B0h, B1h);
                }
            }
        }
        __syncthreads();
    }

    // epilogue
    const int rit = lane >> 2;
    const int cq = (lane & 3) * 2;
#pragma unroll
    for (int tm = 0; tm < 4; tm++)
#pragma unroll
        for (int tn = 0; tn < 4; tn++) {
            size_t row = (size_t)(bm + m0 + tm * 16 + rit);
            int col = bn + n0 + tn * 8 + cq;
            *(float2*)&C[row * CN + col] = make_float2(acc[tm][tn][0], acc[tm][tn][1]);
            *(float2*)&C[(row + 8) * CN + col] = make_float2(acc[tm][tn][2], acc[tm][tn][3]);
        }
}

__global__ void __launch_bounds__(256) k_gemm1() {
    mma_gemm_body<GATD, GATD, 24>(g_A1h, g_A1l, g_W1h, g_W1l, g_h);
}
__global__ void __launch_bounds__(256) k_gemm2() {
    mma_gemm_body<PD, XDP, 26>(g_Xh, g_Xl, g_W2h, g_W2l, g_P);
}

// ---------------- attention scalars ----------------
__global__ void k_att(const float* __restrict__ att_src, const float* __restrict__ att_dst) {
    int warp = (blockIdx.x * blockDim.x + threadIdx.x) >> 5;
    int lane = threadIdx.x & 31;
    if (warp >= NNODE) return;
    const float* hr = g_h + (size_t)warp * GATD;
    float s1 = 0.f, s2 = 0.f;
    for (int j = lane; j < GATD; j += 32) {
        float v = hr[j];
        s1 += v * att_src[j];
        s2 += v * att_dst[j];
    }
#pragma unroll
    for (int off = 16; off > 0; off >>= 1) {
        s1 += __shfl_down_sync(0xffffffffu, s1, off);
        s2 += __shfl_down_sync(0xffffffffu, s2, off);
    }
    if (lane == 0) { g_asrc[warp] = s1; g_adst[warp] = s2; }
}

__global__ void k_init_node() {
    int i = blockIdx.x * blockDim.x + threadIdx.x;
    if (i >= NNODE) return;
    float al = lrelu(g_asrc[i] + g_adst[i]);   // self-loop alpha
    g_amax[i] = f2o(al);
    g_deg[i] = 0;
}

__global__ void k_edge_alpha(const int* __restrict__ ei) {
    int e = blockIdx.x * blockDim.x + threadIdx.x;
    if (e >= NEDGE) return;
    int s = ei[e], d = ei[NEDGE + e];
    float al = lrelu(g_asrc[s] + g_adst[d]);
    g_alphaE[e] = al;
    atomicMax(&g_amax[d], f2o(al));
    atomicAdd(&g_deg[d], 1);
}

// exclusive scan of deg -> rowstart (and pos copy); one block
__global__ void k_scan() {
    __shared__ int sh[1024];
    __shared__ int s_carry;
    int tid = threadIdx.x;
    if (tid == 0) s_carry = 0;
    __syncthreads();
    for (int base = 0; base < NNODE; base += 1024) {
        int i = base + tid;
        int v = (i < NNODE) ? g_deg[i] : 0;
        sh[tid] = v;
        __syncthreads();
        for (int off = 1; off < 1024; off <<= 1) {
            int t = (tid >= off) ? sh[tid - off] : 0;
            __syncthreads();
            sh[tid] += t;
            __syncthreads();
        }
        int incl = sh[tid];
        int carry = s_carry;
        if (i < NNODE) {
            int excl = carry + incl - v;
            g_rowstart[i] = excl;
            g_pos[i] = excl;
        }
        __syncthreads();
        if (tid == 1023) s_carry = carry + incl;
        __syncthreads();
    }
}

__global__ void k_csr_fill(const int* __restrict__ ei) {
    int e = blockIdx.x * blockDim.x + threadIdx.x;
    if (e >= NEDGE) return;
    int s = ei[e], d = ei[NEDGE + e];
    int p = atomicAdd(&g_pos[d], 1);
    g_csr_src[p] = s;
    g_csr_eid[p] = e;
}

__global__ void k_denom_init() {
    int i = blockIdx.x * blockDim.x + threadIdx.x;
    if (i >= NNODE) return;
    float al = lrelu(g_asrc[i] + g_adst[i]);
    g_denom[i] = expf(al - o2f(g_amax[i]));
}

__global__ void k_edge_exp2(const int* __restrict__ ei) {
    int e = blockIdx.x * blockDim.x + threadIdx.x;
    if (e >= NEDGE) return;
    int d = ei[NEDGE + e];
    float ex = expf(g_alphaE[e] - o2f(g_amax[d]));
    g_exE[e] = ex;
    atomicAdd(&g_denom[d], ex);
}

// ---------------- GAT gather-aggregation: warp per node, writes bf16 split x ----------------
__global__ void k_gat_aggr(const float* __restrict__ b_gat) {
    int warp = (blockIdx.x * blockDim.x + threadIdx.x) >> 5;
    int lane = threadIdx.x & 31;
    if (warp >= NNODE) return;
    int i = warp;
    float amaxv = o2f(g_amax[i]);
    float als = lrelu(g_asrc[i] + g_adst[i]);
    float inv_den = 1.0f / g_denom[i];
    float cs = expf(als - amaxv) * inv_den;

    const float4* hrow = (const float4*)(g_h + (size_t)i * GATD);
    const float4* bg = (const float4*)b_gat;
    float4 acc[6];
#pragma unroll
    for (int t = 0; t < 6; t++) {
        float4 hv = hrow[lane + 32 * t];
        float4 bv = bg[lane + 32 * t];
        acc[t].x = cs * hv.x + bv.x;
        acc[t].y = cs * hv.y + bv.y;
        acc[t].z = cs * hv.z + bv.z;
        acc[t].w = cs * hv.w + bv.w;
    }
    int rs = g_rowstart[i], d = g_deg[i];
    for (int k = 0; k < d; k++) {
        int s = g_csr_src[rs + k];
        float coef = g_exE[g_csr_eid[rs + k]] * inv_den;
        const float4* hs = (const float4*)(g_h + (size_t)s * GATD);
#pragma unroll
        for (int t = 0; t < 6; t++) {
            float4 hv = __ldg(&hs[lane + 32 * t]);
            acc[t].x += coef * hv.x;
            acc[t].y += coef * hv.y;
            acc[t].z += coef * hv.z;
            acc[t].w += coef * hv.w;
        }
    }
    // write bf16 hi/lo split directly (cols 4*(lane+32t) .. +3)
    size_t base = (size_t)i * XDP;
#pragma unroll
    for (int t = 0; t < 6; t++) {
        int col = 4 * (lane + 32 * t);
        __nv_bfloat16 h0, h1, h2, h3, l0, l1, l2, l3;
        bsplit(acc[t].x, h0, l0);
        bsplit(acc[t].y, h1, l1);
        bsplit(acc[t].z, h2, l2);
        bsplit(acc[t].w, h3, l3);
        __nv_bfloat162* ph = (__nv_bfloat162*)(g_Xh + base + col);
        __nv_bfloat162* pl = (__nv_bfloat162*)(g_Xl + base + col);
        ph[0] = __nv_bfloat162(h0, h1);
        ph[1] = __nv_bfloat162(h2, h3);
        pl[0] = __nv_bfloat162(l0, l1);
        pl[1] = __nv_bfloat162(l2, l3);
    }
}

// ---------------- final aggregation (fused ea@We): warp per node ----------------
__global__ void k_meta(float* __restrict__ out, const float* __restrict__ b_nbr,
                       const float* __restrict__ b_self, const float* __restrict__ W_nbr) {
    __shared__ float sWe[16 * 128];
    for (int t = threadIdx.x; t < 2048; t += blockDim.x)
        sWe[t] = W_nbr[1600 * 128 + t];
    __syncthreads();

    int warp = (blockIdx.x * blockDim.x + threadIdx.x) >> 5;
    int lane = threadIdx.x & 31;
    if (warp >= NNODE) return;
    int i = warp;
    const float4* Pr = (const float4*)(g_P + (size_t)i * PD);
    float4 p1 = Pr[lane];        // dst-part
    float4 xs = Pr[64 + lane];   // self-part
    float4 bn = ((const float4*)b_nbr)[lane];
    float4 bs = ((const float4*)b_self)[lane];
    float degf = (float)g_deg[i];
    float4 acc;
    acc.x = xs.x + bs.x + degf * (p1.x + bn.x);
    acc.y = xs.y + bs.y + degf * (p1.y + bn.y);
    acc.z = xs.z + bs.z + degf * (p1.z + bn.z);
    acc.w = xs.w + bs.w + degf * (p1.w + bn.w);

    float eas[16];
#pragma unroll
    for (int k = 0; k < 16; k++) eas[k] = 0.f;

    int rs = g_rowstart[i], d = g_deg[i];
    for (int k = 0; k < d; k++) {
        int s = g_csr_src[rs + k];
        int e = g_csr_eid[rs + k];
        float4 p2 = __ldg(&((const float4*)(g_P + (size_t)s * PD))[32 + lane]);
        acc.x += p2.x;
        acc.y += p2.y;
        acc.z += p2.z;
        acc.w += p2.w;
        const float4* ear = (const float4*)(g_ea + (size_t)e * 16);
        float4 e0 = __ldg(ear), e1 = __ldg(ear + 1), e2 = __ldg(ear + 2), e3 = __ldg(ear + 3);
        eas[0] += e0.x;  eas[1] += e0.y;  eas[2] += e0.z;  eas[3] += e0.w;
        eas[4] += e1.x;  eas[5] += e1.y;  eas[6] += e1.z;  eas[7] += e1.w;
        eas[8] += e2.x;  eas[9] += e2.y;  eas[10] += e2.z; eas[11] += e2.w;
        eas[12] += e3.x; eas[13] += e3.y; eas[14] += e3.z; eas[15] += e3.w;
    }

    // (sum of ea rows) @ We : lane handles 4 output cols
    int col = lane * 4;
#pragma unroll
    for (int kk = 0; kk < 16; kk++) {
        float4 wv = *(const float4*)&sWe[kk * 128 + col];
        float ev = eas[kk];
        acc.x += ev * wv.x;
        acc.y += ev * wv.y;
        acc.z += ev * wv.z;
        acc.w += ev * wv.w;
    }
    ((float4*)(out + (size_t)i * MD))[lane] = acc;
}

// ---------------- launch ----------------
extern "C" void kernel_launch(void* const* d_in, const int* in_sizes, int n_in,
                              void* d_out, int out_size) {
    const float* node_feature    = (const float*)d_in[0];
    const float* edge_attr       = (const float*)d_in[1];
    const float* message_feature = (const float*)d_in[2];
    const int*   edge_index      = (const int*)d_in[3];
    const float* W_node = (const float*)d_in[4];
    const float* b_node = (const float*)d_in[5];
    const float* W_edge = (const float*)d_in[6];
    const float* b_edge = (const float*)d_in[7];
    const float* W_gat  = (const float*)d_in[8];
    const float* att_src = (const float*)d_in[9];
    const float* att_dst = (const float*)d_in[10];
    const float* b_gat  = (const float*)d_in[11];
    const float* W_nbr  = (const float*)d_in[12];
    const float* b_nbr  = (const float*)d_in[13];
    const float* W_self = (const float*)d_in[14];
    const float* b_self = (const float*)d_in[15];
    float* out = (float*)d_out;

    const int GEMM_SMEM = 2 * STAGE_BYTES;   // 81920
    static int s_attr_done = 0;
    if (!s_attr_done) {
        cudaFuncSetAttribute(k_gemm1, cudaFuncAttributeMaxDynamicSharedMemorySize, GEMM_SMEM);
        cudaFuncSetAttribute(k_gemm2, cudaFuncAttributeMaxDynamicSharedMemorySize, GEMM_SMEM);
        s_attr_done = 1;
    }

    // learners + GEMM1 prep
    k_nodeL<<<(NNODE * 32 + 255) / 256, 256>>>(node_feature, W_node, b_node);
    k_edgeL<<<(NEDGE * 16 + 255) / 256, 256>>>(edge_attr, W_edge, b_edge);
    k_splitA1<<<(NNODE * GATD + 255) / 256, 256>>>(message_feature);
    k_splitW1<<<(GATD * GATD + 255) / 256, 256>>>(W_gat);

    // h = mf @ W_gat  (bf16 3-term split, mma.sync, cp.async pipelined)
    k_gemm1<<<dim3(GATD / 128, NNODE / 128), 256, GEMM_SMEM>>>();

    // attention scalars + softmax structure
    k_att<<<(NNODE * 32 + 255) / 256, 256>>>(att_src, att_dst);
    k_init_node<<<(NNODE + 255) / 256, 256>>>();
    k_edge_alpha<<<(NEDGE + 255) / 256, 256>>>(edge_index);
    k_scan<<<1, 1024>>>();
    k_csr_fill<<<(NEDGE + 255) / 256, 256>>>(edge_index);
    k_denom_init<<<(NNODE + 255) / 256, 256>>>();
    k_edge_exp2<<<(NEDGE + 255) / 256, 256>>>(edge_index);

    // GAT aggregation -> Xh/Xl cols 0:768 (bf16 split, direct)
    k_gat_aggr<<<(NNODE * 32 + 255) / 256, 256>>>(b_gat);

    // GEMM2 prep + P = x @ Wcat  (bf16 3-term split)
    k_splitW2<<<(PD * XDP + 255) / 256, 256>>>(W_nbr, W_self);
    k_gemm2<<<dim3(PD / 128, NNODE / 128), 256, GEMM_SMEM>>>();

    // final per-node aggregation (fused ea@We) -> out
    k_meta<<<(NNODE * 32 + 255) / 256, 256>>>(out, b_nbr, b_self, W_nbr);
}

// round 6
// speedup vs baseline: 1.0154x; 1.0154x over previous
#include <cuda_runtime.h>
#include <cuda_bf16.h>
#include <cstdint>

// ---------------- problem constants ----------------
#define NNODE 16000
#define NEDGE 128000
#define GATD 768          // GAT dim
#define XD 800            // meta-in dim (768 gat + 32 node)
#define XDP 832           // padded K for GEMM2 (26 x 32)
#define MD 128            // meta out dim
#define PD 384            // P1(dst part) | P2(src part) | Xself

// ---------------- device scratch (no allocs allowed) ----------------
__device__ float    g_h[NNODE * GATD];       // 49 MB
__device__ float    g_P[NNODE * PD];         // 24.6 MB
__device__ float    g_asrc[NNODE];
__device__ float    g_adst[NNODE];
__device__ unsigned g_amax[NNODE];           // ordered-float bits
__device__ float    g_denom[NNODE];
__device__ float    g_alphaE[NEDGE];
__device__ int      g_deg[NNODE];
__device__ int      g_rowstart[NNODE];
__device__ int      g_pos[NNODE];
__device__ int      g_csr_src[NEDGE];
__device__ int      g_csr_eid[NEDGE];
__device__ float    g_csr_ex[NEDGE];
// bf16 split operands for tensor-core GEMMs
__device__ __nv_bfloat16 g_A1h[NNODE * GATD];
__device__ __nv_bfloat16 g_A1l[NNODE * GATD];
__device__ __nv_bfloat16 g_Xh[NNODE * XDP];
__device__ __nv_bfloat16 g_Xl[NNODE * XDP];
__device__ __nv_bfloat16 g_W1h[GATD * GATD];   // W_gat^T  [n,k]
__device__ __nv_bfloat16 g_W1l[GATD * GATD];
__device__ __nv_bfloat16 g_W2h[PD * XDP];      // Wcat^T   [n,k]
__device__ __nv_bfloat16 g_W2l[PD * XDP];

// ---------------- helpers ----------------
__device__ __forceinline__ float lrelu(float x) { return x >= 0.f ? x : 0.2f * x; }
__device__ __forceinline__ unsigned f2o(float f) {
    unsigned b = __float_as_uint(f);
    return (b & 0x80000000u) ? ~b : (b | 0x80000000u);
}
__device__ __forceinline__ float o2f(unsigned b) {
    b = (b & 0x80000000u) ? (b & 0x7fffffffu) : ~b;
    return __uint_as_float(b);
}
__device__ __forceinline__ void bsplit(float v, __nv_bfloat16& h, __nv_bfloat16& l) {
    h = __float2bfloat16(v);
    l = __float2bfloat16(v - __bfloat162float(h));
}
__device__ __forceinline__ uint32_t smem_u32(const void* p) {
    uint32_t a;
    asm("{ .reg .u64 t; cvta.to.shared.u64 t, %1; cvt.u32.u64 %0, t; }" : "=r"(a) : "l"(p));
    return a;
}
__device__ __forceinline__ void ldm_x4(uint32_t& r0, uint32_t& r1, uint32_t& r2, uint32_t& r3,
                                       uint32_t addr) {
    asm volatile("ldmatrix.sync.aligned.m8n8.x4.shared.b16 {%0,%1,%2,%3}, [%4];"
                 : "=r"(r0), "=r"(r1), "=r"(r2), "=r"(r3) : "r"(addr));
}
__device__ __forceinline__ void mma16816(float* c, const uint32_t* a, uint32_t b0, uint32_t b1) {
    asm volatile(
        "mma.sync.aligned.m16n8k16.row.col.f32.bf16.bf16.f32 "
        "{%0,%1,%2,%3}, {%4,%5,%6,%7}, {%8,%9}, {%0,%1,%2,%3};"
        : "+f"(c[0]), "+f"(c[1]), "+f"(c[2]), "+f"(c[3])
        : "r"(a[0]), "r"(a[1]), "r"(a[2]), "r"(a[3]), "r"(b0), "r"(b1));
}
__device__ __forceinline__ void cp16(uint32_t dst, const void* src) {
    asm volatile("cp.async.cg.shared.global [%0], [%1], 16;" :: "r"(dst), "l"(src));
}
#define CP_COMMIT() asm volatile("cp.async.commit_group;" ::: "memory")
#define CP_WAIT1()  asm volatile("cp.async.wait_group 1;" ::: "memory")
#define CP_WAIT0()  asm volatile("cp.async.wait_group 0;" ::: "memory")

// ---------------- node learner (writes bf16 split x cols 768:832) ----------------
__global__ void k_nodeL(const float* __restrict__ nf, const float* __restrict__ W,
                        const float* __restrict__ b) {
    int idx = blockIdx.x * blockDim.x + threadIdx.x;
    if (idx >= NNODE * 32) return;
    int i = idx >> 5, j = idx & 31;
    const float* r = nf + i * 32;
    float s = b[j];
#pragma unroll
    for (int k = 0; k < 32; k++) s += r[k] * W[k * 32 + j];
    __nv_bfloat16 hh, ll;
    bsplit(s, hh, ll);
    size_t base = (size_t)i * XDP;
    g_Xh[base + 768 + j] = hh;
    g_Xl[base + 768 + j] = ll;
    g_Xh[base + 800 + j] = __float2bfloat16(0.f);
    g_Xl[base + 800 + j] = __float2bfloat16(0.f);
}

// ---------------- split / transpose prep kernels ----------------
__global__ void k_splitA1(const float* __restrict__ src) {
    int idx = blockIdx.x * blockDim.x + threadIdx.x;
    if (idx < NNODE) { g_asrc[idx] = 0.f; g_adst[idx] = 0.f; }
    if (idx >= NNODE * GATD) return;
    bsplit(src[idx], g_A1h[idx], g_A1l[idx]);
}
// coalesced 32x32 tiled transpose split of W_gat
__global__ void k_splitW1(const float* __restrict__ Wg) {
    __shared__ float tile[32][33];
    int tx = threadIdx.x, ty = threadIdx.y;       // block 32x8
    int n0 = blockIdx.x * 32, k0 = blockIdx.y * 32;
#pragma unroll
    for (int i = 0; i < 4; i++)
        tile[ty + i * 8][tx] = Wg[(size_t)(k0 + ty + i * 8) * GATD + n0 + tx];
    __syncthreads();
#pragma unroll
    for (int i = 0; i < 4; i++) {
        float v = tile[tx][ty + i * 8];
        __nv_bfloat16 h, l;
        bsplit(v, h, l);
        size_t o = (size_t)(n0 + ty + i * 8) * GATD + k0 + tx;
        g_W1h[o] = h;
        g_W1l[o] = l;
    }
}
__global__ void k_splitW2(const float* __restrict__ Wn, const float* __restrict__ Ws) {
    int idx = blockIdx.x * blockDim.x + threadIdx.x;
    if (idx >= PD * XDP) return;
    int n = idx / XDP, k = idx % XDP;
    float v = 0.f;
    if (k < XD) {
        if (n < 128)      v = Wn[k * 128 + n];
        else if (n < 256) v = Wn[(800 + k) * 128 + (n - 128)];
        else              v = Ws[k * 128 + (n - 256)];
    }
    bsplit(v, g_W2h[idx], g_W2l[idx]);
}

// ---------------- warp-MMA bf16-split GEMM (cp.async double-buffered) ----------------
// C[M,CN] = (Ah+Al) @ (Bh+Bl)^T.  Block tile 128x128, 8 warps (2x4), K chunk 32.
#define ASTRIDE 40
#define TILE_BYTES 10240                  // 128*40*2
#define STAGE_BYTES (4 * TILE_BYTES)      // Ah|Al|Bh|Bl

template <int CN, int KPAD, int NCH, bool DO_ATT>
__device__ __forceinline__ void mma_gemm_body(const __nv_bfloat16* __restrict__ Ah,
                                              const __nv_bfloat16* __restrict__ Al,
                                              const __nv_bfloat16* __restrict__ Bh,
                                              const __nv_bfloat16* __restrict__ Bl,
                                              float* __restrict__ C,
                                              const float* __restrict__ att_s,
                                              const float* __restrict__ att_d) {
    extern __shared__ char smem[];
    const uint32_t sb = smem_u32(smem);

    const int t = threadIdx.x;
    const int lane = t & 31;
    const int wid = t >> 5;
    const int m0 = (wid >> 2) * 64;
    const int n0 = (wid & 3) * 32;
    const int bm = blockIdx.y * 128;
    const int bn = blockIdx.x * 128;

    const uint32_t aoff = (uint32_t)(((lane & 15) * ASTRIDE + (lane >> 4) * 8) * 2);
    const uint32_t boff = (uint32_t)((((lane & 7) + ((lane >> 4) << 3)) * ASTRIDE +
                                     (((lane >> 3) & 1) << 3)) * 2);

    float acc[4][4][4];
#pragma unroll
    for (int i = 0; i < 4; i++)
#pragma unroll
        for (int j = 0; j < 4; j++)
#pragma unroll
            for (int q = 0; q < 4; q++) acc[i][j][q] = 0.f;

    auto issue_chunk = [&](int c, int s) {
        const int c0 = c * 32;
        const uint32_t dst = sb + (uint32_t)s * STAGE_BYTES;
#pragma unroll
        for (int it = 0; it < 2; it++) {
            int idx = it * 256 + t;
            int r = idx >> 2, j = idx & 3;
            size_t ga = (size_t)(bm + r) * KPAD + c0 + j * 8;
            size_t gb = (size_t)(bn + r) * KPAD + c0 + j * 8;
            uint32_t doff = (uint32_t)((r * ASTRIDE + j * 8) * 2);
            cp16(dst + doff, Ah + ga);
            cp16(dst + TILE_BYTES + doff, Al + ga);
            cp16(dst + 2 * TILE_BYTES + doff, Bh + gb);
            cp16(dst + 3 * TILE_BYTES + doff, Bl + gb);
        }
    };

    issue_chunk(0, 0);
    CP_COMMIT();

    for (int c = 0; c < NCH; c++) {
        const int s = c & 1;
        if (c + 1 < NCH) {
            issue_chunk(c + 1, s ^ 1);
            CP_COMMIT();
            CP_WAIT1();
        } else {
            CP_WAIT0();
        }
        __syncthreads();

        const uint32_t baseAh = sb + (uint32_t)s * STAGE_BYTES;
        const uint32_t baseAl = baseAh + TILE_BYTES;
        const uint32_t baseBh = baseAh + 2 * TILE_BYTES;
        const uint32_t baseBl = baseAh + 3 * TILE_BYTES;

#pragma unroll
        for (int ks = 0; ks < 2; ks++) {
            const uint32_t kb = (uint32_t)(ks * 16 * 2);
            uint32_t bh[2][4], bl[2][4];
#pragma unroll
            for (int p = 0; p < 2; p++) {
                uint32_t off = boff + (uint32_t)((n0 + p * 16) * ASTRIDE * 2) + kb;
                ldm_x4(bh[p][0], bh[p][1], bh[p][2], bh[p][3], baseBh + off);
                ldm_x4(bl[p][0], bl[p][1], bl[p][2], bl[p][3], baseBl + off);
            }
#pragma unroll
            for (int tm = 0; tm < 4; tm++) {
                uint32_t off = aoff + (uint32_t)((m0 + tm * 16) * ASTRIDE * 2) + kb;
                uint32_t ah[4], al[4];
                ldm_x4(ah[0], ah[1], ah[2], ah[3], baseAh + off);
                ldm_x4(al[0], al[1], al[2], al[3], baseAl + off);
#pragma unroll
                for (int tn = 0; tn < 4; tn++) {
                    int p = tn >> 1, q = tn & 1;
                    uint32_t B0h = bh[p][q * 2], B1h = bh[p][q * 2 + 1];
                    uint32_t B0l = bl[p][q * 2], B1l = bl[p][q * 2 + 1];
                    mma16816(acc[tm][tn], ah, B0h, B1h);
                    mma16816(acc[tm][tn], ah, B0l, B1l);
                    mma16816(acc[tm][tn], al, B0h, B1h);
                }
            }
        }
        __syncthreads();
    }

    // epilogue: store C (+ optional fused attention partial dots)
    const int rit = lane >> 2;
    const int cq = (lane & 3) * 2;
#pragma unroll
    for (int tm = 0; tm < 4; tm++) {
        float s1a = 0.f, s2a = 0.f, s1b = 0.f, s2b = 0.f;
#pragma unroll
        for (int tn = 0; tn < 4; tn++) {
            size_t row = (size_t)(bm + m0 + tm * 16 + rit);
            int col = bn + n0 + tn * 8 + cq;
            *(float2*)&C[row * CN + col] = make_float2(acc[tm][tn][0], acc[tm][tn][1]);
            *(float2*)&C[(row + 8) * CN + col] = make_float2(acc[tm][tn][2], acc[tm][tn][3]);
            if (DO_ATT) {
                float a0 = __ldg(att_s + col), a1 = __ldg(att_s + col + 1);
                float d0 = __ldg(att_d + col), d1 = __ldg(att_d + col + 1);
                s1a += acc[tm][tn][0] * a0 + acc[tm][tn][1] * a1;
                s2a += acc[tm][tn][0] * d0 + acc[tm][tn][1] * d1;
                s1b += acc[tm][tn][2] * a0 + acc[tm][tn][3] * a1;
                s2b += acc[tm][tn][2] * d0 + acc[tm][tn][3] * d1;
            }
        }
        if (DO_ATT) {
#pragma unroll
            for (int off = 1; off < 4; off <<= 1) {
                s1a += __shfl_xor_sync(0xffffffffu, s1a, off);
                s2a += __shfl_xor_sync(0xffffffffu, s2a, off);
                s1b += __shfl_xor_sync(0xffffffffu, s1b, off);
                s2b += __shfl_xor_sync(0xffffffffu, s2b, off);
            }
            if ((lane & 3) == 0) {
                int rowA = bm + m0 + tm * 16 + rit;
                atomicAdd(&g_asrc[rowA], s1a);
                atomicAdd(&g_adst[rowA], s2a);
                atomicAdd(&g_asrc[rowA + 8], s1b);
                atomicAdd(&g_adst[rowA + 8], s2b);
            }
        }
    }
}

__global__ void __launch_bounds__(256) k_gemm1(const float* __restrict__ att_s,
                                               const float* __restrict__ att_d) {
    mma_gemm_body<GATD, GATD, 24, true>(g_A1h, g_A1l, g_W1h, g_W1l, g_h, att_s, att_d);
}
__global__ void __launch_bounds__(256) k_gemm2() {
    mma_gemm_body<PD, XDP, 26, false>(g_Xh, g_Xl, g_W2h, g_W2l, g_P, nullptr, nullptr);
}

// ---------------- node init (after gemm1: asrc/adst final) ----------------
__global__ void k_init_node() {
    int i = blockIdx.x * blockDim.x + threadIdx.x;
    if (i >= NNODE) return;
    float al = lrelu(g_asrc[i] + g_adst[i]);   // self-loop alpha
    g_amax[i] = f2o(al);
    g_deg[i] = 0;
}

__global__ void k_edge_alpha(const int* __restrict__ ei) {
    int e = blockIdx.x * blockDim.x + threadIdx.x;
    if (e >= NEDGE) return;
    int s = ei[e], d = ei[NEDGE + e];
    float al = lrelu(g_asrc[s] + g_adst[d]);
    g_alphaE[e] = al;
    atomicMax(&g_amax[d], f2o(al));
    atomicAdd(&g_deg[d], 1);
}

// exclusive scan of deg -> rowstart/pos; phase 2: denom self-loop init
__global__ void k_scan() {
    __shared__ int sh[1024];
    __shared__ int s_carry;
    int tid = threadIdx.x;
    if (tid == 0) s_carry = 0;
    __syncthreads();
    for (int base = 0; base < NNODE; base += 1024) {
        int i = base + tid;
        int v = (i < NNODE) ? g_deg[i] : 0;
        sh[tid] = v;
        __syncthreads();
        for (int off = 1; off < 1024; off <<= 1) {
            int t = (tid >= off) ? sh[tid - off] : 0;
            __syncthreads();
            sh[tid] += t;
            __syncthreads();
        }
        int incl = sh[tid];
        int carry = s_carry;
        if (i < NNODE) {
            int excl = carry + incl - v;
            g_rowstart[i] = excl;
            g_pos[i] = excl;
        }
        __syncthreads();
        if (tid == 1023) s_carry = carry + incl;
        __syncthreads();
    }
    // phase 2: denom = exp(self alpha - amax)
    for (int i = tid; i < NNODE; i += 1024) {
        float al = lrelu(g_asrc[i] + g_adst[i]);
        g_denom[i] = expf(al - o2f(g_amax[i]));
    }
}

// fused CSR fill + exp + denom accumulate
__global__ void k_edge_build(const int* __restrict__ ei) {
    int e = blockIdx.x * blockDim.x + threadIdx.x;
    if (e >= NEDGE) return;
    int s = ei[e], d = ei[NEDGE + e];
    int p = atomicAdd(&g_pos[d], 1);
    g_csr_src[p] = s;
    g_csr_eid[p] = e;
    float ex = expf(g_alphaE[e] - o2f(g_amax[d]));
    g_csr_ex[p] = ex;
    atomicAdd(&g_denom[d], ex);
}

// ---------------- GAT gather-aggregation: warp per node, writes bf16 split x ----------------
__global__ void k_gat_aggr(const float* __restrict__ b_gat) {
    int warp = (blockIdx.x * blockDim.x + threadIdx.x) >> 5;
    int lane = threadIdx.x & 31;
    if (warp >= NNODE) return;
    int i = warp;
    float amaxv = o2f(g_amax[i]);
    float als = lrelu(g_asrc[i] + g_adst[i]);
    float inv_den = 1.0f / g_denom[i];
    float cs = expf(als - amaxv) * inv_den;

    const float4* hrow = (const float4*)(g_h + (size_t)i * GATD);
    const float4* bg = (const float4*)b_gat;
    float4 acc[6];
#pragma unroll
    for (int t = 0; t < 6; t++) {
        float4 hv = hrow[lane + 32 * t];
        float4 bv = bg[lane + 32 * t];
        acc[t].x = cs * hv.x + bv.x;
        acc[t].y = cs * hv.y + bv.y;
        acc[t].z = cs * hv.z + bv.z;
        acc[t].w = cs * hv.w + bv.w;
    }
    int rs = g_rowstart[i], d = g_deg[i];
    for (int base = 0; base < d; base += 32) {
        int cnt = min(32, d - base);
        int sj = 0;
        float cj = 0.f;
        if (lane < cnt) {
            sj = g_csr_src[rs + base + lane];
            cj = g_csr_ex[rs + base + lane] * inv_den;
        }
        for (int k = 0; k < cnt; k++) {
            int s = __shfl_sync(0xffffffffu, sj, k);
            float coef = __shfl_sync(0xffffffffu, cj, k);
            const float4* hs = (const float4*)(g_h + (size_t)s * GATD);
#pragma unroll
            for (int t = 0; t < 6; t++) {
                float4 hv = __ldg(&hs[lane + 32 * t]);
                acc[t].x += coef * hv.x;
                acc[t].y += coef * hv.y;
                acc[t].z += coef * hv.z;
                acc[t].w += coef * hv.w;
            }
        }
    }
    size_t xbase = (size_t)i * XDP;
#pragma unroll
    for (int t = 0; t < 6; t++) {
        int col = 4 * (lane + 32 * t);
        __nv_bfloat16 h0, h1, h2, h3, l0, l1, l2, l3;
        bsplit(acc[t].x, h0, l0);
        bsplit(acc[t].y, h1, l1);
        bsplit(acc[t].z, h2, l2);
        bsplit(acc[t].w, h3, l3);
        __nv_bfloat162* ph = (__nv_bfloat162*)(g_Xh + xbase + col);
        __nv_bfloat162* pl = (__nv_bfloat162*)(g_Xl + xbase + col);
        ph[0] = __nv_bfloat162(h0, h1);
        ph[1] = __nv_bfloat162(h2, h3);
        pl[0] = __nv_bfloat162(l0, l1);
        pl[1] = __nv_bfloat162(l2, l3);
    }
}

// ---------------- final aggregation (fused edge learner + ea@We): warp per node ----------------
__global__ void k_meta(float* __restrict__ out, const float* __restrict__ b_nbr,
                       const float* __restrict__ b_self, const float* __restrict__ W_nbr,
                       const float* __restrict__ W_edge, const float* __restrict__ b_edge,
                       const float* __restrict__ edge_attr) {
    __shared__ float sWe[16 * 128];
    __shared__ float sWE[16 * 16];
    __shared__ float sBN[128];
    for (int t = threadIdx.x; t < 2048; t += blockDim.x)
        sWe[t] = W_nbr[1600 * 128 + t];
    for (int t = threadIdx.x; t < 256; t += blockDim.x)
        sWE[t] = W_edge[t];
    __syncthreads();
    if (threadIdx.x < 128) {
        int c = threadIdx.x;
        float s = b_nbr[c];
#pragma unroll
        for (int k = 0; k < 16; k++) s += b_edge[k] * sWe[k * 128 + c];
        sBN[c] = s;
    }
    __syncthreads();

    int warp = (blockIdx.x * blockDim.x + threadIdx.x) >> 5;
    int lane = threadIdx.x & 31;
    if (warp >= NNODE) return;
    int i = warp;
    const float4* Pr = (const float4*)(g_P + (size_t)i * PD);
    float4 p1 = Pr[lane];        // dst-part
    float4 xs = Pr[64 + lane];   // self-part
    float4 bs = ((const float4*)b_self)[lane];
    float4 bn4 = *(const float4*)&sBN[lane * 4];
    float degf = (float)g_deg[i];
    float4 acc;
    acc.x = xs.x + bs.x + degf * (p1.x + bn4.x);
    acc.y = xs.y + bs.y + degf * (p1.y + bn4.y);
    acc.z = xs.z + bs.z + degf * (p1.z + bn4.z);
    acc.w = xs.w + bs.w + degf * (p1.w + bn4.w);

    float eas[16];
#pragma unroll
    for (int k = 0; k < 16; k++) eas[k] = 0.f;

    int rs = g_rowstart[i], d = g_deg[i];
    for (int base = 0; base < d; base += 32) {
        int cnt = min(32, d - base);
        int sj = 0, ej = 0;
        if (lane < cnt) {
            sj = g_csr_src[rs + base + lane];
            ej = g_csr_eid[rs + base + lane];
        }
        for (int k = 0; k < cnt; k++) {
            int s = __shfl_sync(0xffffffffu, sj, k);
            int e = __shfl_sync(0xffffffffu, ej, k);
            float4 p2 = __ldg(&((const float4*)(g_P + (size_t)s * PD))[32 + lane]);
            acc.x += p2.x;
            acc.y += p2.y;
            acc.z += p2.z;
            acc.w += p2.w;
            const float4* ear = (const float4*)(edge_attr + (size_t)e * 16);
            float4 e0 = __ldg(ear), e1 = __ldg(ear + 1), e2 = __ldg(ear + 2), e3 = __ldg(ear + 3);
            eas[0] += e0.x;  eas[1] += e0.y;  eas[2] += e0.z;  eas[3] += e0.w;
            eas[4] += e1.x;  eas[5] += e1.y;  eas[6] += e1.z;  eas[7] += e1.w;
            eas[8] += e2.x;  eas[9] += e2.y;  eas[10] += e2.z; eas[11] += e2.w;
            eas[12] += e3.x; eas[13] += e3.y; eas[14] += e3.z; eas[15] += e3.w;
        }
    }

    // t = (sum raw edge rows) @ W_edge  (16x16)
    float tv[16];
#pragma unroll
    for (int kk = 0; kk < 16; kk++) {
        float s = 0.f;
#pragma unroll
        for (int j = 0; j < 16; j++) s += eas[j] * sWE[j * 16 + kk];
        tv[kk] = s;
    }
    // acc += t @ We
    int col = lane * 4;
#pragma unroll
    for (int kk = 0; kk < 16; kk++) {
        float4 wv = *(const float4*)&sWe[kk * 128 + col];
        float ev = tv[kk];
        acc.x += ev * wv.x;
        acc.y += ev * wv.y;
        acc.z += ev * wv.z;
        acc.w += ev * wv.w;
    }
    ((float4*)(out + (size_t)i * MD))[lane] = acc;
}

// ---------------- launch ----------------
extern "C" void kernel_launch(void* const* d_in, const int* in_sizes, int n_in,
                              void* d_out, int out_size) {
    const float* node_feature    = (const float*)d_in[0];
    const float* edge_attr       = (const float*)d_in[1];
    const float* message_feature = (const float*)d_in[2];
    const int*   edge_index      = (const int*)d_in[3];
    const float* W_node = (const float*)d_in[4];
    const float* b_node = (const float*)d_in[5];
    const float* W_edge = (const float*)d_in[6];
    const float* b_edge = (const float*)d_in[7];
    const float* W_gat  = (const float*)d_in[8];
    const float* att_src = (const float*)d_in[9];
    const float* att_dst = (const float*)d_in[10];
    const float* b_gat  = (const float*)d_in[11];
    const float* W_nbr  = (const float*)d_in[12];
    const float* b_nbr  = (const float*)d_in[13];
    const float* W_self = (const float*)d_in[14];
    const float* b_self = (const float*)d_in[15];
    float* out = (float*)d_out;

    const int GEMM_SMEM = 2 * STAGE_BYTES;   // 81920
    cudaFuncSetAttribute(k_gemm1, cudaFuncAttributeMaxDynamicSharedMemorySize, GEMM_SMEM);
    cudaFuncSetAttribute(k_gemm2, cudaFuncAttributeMaxDynamicSharedMemorySize, GEMM_SMEM);

    // prep
    k_nodeL<<<(NNODE * 32 + 255) / 256, 256>>>(node_feature, W_node, b_node);
    k_splitA1<<<(NNODE * GATD + 255) / 256, 256>>>(message_feature);
    k_splitW1<<<dim3(GATD / 32, GATD / 32), dim3(32, 8)>>>(W_gat);

    // h = mf @ W_gat  (+ fused attention scalar partial dots)
    k_gemm1<<<dim3(GATD / 128, NNODE / 128), 256, GEMM_SMEM>>>(att_src, att_dst);

    // softmax structure
    k_init_node<<<(NNODE + 255) / 256, 256>>>();
    k_edge_alpha<<<(NEDGE + 255) / 256, 256>>>(edge_index);
    k_scan<<<1, 1024>>>();
    k_edge_build<<<(NEDGE + 255) / 256, 256>>>(edge_index);

    // GAT aggregation -> Xh/Xl cols 0:768 (bf16 split, direct)
    k_gat_aggr<<<(NNODE * 32 + 255) / 256, 256>>>(b_gat);

    // P = x @ Wcat  (bf16 3-term split)
    k_splitW2<<<(PD * XDP + 255) / 256, 256>>>(W_nbr, W_self);
    k_gemm2<<<dim3(PD / 128, NNODE / 128), 256, GEMM_SMEM>>>();

    // final per-node aggregation (fused edge learner) -> out
    k_meta<<<(NNODE * 32 + 255) / 256, 256>>>(out, b_nbr, b_self, W_nbr,
                                              W_edge, b_edge, edge_attr);
}

// round 7
// speedup vs baseline: 1.2174x; 1.1990x over previous
#include <cuda_runtime.h>
#include <cuda_fp16.h>
#include <cstdint>

// ---------------- problem constants ----------------
#define NNODE 16000
#define NEDGE 128000
#define GATD 768          // GAT dim
#define XD 800            // meta-in dim (768 gat + 32 node)
#define XDP 832           // padded K for GEMM2 (26 x 32)
#define MD 128            // meta out dim
#define PD 384            // P1(dst part) | P2(src part) | Xself

// ---------------- device scratch (no allocs allowed) ----------------
__device__ float    g_h[NNODE * GATD];       // 49 MB
__device__ float    g_P[NNODE * PD];         // 24.6 MB
__device__ float    g_asrc[NNODE];
__device__ float    g_adst[NNODE];
__device__ unsigned g_amax[NNODE];           // ordered-float bits
__device__ float    g_denom[NNODE];
__device__ float    g_alphaE[NEDGE];
__device__ int      g_deg[NNODE];
__device__ int      g_rowstart[NNODE];
__device__ int      g_pos[NNODE];
__device__ int      g_csr_src[NEDGE];
__device__ int      g_csr_eid[NEDGE];
__device__ float    g_csr_ex[NEDGE];
// fp16 exact-split A operands + single fp16 B operands
__device__ __half g_A1h[NNODE * GATD];
__device__ __half g_A1l[NNODE * GATD];
__device__ __half g_Xh[NNODE * XDP];
__device__ __half g_Xl[NNODE * XDP];
__device__ __half g_W1[GATD * GATD];   // W_gat^T  [n,k]
__device__ __half g_W2[PD * XDP];      // Wcat^T   [n,k]

// ---------------- helpers ----------------
__device__ __forceinline__ float lrelu(float x) { return x >= 0.f ? x : 0.2f * x; }
__device__ __forceinline__ unsigned f2o(float f) {
    unsigned b = __float_as_uint(f);
    return (b & 0x80000000u) ? ~b : (b | 0x80000000u);
}
__device__ __forceinline__ float o2f(unsigned b) {
    b = (b & 0x80000000u) ? (b & 0x7fffffffu) : ~b;
    return __uint_as_float(b);
}
__device__ __forceinline__ void hsplit(float v, __half& h, __half& l) {
    h = __float2half_rn(v);
    l = __float2half_rn(v - __half2float(h));
}
__device__ __forceinline__ uint32_t smem_u32(const void* p) {
    uint32_t a;
    asm("{ .reg .u64 t; cvta.to.shared.u64 t, %1; cvt.u32.u64 %0, t; }" : "=r"(a) : "l"(p));
    return a;
}
__device__ __forceinline__ void ldm_x4(uint32_t& r0, uint32_t& r1, uint32_t& r2, uint32_t& r3,
                                       uint32_t addr) {
    asm volatile("ldmatrix.sync.aligned.m8n8.x4.shared.b16 {%0,%1,%2,%3}, [%4];"
                 : "=r"(r0), "=r"(r1), "=r"(r2), "=r"(r3) : "r"(addr));
}
__device__ __forceinline__ void mma16816(float* c, const uint32_t* a, uint32_t b0, uint32_t b1) {
    asm volatile(
        "mma.sync.aligned.m16n8k16.row.col.f32.f16.f16.f32 "
        "{%0,%1,%2,%3}, {%4,%5,%6,%7}, {%8,%9}, {%0,%1,%2,%3};"
        : "+f"(c[0]), "+f"(c[1]), "+f"(c[2]), "+f"(c[3])
        : "r"(a[0]), "r"(a[1]), "r"(a[2]), "r"(a[3]), "r"(b0), "r"(b1));
}
__device__ __forceinline__ void cp16(uint32_t dst, const void* src) {
    asm volatile("cp.async.cg.shared.global [%0], [%1], 16;" :: "r"(dst), "l"(src));
}
#define CP_COMMIT() asm volatile("cp.async.commit_group;" ::: "memory")
#define CP_WAIT2()  asm volatile("cp.async.wait_group 2;" ::: "memory")
#define CP_WAIT1()  asm volatile("cp.async.wait_group 1;" ::: "memory")
#define CP_WAIT0()  asm volatile("cp.async.wait_group 0;" ::: "memory")

// ---------------- node learner (writes fp16 split x cols 768:832) ----------------
__global__ void k_nodeL(const float* __restrict__ nf, const float* __restrict__ W,
                        const float* __restrict__ b) {
    int idx = blockIdx.x * blockDim.x + threadIdx.x;
    if (idx >= NNODE * 32) return;
    int i = idx >> 5, j = idx & 31;
    const float* r = nf + i * 32;
    float s = b[j];
#pragma unroll
    for (int k = 0; k < 32; k++) s += r[k] * W[k * 32 + j];
    __half hh, ll;
    hsplit(s, hh, ll);
    size_t base = (size_t)i * XDP;
    g_Xh[base + 768 + j] = hh;
    g_Xl[base + 768 + j] = ll;
    g_Xh[base + 800 + j] = __float2half(0.f);
    g_Xl[base + 800 + j] = __float2half(0.f);
}

// ---------------- split / transpose prep kernels ----------------
__global__ void k_splitA1(const float* __restrict__ src) {
    int idx = blockIdx.x * blockDim.x + threadIdx.x;
    if (idx < NNODE) { g_asrc[idx] = 0.f; g_adst[idx] = 0.f; }
    if (idx >= NNODE * GATD) return;
    hsplit(src[idx], g_A1h[idx], g_A1l[idx]);
}
// coalesced 32x32 tiled transpose of W_gat -> fp16
__global__ void k_splitW1(const float* __restrict__ Wg) {
    __shared__ float tile[32][33];
    int tx = threadIdx.x, ty = threadIdx.y;       // block 32x8
    int n0 = blockIdx.x * 32, k0 = blockIdx.y * 32;
#pragma unroll
    for (int i = 0; i < 4; i++)
        tile[ty + i * 8][tx] = Wg[(size_t)(k0 + ty + i * 8) * GATD + n0 + tx];
    __syncthreads();
#pragma unroll
    for (int i = 0; i < 4; i++) {
        size_t o = (size_t)(n0 + ty + i * 8) * GATD + k0 + tx;
        g_W1[o] = __float2half_rn(tile[tx][ty + i * 8]);
    }
}
__global__ void k_splitW2(const float* __restrict__ Wn, const float* __restrict__ Ws) {
    int idx = blockIdx.x * blockDim.x + threadIdx.x;
    if (idx >= PD * XDP) return;
    int n = idx / XDP, k = idx % XDP;
    float v = 0.f;
    if (k < XD) {
        if (n < 128)      v = Wn[k * 128 + n];
        else if (n < 256) v = Wn[(800 + k) * 128 + (n - 128)];
        else              v = Ws[k * 128 + (n - 256)];
    }
    g_W2[idx] = __float2half_rn(v);
}

// ---------------- warp-MMA fp16-split GEMM (cp.async 3-stage) ----------------
// C[M,CN] = (Ah+Al) @ Bh^T.  Block tile 128x128, 8 warps (2x4), K chunk 32.
#define ASTRIDE 40
#define TILE_BYTES 10240                  // 128*40*2
#define STAGE_BYTES (3 * TILE_BYTES)      // Ah|Al|Bh

template <int CN, int KPAD, int NCH, bool DO_ATT>
__device__ __forceinline__ void mma_gemm_body(const __half* __restrict__ Ah,
                                              const __half* __restrict__ Al,
                                              const __half* __restrict__ Bh,
                                              float* __restrict__ C,
                                              const float* __restrict__ att_s,
                                              const float* __restrict__ att_d) {
    extern __shared__ char smem[];
    const uint32_t sb = smem_u32(smem);

    const int t = threadIdx.x;
    const int lane = t & 31;
    const int wid = t >> 5;
    const int m0 = (wid >> 2) * 64;
    const int n0 = (wid & 3) * 32;
    const int bm = blockIdx.y * 128;
    const int bn = blockIdx.x * 128;

    const uint32_t aoff = (uint32_t)(((lane & 15) * ASTRIDE + (lane >> 4) * 8) * 2);
    const uint32_t boff = (uint32_t)((((lane & 7) + ((lane >> 4) << 3)) * ASTRIDE +
                                     (((lane >> 3) & 1) << 3)) * 2);

    float acc[4][4][4];
#pragma unroll
    for (int i = 0; i < 4; i++)
#pragma unroll
        for (int j = 0; j < 4; j++)
#pragma unroll
            for (int q = 0; q < 4; q++) acc[i][j][q] = 0.f;

    auto issue_chunk = [&](int c, int s) {
        const int c0 = c * 32;
        const uint32_t dst = sb + (uint32_t)s * STAGE_BYTES;
#pragma unroll
        for (int it = 0; it < 2; it++) {
            int idx = it * 256 + t;
            int r = idx >> 2, j = idx & 3;
            size_t ga = (size_t)(bm + r) * KPAD + c0 + j * 8;
            size_t gb = (size_t)(bn + r) * KPAD + c0 + j * 8;
            uint32_t doff = (uint32_t)((r * ASTRIDE + j * 8) * 2);
            cp16(dst + doff, Ah + ga);
            cp16(dst + TILE_BYTES + doff, Al + ga);
            cp16(dst + 2 * TILE_BYTES + doff, Bh + gb);
        }
    };

    issue_chunk(0, 0);
    CP_COMMIT();
    issue_chunk(1, 1);
    CP_COMMIT();

    for (int c = 0; c < NCH; c++) {
        const int s = c % 3;
        if (c + 2 < NCH) {
            issue_chunk(c + 2, (c + 2) % 3);
            CP_COMMIT();
            CP_WAIT2();
        } else if (c + 1 < NCH) {
            CP_WAIT1();
        } else {
            CP_WAIT0();
        }
        __syncthreads();

        const uint32_t baseAh = sb + (uint32_t)s * STAGE_BYTES;
        const uint32_t baseAl = baseAh + TILE_BYTES;
        const uint32_t baseBh = baseAh + 2 * TILE_BYTES;

#pragma unroll
        for (int ks = 0; ks < 2; ks++) {
            const uint32_t kb = (uint32_t)(ks * 16 * 2);
            uint32_t bh[2][4];
#pragma unroll
            for (int p = 0; p < 2; p++) {
                uint32_t off = boff + (uint32_t)((n0 + p * 16) * ASTRIDE * 2) + kb;
                ldm_x4(bh[p][0], bh[p][1], bh[p][2], bh[p][3], baseBh + off);
            }
#pragma unroll
            for (int tm = 0; tm < 4; tm++) {
                uint32_t off = aoff + (uint32_t)((m0 + tm * 16) * ASTRIDE * 2) + kb;
                uint32_t ah[4], al[4];
                ldm_x4(ah[0], ah[1], ah[2], ah[3], baseAh + off);
                ldm_x4(al[0], al[1], al[2], al[3], baseAl + off);
#pragma unroll
                for (int tn = 0; tn < 4; tn++) {
                    int p = tn >> 1, q = tn & 1;
                    uint32_t B0 = bh[p][q * 2], B1 = bh[p][q * 2 + 1];
                    mma16816(acc[tm][tn], ah, B0, B1);
                    mma16816(acc[tm][tn], al, B0, B1);
                }
            }
        }
        __syncthreads();
    }

    // epilogue: store C (+ optional fused attention partial dots)
    const int rit = lane >> 2;
    const int cq = (lane & 3) * 2;
#pragma unroll
    for (int tm = 0; tm < 4; tm++) {
        float s1a = 0.f, s2a = 0.f, s1b = 0.f, s2b = 0.f;
#pragma unroll
        for (int tn = 0; tn < 4; tn++) {
            size_t row = (size_t)(bm + m0 + tm * 16 + rit);
            int col = bn + n0 + tn * 8 + cq;
            *(float2*)&C[row * CN + col] = make_float2(acc[tm][tn][0], acc[tm][tn][1]);
            *(float2*)&C[(row + 8) * CN + col] = make_float2(acc[tm][tn][2], acc[tm][tn][3]);
            if (DO_ATT) {
                float a0 = __ldg(att_s + col), a1 = __ldg(att_s + col + 1);
                float d0 = __ldg(att_d + col), d1 = __ldg(att_d + col + 1);
                s1a += acc[tm][tn][0] * a0 + acc[tm][tn][1] * a1;
                s2a += acc[tm][tn][0] * d0 + acc[tm][tn][1] * d1;
                s1b += acc[tm][tn][2] * a0 + acc[tm][tn][3] * a1;
                s2b += acc[tm][tn][2] * d0 + acc[tm][tn][3] * d1;
            }
        }
        if (DO_ATT) {
#pragma unroll
            for (int off = 1; off < 4; off <<= 1) {
                s1a += __shfl_xor_sync(0xffffffffu, s1a, off);
                s2a += __shfl_xor_sync(0xffffffffu, s2a, off);
                s1b += __shfl_xor_sync(0xffffffffu, s1b, off);
                s2b += __shfl_xor_sync(0xffffffffu, s2b, off);
            }
            if ((lane & 3) == 0) {
                int rowA = bm + m0 + tm * 16 + rit;
                atomicAdd(&g_asrc[rowA], s1a);
                atomicAdd(&g_adst[rowA], s2a);
                atomicAdd(&g_asrc[rowA + 8], s1b);
                atomicAdd(&g_adst[rowA + 8], s2b);
            }
        }
    }
}

__global__ void __launch_bounds__(256) k_gemm1(const float* __restrict__ att_s,
                                               const float* __restrict__ att_d) {
    mma_gemm_body<GATD, GATD, 24, true>(g_A1h, g_A1l, g_W1, g_h, att_s, att_d);
}
__global__ void __launch_bounds__(256) k_gemm2() {
    mma_gemm_body<PD, XDP, 26, false>(g_Xh, g_Xl, g_W2, g_P, nullptr, nullptr);
}

// ---------------- node init (after gemm1: asrc/adst final) ----------------
__global__ void k_init_node() {
    int i = blockIdx.x * blockDim.x + threadIdx.x;
    if (i >= NNODE) return;
    float al = lrelu(g_asrc[i] + g_adst[i]);   // self-loop alpha
    g_amax[i] = f2o(al);
    g_deg[i] = 0;
}

__global__ void k_edge_alpha(const int* __restrict__ ei) {
    int e = blockIdx.x * blockDim.x + threadIdx.x;
    if (e >= NEDGE) return;
    int s = ei[e], d = ei[NEDGE + e];
    float al = lrelu(g_asrc[s] + g_adst[d]);
    g_alphaE[e] = al;
    atomicMax(&g_amax[d], f2o(al));
    atomicAdd(&g_deg[d], 1);
}

// exclusive scan of deg -> rowstart/pos; phase 2: denom self-loop init
__global__ void k_scan() {
    __shared__ int sh[1024];
    __shared__ int s_carry;
    int tid = threadIdx.x;
    if (tid == 0) s_carry = 0;
    __syncthreads();
    for (int base = 0; base < NNODE; base += 1024) {
        int i = base + tid;
        int v = (i < NNODE) ? g_deg[i] : 0;
        sh[tid] = v;
        __syncthreads();
        for (int off = 1; off < 1024; off <<= 1) {
            int t = (tid >= off) ? sh[tid - off] : 0;
            __syncthreads();
            sh[tid] += t;
            __syncthreads();
        }
        int incl = sh[tid];
        int carry = s_carry;
        if (i < NNODE) {
            int excl = carry + incl - v;
            g_rowstart[i] = excl;
            g_pos[i] = excl;
        }
        __syncthreads();
        if (tid == 1023) s_carry = carry + incl;
        __syncthreads();
    }
    for (int i = tid; i < NNODE; i += 1024) {
        float al = lrelu(g_asrc[i] + g_adst[i]);
        g_denom[i] = expf(al - o2f(g_amax[i]));
    }
}

// fused CSR fill + exp + denom accumulate
__global__ void k_edge_build(const int* __restrict__ ei) {
    int e = blockIdx.x * blockDim.x + threadIdx.x;
    if (e >= NEDGE) return;
    int s = ei[e], d = ei[NEDGE + e];
    int p = atomicAdd(&g_pos[d], 1);
    g_csr_src[p] = s;
    g_csr_eid[p] = e;
    float ex = expf(g_alphaE[e] - o2f(g_amax[d]));
    g_csr_ex[p] = ex;
    atomicAdd(&g_denom[d], ex);
}

// ---------------- GAT gather-aggregation: warp per node, writes fp16 split x ----------------
__global__ void k_gat_aggr(const float* __restrict__ b_gat) {
    int warp = (blockIdx.x * blockDim.x + threadIdx.x) >> 5;
    int lane = threadIdx.x & 31;
    if (warp >= NNODE) return;
    int i = warp;
    float amaxv = o2f(g_amax[i]);
    float als = lrelu(g_asrc[i] + g_adst[i]);
    float inv_den = 1.0f / g_denom[i];
    float cs = expf(als - amaxv) * inv_den;

    const float4* hrow = (const float4*)(g_h + (size_t)i * GATD);
    const float4* bg = (const float4*)b_gat;
    float4 acc[6];
#pragma unroll
    for (int t = 0; t < 6; t++) {
        float4 hv = hrow[lane + 32 * t];
        float4 bv = bg[lane + 32 * t];
        acc[t].x = cs * hv.x + bv.x;
        acc[t].y = cs * hv.y + bv.y;
        acc[t].z = cs * hv.z + bv.z;
        acc[t].w = cs * hv.w + bv.w;
    }
    int rs = g_rowstart[i], d = g_deg[i];
    for (int base = 0; base < d; base += 32) {
        int cnt = min(32, d - base);
        int sj = 0;
        float cj = 0.f;
        if (lane < cnt) {
            sj = g_csr_src[rs + base + lane];
            cj = g_csr_ex[rs + base + lane] * inv_den;
        }
        for (int k = 0; k < cnt; k++) {
            int s = __shfl_sync(0xffffffffu, sj, k);
            float coef = __shfl_sync(0xffffffffu, cj, k);
            const float4* hs = (const float4*)(g_h + (size_t)s * GATD);
#pragma unroll
            for (int t = 0; t < 6; t++) {
                float4 hv = __ldg(&hs[lane + 32 * t]);
                acc[t].x += coef * hv.x;
                acc[t].y += coef * hv.y;
                acc[t].z += coef * hv.z;
                acc[t].w += coef * hv.w;
            }
        }
    }
    size_t xbase = (size_t)i * XDP;
#pragma unroll
    for (int t = 0; t < 6; t++) {
        int col = 4 * (lane + 32 * t);
        __half h0, h1, h2, h3, l0, l1, l2, l3;
        hsplit(acc[t].x, h0, l0);
        hsplit(acc[t].y, h1, l1);
        hsplit(acc[t].z, h2, l2);
        hsplit(acc[t].w, h3, l3);
        __half2* ph = (__half2*)(g_Xh + xbase + col);
        __half2* pl = (__half2*)(g_Xl + xbase + col);
        ph[0] = __half2(h0, h1);
        ph[1] = __half2(h2, h3);
        pl[0] = __half2(l0, l1);
        pl[1] = __half2(l2, l3);
    }
}

// ---------------- final aggregation (fused edge learner + ea@We): warp per node ----------------
__global__ void k_meta(float* __restrict__ out, const float* __restrict__ b_nbr,
                       const float* __restrict__ b_self, const float* __restrict__ W_nbr,
                       const float* __restrict__ W_edge, const float* __restrict__ b_edge,
                       const float* __restrict__ edge_attr) {
    __shared__ float sWe[16 * 128];
    __shared__ float sWE[16 * 16];
    __shared__ float sBN[128];
    for (int t = threadIdx.x; t < 2048; t += blockDim.x)
        sWe[t] = W_nbr[1600 * 128 + t];
    for (int t = threadIdx.x; t < 256; t += blockDim.x)
        sWE[t] = W_edge[t];
    __syncthreads();
    if (threadIdx.x < 128) {
        int c = threadIdx.x;
        float s = b_nbr[c];
#pragma unroll
        for (int k = 0; k < 16; k++) s += b_edge[k] * sWe[k * 128 + c];
        sBN[c] = s;
    }
    __syncthreads();

    int warp = (blockIdx.x * blockDim.x + threadIdx.x) >> 5;
    int lane = threadIdx.x & 31;
    if (warp >= NNODE) return;
    int i = warp;
    const float4* Pr = (const float4*)(g_P + (size_t)i * PD);
    float4 p1 = Pr[lane];        // dst-part
    float4 xs = Pr[64 + lane];   // self-part
    float4 bs = ((const float4*)b_self)[lane];
    float4 bn4 = *(const float4*)&sBN[lane * 4];
    float degf = (float)g_deg[i];
    float4 acc;
    acc.x = xs.x + bs.x + degf * (p1.x + bn4.x);
    acc.y = xs.y + bs.y + degf * (p1.y + bn4.y);
    acc.z = xs.z + bs.z + degf * (p1.z + bn4.z);
    acc.w = xs.w + bs.w + degf * (p1.w + bn4.w);

    float eas[16];
#pragma unroll
    for (int k = 0; k < 16; k++) eas[k] = 0.f;

    int rs = g_rowstart[i], d = g_deg[i];
    for (int base = 0; base < d; base += 32) {
        int cnt = min(32, d - base);
        int sj = 0, ej = 0;
        if (lane < cnt) {
            sj = g_csr_src[rs + base + lane];
            ej = g_csr_eid[rs + base + lane];
        }
        for (int k = 0; k < cnt; k++) {
            int s = __shfl_sync(0xffffffffu, sj, k);
            int e = __shfl_sync(0xffffffffu, ej, k);
            float4 p2 = __ldg(&((const float4*)(g_P + (size_t)s * PD))[32 + lane]);
            acc.x += p2.x;
            acc.y += p2.y;
            acc.z += p2.z;
            acc.w += p2.w;
            const float4* ear = (const float4*)(edge_attr + (size_t)e * 16);
            float4 e0 = __ldg(ear), e1 = __ldg(ear + 1), e2 = __ldg(ear + 2), e3 = __ldg(ear + 3);
            eas[0] += e0.x;  eas[1] += e0.y;  eas[2] += e0.z;  eas[3] += e0.w;
            eas[4] += e1.x;  eas[5] += e1.y;  eas[6] += e1.z;  eas[7] += e1.w;
            eas[8] += e2.x;  eas[9] += e2.y;  eas[10] += e2.z; eas[11] += e2.w;
            eas[12] += e3.x; eas[13] += e3.y; eas[14] += e3.z; eas[15] += e3.w;
        }
    }

    float tv[16];
#pragma unroll
    for (int kk = 0; kk < 16; kk++) {
        float s = 0.f;
#pragma unroll
        for (int j = 0; j < 16; j++) s += eas[j] * sWE[j * 16 + kk];
        tv[kk] = s;
    }
    int col = lane * 4;
#pragma unroll
    for (int kk = 0; kk < 16; kk++) {
        float4 wv = *(const float4*)&sWe[kk * 128 + col];
        float ev = tv[kk];
        acc.x += ev * wv.x;
        acc.y += ev * wv.y;
        acc.z += ev * wv.z;
        acc.w += ev * wv.w;
    }
    ((float4*)(out + (size_t)i * MD))[lane] = acc;
}

// ---------------- launch ----------------
extern "C" void kernel_launch(void* const* d_in, const int* in_sizes, int n_in,
                              void* d_out, int out_size) {
    const float* node_feature    = (const float*)d_in[0];
    const float* edge_attr       = (const float*)d_in[1];
    const float* message_feature = (const float*)d_in[2];
    const int*   edge_index      = (const int*)d_in[3];
    const float* W_node = (const float*)d_in[4];
    const float* b_node = (const float*)d_in[5];
    const float* W_edge = (const float*)d_in[6];
    const float* b_edge = (const float*)d_in[7];
    const float* W_gat  = (const float*)d_in[8];
    const float* att_src = (const float*)d_in[9];
    const float* att_dst = (const float*)d_in[10];
    const float* b_gat  = (const float*)d_in[11];
    const float* W_nbr  = (const float*)d_in[12];
    const float* b_nbr  = (const float*)d_in[13];
    const float* W_self = (const float*)d_in[14];
    const float* b_self = (const float*)d_in[15];
    float* out = (float*)d_out;

    const int GEMM_SMEM = 3 * STAGE_BYTES;   // 92160 (3 stages x Ah|Al|Bh)
    cudaFuncSetAttribute(k_gemm1, cudaFuncAttributeMaxDynamicSharedMemorySize, GEMM_SMEM);
    cudaFuncSetAttribute(k_gemm2, cudaFuncAttributeMaxDynamicSharedMemorySize, GEMM_SMEM);

    // prep
    k_nodeL<<<(NNODE * 32 + 255) / 256, 256>>>(node_feature, W_node, b_node);
    k_splitA1<<<(NNODE * GATD + 255) / 256, 256>>>(message_feature);
    k_splitW1<<<dim3(GATD / 32, GATD / 32), dim3(32, 8)>>>(W_gat);

    // h = mf @ W_gat  (+ fused attention scalar partial dots)
    k_gemm1<<<dim3(GATD / 128, NNODE / 128), 256, GEMM_SMEM>>>(att_src, att_dst);

    // softmax structure
    k_init_node<<<(NNODE + 255) / 256, 256>>>();
    k_edge_alpha<<<(NEDGE + 255) / 256, 256>>>(edge_index);
    k_scan<<<1, 1024>>>();
    k_edge_build<<<(NEDGE + 255) / 256, 256>>>(edge_index);

    // GAT aggregation -> Xh/Xl cols 0:768 (fp16 split, direct)
    k_gat_aggr<<<(NNODE * 32 + 255) / 256, 256>>>(b_gat);

    // P = x @ Wcat  (fp16 2-term split)
    k_splitW2<<<(PD * XDP + 255) / 256, 256>>>(W_nbr, W_self);
    k_gemm2<<<dim3(PD / 128, NNODE / 128), 256, GEMM_SMEM>>>();

    // final per-node aggregation (fused edge learner) -> out
    k_meta<<<(NNODE * 32 + 255) / 256, 256>>>(out, b_nbr, b_self, W_nbr,
                                              W_edge, b_edge, edge_attr);
}

// round 8
// speedup vs baseline: 1.5372x; 1.2626x over previous
#include <cuda_runtime.h>
#include <cuda_fp16.h>
#include <cstdint>

// ---------------- problem constants ----------------
#define NNODE 16000
#define NEDGE 128000
#define GATD 768          // GAT dim
#define XD 800            // meta-in dim (768 gat + 32 node)
#define XDP 832           // padded K for GEMM2 (26 x 32)
#define MD 128            // meta out dim
#define PD 384            // P1(dst part) | P2(src part) | Xself

// ---------------- device scratch (no allocs allowed) ----------------
__device__ float    g_h[NNODE * GATD];       // 49 MB
__device__ float    g_P[NNODE * PD];         // 24.6 MB
__device__ float    g_asrc[NNODE];
__device__ float    g_adst[NNODE];
__device__ unsigned g_amax[NNODE];           // ordered-float bits
__device__ float    g_denom[NNODE];
__device__ float    g_alphaE[NEDGE];
__device__ int      g_deg[NNODE];
__device__ int      g_rowstart[NNODE];
__device__ int      g_pos[NNODE];
__device__ int      g_csr_src[NEDGE];
__device__ int      g_csr_eid[NEDGE];
__device__ float    g_csr_ex[NEDGE];
// fp16 operands
__device__ __half g_A1[NNODE * GATD];
__device__ __half g_X[NNODE * XDP];
__device__ __half g_W1[GATD * GATD];   // W_gat^T  [n,k]
__device__ __half g_W2[PD * XDP];      // Wcat^T   [n,k]

// ---------------- helpers ----------------
__device__ __forceinline__ float lrelu(float x) { return x >= 0.f ? x : 0.2f * x; }
__device__ __forceinline__ unsigned f2o(float f) {
    unsigned b = __float_as_uint(f);
    return (b & 0x80000000u) ? ~b : (b | 0x80000000u);
}
__device__ __forceinline__ float o2f(unsigned b) {
    b = (b & 0x80000000u) ? (b & 0x7fffffffu) : ~b;
    return __uint_as_float(b);
}
__device__ __forceinline__ uint32_t smem_u32(const void* p) {
    uint32_t a;
    asm("{ .reg .u64 t; cvta.to.shared.u64 t, %1; cvt.u32.u64 %0, t; }" : "=r"(a) : "l"(p));
    return a;
}
__device__ __forceinline__ void ldm_x4(uint32_t& r0, uint32_t& r1, uint32_t& r2, uint32_t& r3,
                                       uint32_t addr) {
    asm volatile("ldmatrix.sync.aligned.m8n8.x4.shared.b16 {%0,%1,%2,%3}, [%4];"
                 : "=r"(r0), "=r"(r1), "=r"(r2), "=r"(r3) : "r"(addr));
}
__device__ __forceinline__ void mma16816(float* c, const uint32_t* a, uint32_t b0, uint32_t b1) {
    asm volatile(
        "mma.sync.aligned.m16n8k16.row.col.f32.f16.f16.f32 "
        "{%0,%1,%2,%3}, {%4,%5,%6,%7}, {%8,%9}, {%0,%1,%2,%3};"
        : "+f"(c[0]), "+f"(c[1]), "+f"(c[2]), "+f"(c[3])
        : "r"(a[0]), "r"(a[1]), "r"(a[2]), "r"(a[3]), "r"(b0), "r"(b1));
}
__device__ __forceinline__ void cp16(uint32_t dst, const void* src) {
    asm volatile("cp.async.cg.shared.global [%0], [%1], 16;" :: "r"(dst), "l"(src));
}
#define CP_COMMIT() asm volatile("cp.async.commit_group;" ::: "memory")
#define CP_WAIT2()  asm volatile("cp.async.wait_group 2;" ::: "memory")
#define CP_WAIT1()  asm volatile("cp.async.wait_group 1;" ::: "memory")
#define CP_WAIT0()  asm volatile("cp.async.wait_group 0;" ::: "memory")

// ---------------- node learner (writes fp16 x cols 768:832) ----------------
__global__ void k_nodeL(const float* __restrict__ nf, const float* __restrict__ W,
                        const float* __restrict__ b) {
    int idx = blockIdx.x * blockDim.x + threadIdx.x;
    if (idx >= NNODE * 32) return;
    int i = idx >> 5, j = idx & 31;
    const float* r = nf + i * 32;
    float s = b[j];
#pragma unroll
    for (int k = 0; k < 32; k++) s += r[k] * W[k * 32 + j];
    size_t base = (size_t)i * XDP;
    g_X[base + 768 + j] = __float2half_rn(s);
    g_X[base + 800 + j] = __float2half(0.f);
}

// ---------------- prep kernels ----------------
__global__ void k_cvtA1(const float* __restrict__ src) {
    int idx = blockIdx.x * blockDim.x + threadIdx.x;
    if (idx < NNODE) { g_asrc[idx] = 0.f; g_adst[idx] = 0.f; }
    if (idx >= NNODE * GATD) return;
    g_A1[idx] = __float2half_rn(src[idx]);
}
// coalesced 32x32 tiled transpose of W_gat -> fp16
__global__ void k_cvtW1(const float* __restrict__ Wg) {
    __shared__ float tile[32][33];
    int tx = threadIdx.x, ty = threadIdx.y;       // block 32x8
    int n0 = blockIdx.x * 32, k0 = blockIdx.y * 32;
#pragma unroll
    for (int i = 0; i < 4; i++)
        tile[ty + i * 8][tx] = Wg[(size_t)(k0 + ty + i * 8) * GATD + n0 + tx];
    __syncthreads();
#pragma unroll
    for (int i = 0; i < 4; i++) {
        size_t o = (size_t)(n0 + ty + i * 8) * GATD + k0 + tx;
        g_W1[o] = __float2half_rn(tile[tx][ty + i * 8]);
    }
}
__global__ void k_cvtW2(const float* __restrict__ Wn, const float* __restrict__ Ws) {
    int idx = blockIdx.x * blockDim.x + threadIdx.x;
    if (idx >= PD * XDP) return;
    int n = idx / XDP, k = idx % XDP;
    float v = 0.f;
    if (k < XD) {
        if (n < 128)      v = Wn[k * 128 + n];
        else if (n < 256) v = Wn[(800 + k) * 128 + (n - 128)];
        else              v = Ws[k * 128 + (n - 256)];
    }
    g_W2[idx] = __float2half_rn(v);
}

// ---------------- warp-MMA fp16 GEMM (cp.async 3-stage) ----------------
// C[M,CN] = A @ B^T.  Block tile 128x128, 8 warps (2x4), K chunk 32.
#define ASTRIDE 40
#define TILE_BYTES 10240                  // 128*40*2
#define STAGE_BYTES (2 * TILE_BYTES)      // A|B

template <int CN, int KPAD, int NCH, bool DO_ATT>
__device__ __forceinline__ void mma_gemm_body(const __half* __restrict__ A,
                                              const __half* __restrict__ B,
                                              float* __restrict__ C,
                                              const float* __restrict__ att_s,
                                              const float* __restrict__ att_d) {
    extern __shared__ char smem[];
    const uint32_t sb = smem_u32(smem);

    const int t = threadIdx.x;
    const int lane = t & 31;
    const int wid = t >> 5;
    const int m0 = (wid >> 2) * 64;
    const int n0 = (wid & 3) * 32;
    const int bm = blockIdx.y * 128;
    const int bn = blockIdx.x * 128;

    const uint32_t aoff = (uint32_t)(((lane & 15) * ASTRIDE + (lane >> 4) * 8) * 2);
    const uint32_t boff = (uint32_t)((((lane & 7) + ((lane >> 4) << 3)) * ASTRIDE +
                                     (((lane >> 3) & 1) << 3)) * 2);

    float acc[4][4][4];
#pragma unroll
    for (int i = 0; i < 4; i++)
#pragma unroll
        for (int j = 0; j < 4; j++)
#pragma unroll
            for (int q = 0; q < 4; q++) acc[i][j][q] = 0.f;

    auto issue_chunk = [&](int c, int s) {
        const int c0 = c * 32;
        const uint32_t dst = sb + (uint32_t)s * STAGE_BYTES;
#pragma unroll
        for (int it = 0; it < 2; it++) {
            int idx = it * 256 + t;
            int r = idx >> 2, j = idx & 3;
            size_t ga = (size_t)(bm + r) * KPAD + c0 + j * 8;
            size_t gb = (size_t)(bn + r) * KPAD + c0 + j * 8;
            uint32_t doff = (uint32_t)((r * ASTRIDE + j * 8) * 2);
            cp16(dst + doff, A + ga);
            cp16(dst + TILE_BYTES + doff, B + gb);
        }
    };

    issue_chunk(0, 0);
    CP_COMMIT();
    issue_chunk(1, 1);
    CP_COMMIT();

    for (int c = 0; c < NCH; c++) {
        const int s = c % 3;
        if (c + 2 < NCH) {
            issue_chunk(c + 2, (c + 2) % 3);
            CP_COMMIT();
            CP_WAIT2();
        } else if (c + 1 < NCH) {
            CP_WAIT1();
        } else {
            CP_WAIT0();
        }
        __syncthreads();

        const uint32_t baseA = sb + (uint32_t)s * STAGE_BYTES;
        const uint32_t baseB = baseA + TILE_BYTES;

#pragma unroll
        for (int ks = 0; ks < 2; ks++) {
            const uint32_t kb = (uint32_t)(ks * 16 * 2);
            uint32_t bh[2][4];
#pragma unroll
            for (int p = 0; p < 2; p++) {
                uint32_t off = boff + (uint32_t)((n0 + p * 16) * ASTRIDE * 2) + kb;
                ldm_x4(bh[p][0], bh[p][1], bh[p][2], bh[p][3], baseB + off);
            }
#pragma unroll
            for (int tm = 0; tm < 4; tm++) {
                uint32_t off = aoff + (uint32_t)((m0 + tm * 16) * ASTRIDE * 2) + kb;
                uint32_t ah[4];
                ldm_x4(ah[0], ah[1], ah[2], ah[3], baseA + off);
#pragma unroll
                for (int tn = 0; tn < 4; tn++) {
                    int p = tn >> 1, q = tn & 1;
                    mma16816(acc[tm][tn], ah, bh[p][q * 2], bh[p][q * 2 + 1]);
                }
            }
        }
        __syncthreads();
    }

    // epilogue: store C (+ optional fused attention partial dots)
    const int rit = lane >> 2;
    const int cq = (lane & 3) * 2;
#pragma unroll
    for (int tm = 0; tm < 4; tm++) {
        float s1a = 0.f, s2a = 0.f, s1b = 0.f, s2b = 0.f;
#pragma unroll
        for (int tn = 0; tn < 4; tn++) {
            size_t row = (size_t)(bm + m0 + tm * 16 + rit);
            int col = bn + n0 + tn * 8 + cq;
            *(float2*)&C[row * CN + col] = make_float2(acc[tm][tn][0], acc[tm][tn][1]);
            *(float2*)&C[(row + 8) * CN + col] = make_float2(acc[tm][tn][2], acc[tm][tn][3]);
            if (DO_ATT) {
                float a0 = __ldg(att_s + col), a1 = __ldg(att_s + col + 1);
                float d0 = __ldg(att_d + col), d1 = __ldg(att_d + col + 1);
                s1a += acc[tm][tn][0] * a0 + acc[tm][tn][1] * a1;
                s2a += acc[tm][tn][0] * d0 + acc[tm][tn][1] * d1;
                s1b += acc[tm][tn][2] * a0 + acc[tm][tn][3] * a1;
                s2b += acc[tm][tn][2] * d0 + acc[tm][tn][3] * d1;
            }
        }
        if (DO_ATT) {
#pragma unroll
            for (int off = 1; off < 4; off <<= 1) {
                s1a += __shfl_xor_sync(0xffffffffu, s1a, off);
                s2a += __shfl_xor_sync(0xffffffffu, s2a, off);
                s1b += __shfl_xor_sync(0xffffffffu, s1b, off);
                s2b += __shfl_xor_sync(0xffffffffu, s2b, off);
            }
            if ((lane & 3) == 0) {
                int rowA = bm + m0 + tm * 16 + rit;
                atomicAdd(&g_asrc[rowA], s1a);
                atomicAdd(&g_adst[rowA], s2a);
                atomicAdd(&g_asrc[rowA + 8], s1b);
                atomicAdd(&g_adst[rowA + 8], s2b);
            }
        }
    }
}

__global__ void __launch_bounds__(256) k_gemm1(const float* __restrict__ att_s,
                                               const float* __restrict__ att_d) {
    mma_gemm_body<GATD, GATD, 24, true>(g_A1, g_W1, g_h, att_s, att_d);
}
__global__ void __launch_bounds__(256) k_gemm2() {
    mma_gemm_body<PD, XDP, 26, false>(g_X, g_W2, g_P, nullptr, nullptr);
}

// ---------------- node init (after gemm1: asrc/adst final) ----------------
__global__ void k_init_node() {
    int i = blockIdx.x * blockDim.x + threadIdx.x;
    if (i >= NNODE) return;
    float al = lrelu(g_asrc[i] + g_adst[i]);   // self-loop alpha
    g_amax[i] = f2o(al);
    g_deg[i] = 0;
}

__global__ void k_edge_alpha(const int* __restrict__ ei) {
    int e = blockIdx.x * blockDim.x + threadIdx.x;
    if (e >= NEDGE) return;
    int s = ei[e], d = ei[NEDGE + e];
    float al = lrelu(g_asrc[s] + g_adst[d]);
    g_alphaE[e] = al;
    atomicMax(&g_amax[d], f2o(al));
    atomicAdd(&g_deg[d], 1);
}

// exclusive scan of deg -> rowstart/pos; phase 2: denom self-loop init
__global__ void k_scan() {
    __shared__ int sh[1024];
    __shared__ int s_carry;
    int tid = threadIdx.x;
    if (tid == 0) s_carry = 0;
    __syncthreads();
    for (int base = 0; base < NNODE; base += 1024) {
        int i = base + tid;
        int v = (i < NNODE) ? g_deg[i] : 0;
        sh[tid] = v;
        __syncthreads();
        for (int off = 1; off < 1024; off <<= 1) {
            int t = (tid >= off) ? sh[tid - off] : 0;
            __syncthreads();
            sh[tid] += t;
            __syncthreads();
        }
        int incl = sh[tid];
        int carry = s_carry;
        if (i < NNODE) {
            int excl = carry + incl - v;
            g_rowstart[i] = excl;
            g_pos[i] = excl;
        }
        __syncthreads();
        if (tid == 1023) s_carry = carry + incl;
        __syncthreads();
    }
    for (int i = tid; i < NNODE; i += 1024) {
        float al = lrelu(g_asrc[i] + g_adst[i]);
        g_denom[i] = expf(al - o2f(g_amax[i]));
    }
}

// fused CSR fill + exp + denom accumulate
__global__ void k_edge_build(const int* __restrict__ ei) {
    int e = blockIdx.x * blockDim.x + threadIdx.x;
    if (e >= NEDGE) return;
    int s = ei[e], d = ei[NEDGE + e];
    int p = atomicAdd(&g_pos[d], 1);
    g_csr_src[p] = s;
    g_csr_eid[p] = e;
    float ex = expf(g_alphaE[e] - o2f(g_amax[d]));
    g_csr_ex[p] = ex;
    atomicAdd(&g_denom[d], ex);
}

// ---------------- GAT gather-aggregation: warp per node, writes fp16 x ----------------
__global__ void k_gat_aggr(const float* __restrict__ b_gat) {
    int warp = (blockIdx.x * blockDim.x + threadIdx.x) >> 5;
    int lane = threadIdx.x & 31;
    if (warp >= NNODE) return;
    int i = warp;
    float amaxv = o2f(g_amax[i]);
    float als = lrelu(g_asrc[i] + g_adst[i]);
    float inv_den = 1.0f / g_denom[i];
    float cs = expf(als - amaxv) * inv_den;

    const float4* hrow = (const float4*)(g_h + (size_t)i * GATD);
    const float4* bg = (const float4*)b_gat;
    float4 acc[6];
#pragma unroll
    for (int t = 0; t < 6; t++) {
        float4 hv = hrow[lane + 32 * t];
        float4 bv = bg[lane + 32 * t];
        acc[t].x = cs * hv.x + bv.x;
        acc[t].y = cs * hv.y + bv.y;
        acc[t].z = cs * hv.z + bv.z;
        acc[t].w = cs * hv.w + bv.w;
    }
    int rs = g_rowstart[i], d = g_deg[i];
    for (int base = 0; base < d; base += 32) {
        int cnt = min(32, d - base);
        int sj = 0;
        float cj = 0.f;
        if (lane < cnt) {
            sj = g_csr_src[rs + base + lane];
            cj = g_csr_ex[rs + base + lane] * inv_den;
        }
        for (int k = 0; k < cnt; k++) {
            int s = __shfl_sync(0xffffffffu, sj, k);
            float coef = __shfl_sync(0xffffffffu, cj, k);
            const float4* hs = (const float4*)(g_h + (size_t)s * GATD);
#pragma unroll
            for (int t = 0; t < 6; t++) {
                float4 hv = __ldg(&hs[lane + 32 * t]);
                acc[t].x += coef * hv.x;
                acc[t].y += coef * hv.y;
                acc[t].z += coef * hv.z;
                acc[t].w += coef * hv.w;
            }
        }
    }
    size_t xbase = (size_t)i * XDP;
#pragma unroll
    for (int t = 0; t < 6; t++) {
        int col = 4 * (lane + 32 * t);
        __half2* px = (__half2*)(g_X + xbase + col);
        px[0] = __half2(__float2half_rn(acc[t].x), __float2half_rn(acc[t].y));
        px[1] = __half2(__float2half_rn(acc[t].z), __float2half_rn(acc[t].w));
    }
}

// ---------------- final aggregation (fused edge learner + ea@We): warp per node ----------------
__global__ void k_meta(float* __restrict__ out, const float* __restrict__ b_nbr,
                       const float* __restrict__ b_self, const float* __restrict__ W_nbr,
                       const float* __restrict__ W_edge, const float* __restrict__ b_edge,
                       const float* __restrict__ edge_attr) {
    __shared__ float sWe[16 * 128];
    __shared__ float sWE[16 * 16];
    __shared__ float sBN[128];
    for (int t = threadIdx.x; t < 2048; t += blockDim.x)
        sWe[t] = W_nbr[1600 * 128 + t];
    for (int t = threadIdx.x; t < 256; t += blockDim.x)
        sWE[t] = W_edge[t];
    __syncthreads();
    if (threadIdx.x < 128) {
        int c = threadIdx.x;
        float s = b_nbr[c];
#pragma unroll
        for (int k = 0; k < 16; k++) s += b_edge[k] * sWe[k * 128 + c];
        sBN[c] = s;
    }
    __syncthreads();

    int warp = (blockIdx.x * blockDim.x + threadIdx.x) >> 5;
    int lane = threadIdx.x & 31;
    if (warp >= NNODE) return;
    int i = warp;
    const float4* Pr = (const float4*)(g_P + (size_t)i * PD);
    float4 p1 = Pr[lane];        // dst-part
    float4 xs = Pr[64 + lane];   // self-part
    float4 bs = ((const float4*)b_self)[lane];
    float4 bn4 = *(const float4*)&sBN[lane * 4];
    float degf = (float)g_deg[i];
    float4 acc;
    acc.x = xs.x + bs.x + degf * (p1.x + bn4.x);
    acc.y = xs.y + bs.y + degf * (p1.y + bn4.y);
    acc.z = xs.z + bs.z + degf * (p1.z + bn4.z);
    acc.w = xs.w + bs.w + degf * (p1.w + bn4.w);

    float eas[16];
#pragma unroll
    for (int k = 0; k < 16; k++) eas[k] = 0.f;

    int rs = g_rowstart[i], d = g_deg[i];
    for (int base = 0; base < d; base += 32) {
        int cnt = min(32, d - base);
        int sj = 0, ej = 0;
        if (lane < cnt) {
            sj = g_csr_src[rs + base + lane];
            ej = g_csr_eid[rs + base + lane];
        }
        for (int k = 0; k < cnt; k++) {
            int s = __shfl_sync(0xffffffffu, sj, k);
            int e = __shfl_sync(0xffffffffu, ej, k);
            float4 p2 = __ldg(&((const float4*)(g_P + (size_t)s * PD))[32 + lane]);
            acc.x += p2.x;
            acc.y += p2.y;
            acc.z += p2.z;
            acc.w += p2.w;
            const float4* ear = (const float4*)(edge_attr + (size_t)e * 16);
            float4 e0 = __ldg(ear), e1 = __ldg(ear + 1), e2 = __ldg(ear + 2), e3 = __ldg(ear + 3);
            eas[0] += e0.x;  eas[1] += e0.y;  eas[2] += e0.z;  eas[3] += e0.w;
            eas[4] += e1.x;  eas[5] += e1.y;  eas[6] += e1.z;  eas[7] += e1.w;
            eas[8] += e2.x;  eas[9] += e2.y;  eas[10] += e2.z; eas[11] += e2.w;
            eas[12] += e3.x; eas[13] += e3.y; eas[14] += e3.z; eas[15] += e3.w;
        }
    }

    float tv[16];
#pragma unroll
    for (int kk = 0; kk < 16; kk++) {
        float s = 0.f;
#pragma unroll
        for (int j = 0; j < 16; j++) s += eas[j] * sWE[j * 16 + kk];
        tv[kk] = s;
    }
    int col = lane * 4;
#pragma unroll
    for (int kk = 0; kk < 16; kk++) {
        float4 wv = *(const float4*)&sWe[kk * 128 + col];
        float ev = tv[kk];
        acc.x += ev * wv.x;
        acc.y += ev * wv.y;
        acc.z += ev * wv.z;
        acc.w += ev * wv.w;
    }
    ((float4*)(out + (size_t)i * MD))[lane] = acc;
}

// ---------------- launch ----------------
extern "C" void kernel_launch(void* const* d_in, const int* in_sizes, int n_in,
                              void* d_out, int out_size) {
    const float* node_feature    = (const float*)d_in[0];
    const float* edge_attr       = (const float*)d_in[1];
    const float* message_feature = (const float*)d_in[2];
    const int*   edge_index      = (const int*)d_in[3];
    const float* W_node = (const float*)d_in[4];
    const float* b_node = (const float*)d_in[5];
    const float* W_edge = (const float*)d_in[6];
    const float* b_edge = (const float*)d_in[7];
    const float* W_gat  = (const float*)d_in[8];
    const float* att_src = (const float*)d_in[9];
    const float* att_dst = (const float*)d_in[10];
    const float* b_gat  = (const float*)d_in[11];
    const float* W_nbr  = (const float*)d_in[12];
    const float* b_nbr  = (const float*)d_in[13];
    const float* W_self = (const float*)d_in[14];
    const float* b_self = (const float*)d_in[15];
    float* out = (float*)d_out;

    const int GEMM_SMEM = 3 * STAGE_BYTES;   // 61440 (3 stages x A|B)
    cudaFuncSetAttribute(k_gemm1, cudaFuncAttributeMaxDynamicSharedMemorySize, GEMM_SMEM);
    cudaFuncSetAttribute(k_gemm2, cudaFuncAttributeMaxDynamicSharedMemorySize, GEMM_SMEM);

    // prep
    k_nodeL<<<(NNODE * 32 + 255) / 256, 256>>>(node_feature, W_node, b_node);
    k_cvtA1<<<(NNODE * GATD + 255) / 256, 256>>>(message_feature);
    k_cvtW1<<<dim3(GATD / 32, GATD / 32), dim3(32, 8)>>>(W_gat);

    // h = mf @ W_gat  (+ fused attention scalar partial dots)
    k_gemm1<<<dim3(GATD / 128, NNODE / 128), 256, GEMM_SMEM>>>(att_src, att_dst);

    // softmax structure
    k_init_node<<<(NNODE + 255) / 256, 256>>>();
    k_edge_alpha<<<(NEDGE + 255) / 256, 256>>>(edge_index);
    k_scan<<<1, 1024>>>();
    k_edge_build<<<(NEDGE + 255) / 256, 256>>>(edge_index);

    // GAT aggregation -> X cols 0:768 (fp16, direct)
    k_gat_aggr<<<(NNODE * 32 + 255) / 256, 256>>>(b_gat);

    // P = x @ Wcat  (fp16)
    k_cvtW2<<<(PD * XDP + 255) / 256, 256>>>(W_nbr, W_self);
    k_gemm2<<<dim3(PD / 128, NNODE / 128), 256, GEMM_SMEM>>>();

    // final per-node aggregation (fused edge learner) -> out
    k_meta<<<(NNODE * 32 + 255) / 256, 256>>>(out, b_nbr, b_self, W_nbr,
                                              W_edge, b_edge, edge_attr);
}

// round 9
// speedup vs baseline: 1.8296x; 1.1902x over previous
#include <cuda_runtime.h>
#include <cuda_fp16.h>
#include <cstdint>

// ---------------- problem constants ----------------
#define NNODE 16000
#define NEDGE 128000
#define GATD 768          // GAT dim
#define XD 800            // meta-in dim (768 gat + 32 node)
#define XDP 832           // padded K for GEMM2 (13 x 64)
#define MD 128            // meta out dim
#define PD 384            // P1(dst part) | P2(src part) | Xself

// ---------------- device scratch (no allocs allowed) ----------------
__device__ __half   g_hh[NNODE * GATD];      // h in fp16 (only consumer: gather)
__device__ float    g_P[NNODE * PD];         // 24.6 MB
__device__ float    g_asrc[NNODE];
__device__ float    g_adst[NNODE];
__device__ unsigned g_amax[NNODE];           // ordered-float bits
__device__ float    g_denom[NNODE];
__device__ float    g_alphaE[NEDGE];
__device__ int      g_deg[NNODE];
__device__ int      g_rowstart[NNODE];
__device__ int      g_pos[NNODE];
__device__ int      g_csr_src[NEDGE];
__device__ int      g_csr_eid[NEDGE];
__device__ float    g_csr_ex[NEDGE];
// fp16 operands
__device__ __half g_A1[NNODE * GATD];
__device__ __half g_X[NNODE * XDP];
__device__ __half g_W1[GATD * GATD];   // W_gat^T  [n,k]
__device__ __half g_W2[PD * XDP];      // Wcat^T   [n,k]

// ---------------- helpers ----------------
__device__ __forceinline__ float lrelu(float x) { return x >= 0.f ? x : 0.2f * x; }
__device__ __forceinline__ unsigned f2o(float f) {
    unsigned b = __float_as_uint(f);
    return (b & 0x80000000u) ? ~b : (b | 0x80000000u);
}
__device__ __forceinline__ float o2f(unsigned b) {
    b = (b & 0x80000000u) ? (b & 0x7fffffffu) : ~b;
    return __uint_as_float(b);
}
__device__ __forceinline__ uint32_t smem_u32(const void* p) {
    uint32_t a;
    asm("{ .reg .u64 t; cvta.to.shared.u64 t, %1; cvt.u32.u64 %0, t; }" : "=r"(a) : "l"(p));
    return a;
}
__device__ __forceinline__ void ldm_x4(uint32_t& r0, uint32_t& r1, uint32_t& r2, uint32_t& r3,
                                       uint32_t addr) {
    asm volatile("ldmatrix.sync.aligned.m8n8.x4.shared.b16 {%0,%1,%2,%3}, [%4];"
                 : "=r"(r0), "=r"(r1), "=r"(r2), "=r"(r3) : "r"(addr));
}
__device__ __forceinline__ void mma16816(float* c, const uint32_t* a, uint32_t b0, uint32_t b1) {
    asm volatile(
        "mma.sync.aligned.m16n8k16.row.col.f32.f16.f16.f32 "
        "{%0,%1,%2,%3}, {%4,%5,%6,%7}, {%8,%9}, {%0,%1,%2,%3};"
        : "+f"(c[0]), "+f"(c[1]), "+f"(c[2]), "+f"(c[3])
        : "r"(a[0]), "r"(a[1]), "r"(a[2]), "r"(a[3]), "r"(b0), "r"(b1));
}
__device__ __forceinline__ void cp16(uint32_t dst, const void* src) {
    asm volatile("cp.async.cg.shared.global [%0], [%1], 16;" :: "r"(dst), "l"(src));
}
#define CP_COMMIT() asm volatile("cp.async.commit_group;" ::: "memory")
#define CP_WAIT2()  asm volatile("cp.async.wait_group 2;" ::: "memory")
#define CP_WAIT1()  asm volatile("cp.async.wait_group 1;" ::: "memory")
#define CP_WAIT0()  asm volatile("cp.async.wait_group 0;" ::: "memory")

__device__ __forceinline__ void unpack8(uint4 v, float* f) {
    float2 a = __half22float2(*(__half2*)&v.x);
    float2 b = __half22float2(*(__half2*)&v.y);
    float2 c = __half22float2(*(__half2*)&v.z);
    float2 d = __half22float2(*(__half2*)&v.w);
    f[0] = a.x; f[1] = a.y; f[2] = b.x; f[3] = b.y;
    f[4] = c.x; f[5] = c.y; f[6] = d.x; f[7] = d.y;
}
__device__ __forceinline__ uint4 pack8(const float* f) {
    uint4 o;
    __half2 h0 = __floats2half2_rn(f[0], f[1]);
    __half2 h1 = __floats2half2_rn(f[2], f[3]);
    __half2 h2 = __floats2half2_rn(f[4], f[5]);
    __half2 h3 = __floats2half2_rn(f[6], f[7]);
    o.x = *(uint32_t*)&h0; o.y = *(uint32_t*)&h1;
    o.z = *(uint32_t*)&h2; o.w = *(uint32_t*)&h3;
    return o;
}

// ---------------- node learner (writes fp16 x cols 768:832) ----------------
__global__ void k_nodeL(const float* __restrict__ nf, const float* __restrict__ W,
                        const float* __restrict__ b) {
    int idx = blockIdx.x * blockDim.x + threadIdx.x;
    if (idx >= NNODE * 32) return;
    int i = idx >> 5, j = idx & 31;
    const float* r = nf + i * 32;
    float s = b[j];
#pragma unroll
    for (int k = 0; k < 32; k++) s += r[k] * W[k * 32 + j];
    size_t base = (size_t)i * XDP;
    g_X[base + 768 + j] = __float2half_rn(s);
    g_X[base + 800 + j] = __float2half(0.f);
}

// ---------------- prep kernels ----------------
__global__ void k_cvtA1(const float* __restrict__ src) {
    int idx = blockIdx.x * blockDim.x + threadIdx.x;
    if (idx < NNODE) { g_asrc[idx] = 0.f; g_adst[idx] = 0.f; }
    if (idx >= NNODE * GATD / 2) return;
    float2 v = ((const float2*)src)[idx];
    __half2 h = __floats2half2_rn(v.x, v.y);
    ((__half2*)g_A1)[idx] = h;
}
// coalesced 32x32 tiled transpose of W_gat -> fp16
__global__ void k_cvtW1(const float* __restrict__ Wg) {
    __shared__ float tile[32][33];
    int tx = threadIdx.x, ty = threadIdx.y;       // block 32x8
    int n0 = blockIdx.x * 32, k0 = blockIdx.y * 32;
#pragma unroll
    for (int i = 0; i < 4; i++)
        tile[ty + i * 8][tx] = Wg[(size_t)(k0 + ty + i * 8) * GATD + n0 + tx];
    __syncthreads();
#pragma unroll
    for (int i = 0; i < 4; i++) {
        size_t o = (size_t)(n0 + ty + i * 8) * GATD + k0 + tx;
        g_W1[o] = __float2half_rn(tile[tx][ty + i * 8]);
    }
}
__global__ void k_cvtW2(const float* __restrict__ Wn, const float* __restrict__ Ws) {
    int idx = blockIdx.x * blockDim.x + threadIdx.x;
    if (idx >= PD * XDP) return;
    int n = idx / XDP, k = idx % XDP;
    float v = 0.f;
    if (k < XD) {
        if (n < 128)      v = Wn[k * 128 + n];
        else if (n < 256) v = Wn[(800 + k) * 128 + (n - 128)];
        else              v = Ws[k * 128 + (n - 256)];
    }
    g_W2[idx] = __float2half_rn(v);
}

// ---------------- warp-MMA fp16 GEMM (cp.async 3-stage, K chunk 64) ----------------
// C[M,CN] = A @ B^T.  Block tile 128x128, 8 warps (2x4).
#define ASTRIDE 72
#define TILE_BYTES 18432                  // 128*72*2
#define STAGE_BYTES (2 * TILE_BYTES)      // A|B

template <int CN, int KPAD, int NCH, bool DO_ATT, bool HALF_OUT>
__device__ __forceinline__ void mma_gemm_body(const __half* __restrict__ A,
                                              const __half* __restrict__ B,
                                              float* __restrict__ Cf,
                                              __half* __restrict__ Ch,
                                              const float* __restrict__ att_s,
                                              const float* __restrict__ att_d) {
    extern __shared__ char smem[];
    const uint32_t sb = smem_u32(smem);

    const int t = threadIdx.x;
    const int lane = t & 31;
    const int wid = t >> 5;
    const int m0 = (wid >> 2) * 64;
    const int n0 = (wid & 3) * 32;
    const int bm = blockIdx.y * 128;
    const int bn = blockIdx.x * 128;

    const uint32_t aoff = (uint32_t)(((lane & 15) * ASTRIDE + (lane >> 4) * 8) * 2);
    const uint32_t boff = (uint32_t)((((lane & 7) + ((lane >> 4) << 3)) * ASTRIDE +
                                     (((lane >> 3) & 1) << 3)) * 2);

    float acc[4][4][4];
#pragma unroll
    for (int i = 0; i < 4; i++)
#pragma unroll
        for (int j = 0; j < 4; j++)
#pragma unroll
            for (int q = 0; q < 4; q++) acc[i][j][q] = 0.f;

    auto issue_chunk = [&](int c, int s) {
        const int c0 = c * 64;
        const uint32_t dst = sb + (uint32_t)s * STAGE_BYTES;
#pragma unroll
        for (int it = 0; it < 4; it++) {
            int idx = it * 256 + t;
            int r = idx >> 3, j = idx & 7;            // 128 rows x 8 16B segs
            size_t ga = (size_t)(bm + r) * KPAD + c0 + j * 8;
            size_t gb = (size_t)(bn + r) * KPAD + c0 + j * 8;
            uint32_t doff = (uint32_t)((r * ASTRIDE + j * 8) * 2);
            cp16(dst + doff, A + ga);
            cp16(dst + TILE_BYTES + doff, B + gb);
        }
    };

    issue_chunk(0, 0);
    CP_COMMIT();
    issue_chunk(1, 1);
    CP_COMMIT();

    for (int c = 0; c < NCH; c++) {
        const int s = c % 3;
        if (c + 2 < NCH) {
            issue_chunk(c + 2, (c + 2) % 3);
            CP_COMMIT();
            CP_WAIT2();
        } else if (c + 1 < NCH) {
            CP_WAIT1();
        } else {
            CP_WAIT0();
        }
        __syncthreads();

        const uint32_t baseA = sb + (uint32_t)s * STAGE_BYTES;
        const uint32_t baseB = baseA + TILE_BYTES;

#pragma unroll
        for (int ks = 0; ks < 4; ks++) {
            const uint32_t kb = (uint32_t)(ks * 16 * 2);
            uint32_t bh[2][4];
#pragma unroll
            for (int p = 0; p < 2; p++) {
                uint32_t off = boff + (uint32_t)((n0 + p * 16) * ASTRIDE * 2) + kb;
                ldm_x4(bh[p][0], bh[p][1], bh[p][2], bh[p][3], baseB + off);
            }
#pragma unroll
            for (int tm = 0; tm < 4; tm++) {
                uint32_t off = aoff + (uint32_t)((m0 + tm * 16) * ASTRIDE * 2) + kb;
                uint32_t ah[4];
                ldm_x4(ah[0], ah[1], ah[2], ah[3], baseA + off);
#pragma unroll
                for (int tn = 0; tn < 4; tn++) {
                    int p = tn >> 1, q = tn & 1;
                    mma16816(acc[tm][tn], ah, bh[p][q * 2], bh[p][q * 2 + 1]);
                }
            }
        }
        __syncthreads();
    }

    // epilogue: store C (+ optional fused attention partial dots)
    const int rit = lane >> 2;
    const int cq = (lane & 3) * 2;
#pragma unroll
    for (int tm = 0; tm < 4; tm++) {
        float s1a = 0.f, s2a = 0.f, s1b = 0.f, s2b = 0.f;
#pragma unroll
        for (int tn = 0; tn < 4; tn++) {
            size_t row = (size_t)(bm + m0 + tm * 16 + rit);
            int col = bn + n0 + tn * 8 + cq;
            if (HALF_OUT) {
                __half2 v0 = __floats2half2_rn(acc[tm][tn][0], acc[tm][tn][1]);
                __half2 v1 = __floats2half2_rn(acc[tm][tn][2], acc[tm][tn][3]);
                *(__half2*)&Ch[row * CN + col] = v0;
                *(__half2*)&Ch[(row + 8) * CN + col] = v1;
            } else {
                *(float2*)&Cf[row * CN + col] = make_float2(acc[tm][tn][0], acc[tm][tn][1]);
                *(float2*)&Cf[(row + 8) * CN + col] = make_float2(acc[tm][tn][2], acc[tm][tn][3]);
            }
            if (DO_ATT) {
                float a0 = __ldg(att_s + col), a1 = __ldg(att_s + col + 1);
                float d0 = __ldg(att_d + col), d1 = __ldg(att_d + col + 1);
                s1a += acc[tm][tn][0] * a0 + acc[tm][tn][1] * a1;
                s2a += acc[tm][tn][0] * d0 + acc[tm][tn][1] * d1;
                s1b += acc[tm][tn][2] * a0 + acc[tm][tn][3] * a1;
                s2b += acc[tm][tn][2] * d0 + acc[tm][tn][3] * d1;
            }
        }
        if (DO_ATT) {
#pragma unroll
            for (int off = 1; off < 4; off <<= 1) {
                s1a += __shfl_xor_sync(0xffffffffu, s1a, off);
                s2a += __shfl_xor_sync(0xffffffffu, s2a, off);
                s1b += __shfl_xor_sync(0xffffffffu, s1b, off);
                s2b += __shfl_xor_sync(0xffffffffu, s2b, off);
            }
            if ((lane & 3) == 0) {
                int rowA = bm + m0 + tm * 16 + rit;
                atomicAdd(&g_asrc[rowA], s1a);
                atomicAdd(&g_adst[rowA], s2a);
                atomicAdd(&g_asrc[rowA + 8], s1b);
                atomicAdd(&g_adst[rowA + 8], s2b);
            }
        }
    }
}

__global__ void __launch_bounds__(256, 2) k_gemm1(const float* __restrict__ att_s,
                                                  const float* __restrict__ att_d) {
    mma_gemm_body<GATD, GATD, 12, true, true>(g_A1, g_W1, nullptr, g_hh, att_s, att_d);
}
__global__ void __launch_bounds__(256, 2) k_gemm2() {
    mma_gemm_body<PD, XDP, 13, false, false>(g_X, g_W2, g_P, nullptr, nullptr, nullptr);
}

// ---------------- node init (after gemm1: asrc/adst final) ----------------
__global__ void k_init_node() {
    int i = blockIdx.x * blockDim.x + threadIdx.x;
    if (i >= NNODE) return;
    float al = lrelu(g_asrc[i] + g_adst[i]);   // self-loop alpha
    g_amax[i] = f2o(al);
    g_deg[i] = 0;
}

__global__ void k_edge_alpha(const int* __restrict__ ei) {
    int e = blockIdx.x * blockDim.x + threadIdx.x;
    if (e >= NEDGE) return;
    int s = ei[e], d = ei[NEDGE + e];
    float al = lrelu(g_asrc[s] + g_adst[d]);
    g_alphaE[e] = al;
    atomicMax(&g_amax[d], f2o(al));
    atomicAdd(&g_deg[d], 1);
}

// exclusive scan of deg -> rowstart/pos; phase 2: denom self-loop init
__global__ void k_scan() {
    __shared__ int sh[1024];
    __shared__ int s_carry;
    int tid = threadIdx.x;
    if (tid == 0) s_carry = 0;
    __syncthreads();
    for (int base = 0; base < NNODE; base += 1024) {
        int i = base + tid;
        int v = (i < NNODE) ? g_deg[i] : 0;
        sh[tid] = v;
        __syncthreads();
        for (int off = 1; off < 1024; off <<= 1) {
            int t = (tid >= off) ? sh[tid - off] : 0;
            __syncthreads();
            sh[tid] += t;
            __syncthreads();
        }
        int incl = sh[tid];
        int carry = s_carry;
        if (i < NNODE) {
            int excl = carry + incl - v;
            g_rowstart[i] = excl;
            g_pos[i] = excl;
        }
        __syncthreads();
        if (tid == 1023) s_carry = carry + incl;
        __syncthreads();
    }
    for (int i = tid; i < NNODE; i += 1024) {
        float al = lrelu(g_asrc[i] + g_adst[i]);
        g_denom[i] = expf(al - o2f(g_amax[i]));
    }
}

// fused CSR fill + exp + denom accumulate
__global__ void k_edge_build(const int* __restrict__ ei) {
    int e = blockIdx.x * blockDim.x + threadIdx.x;
    if (e >= NEDGE) return;
    int s = ei[e], d = ei[NEDGE + e];
    int p = atomicAdd(&g_pos[d], 1);
    g_csr_src[p] = s;
    g_csr_eid[p] = e;
    float ex = expf(g_alphaE[e] - o2f(g_amax[d]));
    g_csr_ex[p] = ex;
    atomicAdd(&g_denom[d], ex);
}

// ---------------- GAT gather-aggregation: warp per node (fp16 h rows) ----------------
__global__ void k_gat_aggr(const float* __restrict__ b_gat) {
    int warp = (blockIdx.x * blockDim.x + threadIdx.x) >> 5;
    int lane = threadIdx.x & 31;
    if (warp >= NNODE) return;
    int i = warp;
    float amaxv = o2f(g_amax[i]);
    float als = lrelu(g_asrc[i] + g_adst[i]);
    float inv_den = 1.0f / g_denom[i];
    float cs = expf(als - amaxv) * inv_den;

    const uint4* hrow = (const uint4*)(g_hh + (size_t)i * GATD);
    const float4* bg = (const float4*)b_gat;
    float acc[3][8];
#pragma unroll
    for (int t = 0; t < 3; t++) {
        float f[8];
        unpack8(hrow[lane + 32 * t], f);
        float4 b0 = bg[2 * (lane + 32 * t)];
        float4 b1 = bg[2 * (lane + 32 * t) + 1];
        acc[t][0] = cs * f[0] + b0.x; acc[t][1] = cs * f[1] + b0.y;
        acc[t][2] = cs * f[2] + b0.z; acc[t][3] = cs * f[3] + b0.w;
        acc[t][4] = cs * f[4] + b1.x; acc[t][5] = cs * f[5] + b1.y;
        acc[t][6] = cs * f[6] + b1.z; acc[t][7] = cs * f[7] + b1.w;
    }
    int rs = g_rowstart[i], d = g_deg[i];
    for (int base = 0; base < d; base += 32) {
        int cnt = min(32, d - base);
        int sj = 0;
        float cj = 0.f;
        if (lane < cnt) {
            sj = g_csr_src[rs + base + lane];
            cj = g_csr_ex[rs + base + lane] * inv_den;
        }
        for (int k = 0; k < cnt; k++) {
            int s = __shfl_sync(0xffffffffu, sj, k);
            float coef = __shfl_sync(0xffffffffu, cj, k);
            const uint4* hs = (const uint4*)(g_hh + (size_t)s * GATD);
#pragma unroll
            for (int t = 0; t < 3; t++) {
                float f[8];
                unpack8(__ldg(&hs[lane + 32 * t]), f);
#pragma unroll
                for (int q = 0; q < 8; q++) acc[t][q] += coef * f[q];
            }
        }
    }
    size_t xbase = (size_t)i * XDP;
#pragma unroll
    for (int t = 0; t < 3; t++) {
        *(uint4*)(g_X + xbase + 8 * (lane + 32 * t)) = pack8(acc[t]);
    }
}

// ---------------- final aggregation (fused edge learner + ea@We): warp per node ----------------
__global__ void k_meta(float* __restrict__ out, const float* __restrict__ b_nbr,
                       const float* __restrict__ b_self, const float* __restrict__ W_nbr,
                       const float* __restrict__ W_edge, const float* __restrict__ b_edge,
                       const float* __restrict__ edge_attr) {
    __shared__ float sWe[16 * 128];
    __shared__ float sWE[16 * 16];
    __shared__ float sBN[128];
    for (int t = threadIdx.x; t < 2048; t += blockDim.x)
        sWe[t] = W_nbr[1600 * 128 + t];
    for (int t = threadIdx.x; t < 256; t += blockDim.x)
        sWE[t] = W_edge[t];
    __syncthreads();
    if (threadIdx.x < 128) {
        int c = threadIdx.x;
        float s = b_nbr[c];
#pragma unroll
        for (int k = 0; k < 16; k++) s += b_edge[k] * sWe[k * 128 + c];
        sBN[c] = s;
    }
    __syncthreads();

    int warp = (blockIdx.x * blockDim.x + threadIdx.x) >> 5;
    int lane = threadIdx.x & 31;
    if (warp >= NNODE) return;
    int i = warp;
    const float4* Pr = (const float4*)(g_P + (size_t)i * PD);
    float4 p1 = Pr[lane];        // dst-part
    float4 xs = Pr[64 + lane];   // self-part
    float4 bs = ((const float4*)b_self)[lane];
    float4 bn4 = *(const float4*)&sBN[lane * 4];
    float degf = (float)g_deg[i];
    float4 acc;
    acc.x = xs.x + bs.x + degf * (p1.x + bn4.x);
    acc.y = xs.y + bs.y + degf * (p1.y + bn4.y);
    acc.z = xs.z + bs.z + degf * (p1.z + bn4.z);
    acc.w = xs.w + bs.w + degf * (p1.w + bn4.w);

    float eas[16];
#pragma unroll
    for (int k = 0; k < 16; k++) eas[k] = 0.f;

    int rs = g_rowstart[i], d = g_deg[i];
    for (int base = 0; base < d; base += 32) {
        int cnt = min(32, d - base);
        int sj = 0, ej = 0;
        if (lane < cnt) {
            sj = g_csr_src[rs + base + lane];
            ej = g_csr_eid[rs + base + lane];
        }
        for (int k = 0; k < cnt; k++) {
            int s = __shfl_sync(0xffffffffu, sj, k);
            int e = __shfl_sync(0xffffffffu, ej, k);
            float4 p2 = __ldg(&((const float4*)(g_P + (size_t)s * PD))[32 + lane]);
            acc.x += p2.x;
            acc.y += p2.y;
            acc.z += p2.z;
            acc.w += p2.w;
            const float4* ear = (const float4*)(edge_attr + (size_t)e * 16);
            float4 e0 = __ldg(ear), e1 = __ldg(ear + 1), e2 = __ldg(ear + 2), e3 = __ldg(ear + 3);
            eas[0] += e0.x;  eas[1] += e0.y;  eas[2] += e0.z;  eas[3] += e0.w;
            eas[4] += e1.x;  eas[5] += e1.y;  eas[6] += e1.z;  eas[7] += e1.w;
            eas[8] += e2.x;  eas[9] += e2.y;  eas[10] += e2.z; eas[11] += e2.w;
            eas[12] += e3.x; eas[13] += e3.y; eas[14] += e3.z; eas[15] += e3.w;
        }
    }

    float tv[16];
#pragma unroll
    for (int kk = 0; kk < 16; kk++) {
        float s = 0.f;
#pragma unroll
        for (int j = 0; j < 16; j++) s += eas[j] * sWE[j * 16 + kk];
        tv[kk] = s;
    }
    int col = lane * 4;
#pragma unroll
    for (int kk = 0; kk < 16; kk++) {
        float4 wv = *(const float4*)&sWe[kk * 128 + col];
        float ev = tv[kk];
        acc.x += ev * wv.x;
        acc.y += ev * wv.y;
        acc.z += ev * wv.z;
        acc.w += ev * wv.w;
    }
    ((float4*)(out + (size_t)i * MD))[lane] = acc;
}

// ---------------- launch ----------------
extern "C" void kernel_launch(void* const* d_in, const int* in_sizes, int n_in,
                              void* d_out, int out_size) {
    const float* node_feature    = (const float*)d_in[0];
    const float* edge_attr       = (const float*)d_in[1];
    const float* message_feature = (const float*)d_in[2];
    const int*   edge_index      = (const int*)d_in[3];
    const float* W_node = (const float*)d_in[4];
    const float* b_node = (const float*)d_in[5];
    const float* W_edge = (const float*)d_in[6];
    const float* b_edge = (const float*)d_in[7];
    const float* W_gat  = (const float*)d_in[8];
    const float* att_src = (const float*)d_in[9];
    const float* att_dst = (const float*)d_in[10];
    const float* b_gat  = (const float*)d_in[11];
    const float* W_nbr  = (const float*)d_in[12];
    const float* b_nbr  = (const float*)d_in[13];
    const float* W_self = (const float*)d_in[14];
    const float* b_self = (const float*)d_in[15];
    float* out = (float*)d_out;

    const int GEMM_SMEM = 3 * STAGE_BYTES;   // 110592 (3 stages x A|B, K chunk 64)
    cudaFuncSetAttribute(k_gemm1, cudaFuncAttributeMaxDynamicSharedMemorySize, GEMM_SMEM);
    cudaFuncSetAttribute(k_gemm2, cudaFuncAttributeMaxDynamicSharedMemorySize, GEMM_SMEM);

    // prep
    k_nodeL<<<(NNODE * 32 + 255) / 256, 256>>>(node_feature, W_node, b_node);
    k_cvtA1<<<(NNODE * GATD / 2 + 255) / 256, 256>>>(message_feature);
    k_cvtW1<<<dim3(GATD / 32, GATD / 32), dim3(32, 8)>>>(W_gat);

    // h = mf @ W_gat  (fp16 out, + fused attention scalar partial dots)
    k_gemm1<<<dim3(GATD / 128, NNODE / 128), 256, GEMM_SMEM>>>(att_src, att_dst);

    // softmax structure
    k_init_node<<<(NNODE + 255) / 256, 256>>>();
    k_edge_alpha<<<(NEDGE + 255) / 256, 256>>>(edge_index);
    k_scan<<<1, 1024>>>();
    k_edge_build<<<(NEDGE + 255) / 256, 256>>>(edge_index);

    // GAT aggregation -> X cols 0:768 (fp16 h rows)
    k_gat_aggr<<<(NNODE * 32 + 255) / 256, 256>>>(b_gat);

    // P = x @ Wcat  (fp16)
    k_cvtW2<<<(PD * XDP + 255) / 256, 256>>>(W_nbr, W_self);
    k_gemm2<<<dim3(PD / 128, NNODE / 128), 256, GEMM_SMEM>>>();

    // final per-node aggregation (fused edge learner) -> out
    k_meta<<<(NNODE * 32 + 255) / 256, 256>>>(out, b_nbr, b_self, W_nbr,
                                              W_edge, b_edge, edge_attr);
}

// round 10
// speedup vs baseline: 1.8312x; 1.0009x over previous
#include <cuda_runtime.h>
#include <cuda_fp16.h>
#include <cstdint>

// ---------------- problem constants ----------------
#define NNODE 16000
#define NEDGE 128000
#define GATD 768          // GAT dim
#define XD 800            // meta-in dim (768 gat + 32 node)
#define XDP 832           // padded K for GEMM2 (13 x 64)
#define MD 128            // meta out dim
#define PD 384            // P1(dst part) | P2(src part) | Xself

// ---------------- device scratch (no allocs allowed) ----------------
__device__ __half   g_hh[NNODE * GATD];      // h in fp16 (only consumer: gather)
__device__ float    g_P[NNODE * PD];         // 24.6 MB
__device__ float    g_asrc[NNODE];
__device__ float    g_adst[NNODE];
__device__ unsigned g_amax[NNODE];           // ordered-float bits
__device__ float    g_denom[NNODE];
__device__ float    g_alphaE[NEDGE];
__device__ int      g_deg[NNODE];
__device__ int      g_rowstart[NNODE];
__device__ int      g_pos[NNODE];
__device__ int      g_csr_src[NEDGE];
__device__ int      g_csr_eid[NEDGE];
__device__ float    g_csr_ex[NEDGE];
// fp16 operands
__device__ __half g_A1[NNODE * GATD];
__device__ __half g_X[NNODE * XDP];
__device__ __half g_W1[GATD * GATD];   // W_gat^T  [n,k]
__device__ __half g_W2[PD * XDP];      // Wcat^T   [n,k]

// ---------------- helpers ----------------
__device__ __forceinline__ float lrelu(float x) { return x >= 0.f ? x : 0.2f * x; }
__device__ __forceinline__ unsigned f2o(float f) {
    unsigned b = __float_as_uint(f);
    return (b & 0x80000000u) ? ~b : (b | 0x80000000u);
}
__device__ __forceinline__ float o2f(unsigned b) {
    b = (b & 0x80000000u) ? (b & 0x7fffffffu) : ~b;
    return __uint_as_float(b);
}
__device__ __forceinline__ uint32_t smem_u32(const void* p) {
    uint32_t a;
    asm("{ .reg .u64 t; cvta.to.shared.u64 t, %1; cvt.u32.u64 %0, t; }" : "=r"(a) : "l"(p));
    return a;
}
__device__ __forceinline__ void ldm_x4(uint32_t& r0, uint32_t& r1, uint32_t& r2, uint32_t& r3,
                                       uint32_t addr) {
    asm volatile("ldmatrix.sync.aligned.m8n8.x4.shared.b16 {%0,%1,%2,%3}, [%4];"
                 : "=r"(r0), "=r"(r1), "=r"(r2), "=r"(r3) : "r"(addr));
}
__device__ __forceinline__ void mma16816(float* c, const uint32_t* a, uint32_t b0, uint32_t b1) {
    asm volatile(
        "mma.sync.aligned.m16n8k16.row.col.f32.f16.f16.f32 "
        "{%0,%1,%2,%3}, {%4,%5,%6,%7}, {%8,%9}, {%0,%1,%2,%3};"
        : "+f"(c[0]), "+f"(c[1]), "+f"(c[2]), "+f"(c[3])
        : "r"(a[0]), "r"(a[1]), "r"(a[2]), "r"(a[3]), "r"(b0), "r"(b1));
}
__device__ __forceinline__ void cp16(uint32_t dst, const void* src) {
    asm volatile("cp.async.cg.shared.global [%0], [%1], 16;" :: "r"(dst), "l"(src));
}
#define CP_COMMIT() asm volatile("cp.async.commit_group;" ::: "memory")
#define CP_WAIT2()  asm volatile("cp.async.wait_group 2;" ::: "memory")
#define CP_WAIT1()  asm volatile("cp.async.wait_group 1;" ::: "memory")
#define CP_WAIT0()  asm volatile("cp.async.wait_group 0;" ::: "memory")

__device__ __forceinline__ void unpack8(uint4 v, float* f) {
    float2 a = __half22float2(*(__half2*)&v.x);
    float2 b = __half22float2(*(__half2*)&v.y);
    float2 c = __half22float2(*(__half2*)&v.z);
    float2 d = __half22float2(*(__half2*)&v.w);
    f[0] = a.x; f[1] = a.y; f[2] = b.x; f[3] = b.y;
    f[4] = c.x; f[5] = c.y; f[6] = d.x; f[7] = d.y;
}
__device__ __forceinline__ uint4 pack8(const float* f) {
    uint4 o;
    __half2 h0 = __floats2half2_rn(f[0], f[1]);
    __half2 h1 = __floats2half2_rn(f[2], f[3]);
    __half2 h2 = __floats2half2_rn(f[4], f[5]);
    __half2 h3 = __floats2half2_rn(f[6], f[7]);
    o.x = *(uint32_t*)&h0; o.y = *(uint32_t*)&h1;
    o.z = *(uint32_t*)&h2; o.w = *(uint32_t*)&h3;
    return o;
}

// ---------------- node learner (writes fp16 x cols 768:832) ----------------
__global__ void k_nodeL(const float* __restrict__ nf, const float* __restrict__ W,
                        const float* __restrict__ b) {
    int idx = blockIdx.x * blockDim.x + threadIdx.x;
    if (idx >= NNODE * 32) return;
    int i = idx >> 5, j = idx & 31;
    const float* r = nf + i * 32;
    float s = b[j];
#pragma unroll
    for (int k = 0; k < 32; k++) s += r[k] * W[k * 32 + j];
    size_t base = (size_t)i * XDP;
    g_X[base + 768 + j] = __float2half_rn(s);
    g_X[base + 800 + j] = __float2half(0.f);
}

// ---------------- prep kernels ----------------
__global__ void k_cvtA1(const float* __restrict__ src) {
    int idx = blockIdx.x * blockDim.x + threadIdx.x;
    if (idx < NNODE) { g_asrc[idx] = 0.f; g_adst[idx] = 0.f; }
    if (idx >= NNODE * GATD / 2) return;
    float2 v = ((const float2*)src)[idx];
    __half2 h = __floats2half2_rn(v.x, v.y);
    ((__half2*)g_A1)[idx] = h;
}
// coalesced 32x32 tiled transpose of W_gat -> fp16
__global__ void k_cvtW1(const float* __restrict__ Wg) {
    __shared__ float tile[32][33];
    int tx = threadIdx.x, ty = threadIdx.y;       // block 32x8
    int n0 = blockIdx.x * 32, k0 = blockIdx.y * 32;
#pragma unroll
    for (int i = 0; i < 4; i++)
        tile[ty + i * 8][tx] = Wg[(size_t)(k0 + ty + i * 8) * GATD + n0 + tx];
    __syncthreads();
#pragma unroll
    for (int i = 0; i < 4; i++) {
        size_t o = (size_t)(n0 + ty + i * 8) * GATD + k0 + tx;
        g_W1[o] = __float2half_rn(tile[tx][ty + i * 8]);
    }
}
__global__ void k_cvtW2(const float* __restrict__ Wn, const float* __restrict__ Ws) {
    int idx = blockIdx.x * blockDim.x + threadIdx.x;
    if (idx >= PD * XDP) return;
    int n = idx / XDP, k = idx % XDP;
    float v = 0.f;
    if (k < XD) {
        if (n < 128)      v = Wn[k * 128 + n];
        else if (n < 256) v = Wn[(800 + k) * 128 + (n - 128)];
        else              v = Ws[k * 128 + (n - 256)];
    }
    g_W2[idx] = __float2half_rn(v);
}

// ---------------- warp-MMA fp16 GEMM (cp.async 3-stage, K chunk 64) ----------------
// C[M,CN] = A @ B^T.  Block tile 128x128, 8 warps (2x4).
#define ASTRIDE 72
#define TILE_BYTES 18432                  // 128*72*2
#define STAGE_BYTES (2 * TILE_BYTES)      // A|B

template <int CN, int KPAD, int NCH, bool DO_ATT, bool HALF_OUT>
__device__ __forceinline__ void mma_gemm_body(const __half* __restrict__ A,
                                              const __half* __restrict__ B,
                                              float* __restrict__ Cf,
                                              __half* __restrict__ Ch,
                                              const float* __restrict__ att_s,
                                              const float* __restrict__ att_d) {
    extern __shared__ char smem[];
    const uint32_t sb = smem_u32(smem);

    const int t = threadIdx.x;
    const int lane = t & 31;
    const int wid = t >> 5;
    const int m0 = (wid >> 2) * 64;
    const int n0 = (wid & 3) * 32;
    const int bm = blockIdx.y * 128;
    const int bn = blockIdx.x * 128;

    const uint32_t aoff = (uint32_t)(((lane & 15) * ASTRIDE + (lane >> 4) * 8) * 2);
    const uint32_t boff = (uint32_t)((((lane & 7) + ((lane >> 4) << 3)) * ASTRIDE +
                                     (((lane >> 3) & 1) << 3)) * 2);

    float acc[4][4][4];
#pragma unroll
    for (int i = 0; i < 4; i++)
#pragma unroll
        for (int j = 0; j < 4; j++)
#pragma unroll
            for (int q = 0; q < 4; q++) acc[i][j][q] = 0.f;

    auto issue_chunk = [&](int c, int s) {
        const int c0 = c * 64;
        const uint32_t dst = sb + (uint32_t)s * STAGE_BYTES;
#pragma unroll
        for (int it = 0; it < 4; it++) {
            int idx = it * 256 + t;
            int r = idx >> 3, j = idx & 7;            // 128 rows x 8 16B segs
            size_t ga = (size_t)(bm + r) * KPAD + c0 + j * 8;
            size_t gb = (size_t)(bn + r) * KPAD + c0 + j * 8;
            uint32_t doff = (uint32_t)((r * ASTRIDE + j * 8) * 2);
            cp16(dst + doff, A + ga);
            cp16(dst + TILE_BYTES + doff, B + gb);
        }
    };

    issue_chunk(0, 0);
    CP_COMMIT();
    issue_chunk(1, 1);
    CP_COMMIT();

    for (int c = 0; c < NCH; c++) {
        const int s = c % 3;
        if (c + 2 < NCH) {
            issue_chunk(c + 2, (c + 2) % 3);
            CP_COMMIT();
            CP_WAIT2();
        } else if (c + 1 < NCH) {
            CP_WAIT1();
        } else {
            CP_WAIT0();
        }
        __syncthreads();

        const uint32_t baseA = sb + (uint32_t)s * STAGE_BYTES;
        const uint32_t baseB = baseA + TILE_BYTES;

#pragma unroll
        for (int ks = 0; ks < 4; ks++) {
            const uint32_t kb = (uint32_t)(ks * 16 * 2);
            uint32_t bh[2][4];
#pragma unroll
            for (int p = 0; p < 2; p++) {
                uint32_t off = boff + (uint32_t)((n0 + p * 16) * ASTRIDE * 2) + kb;
                ldm_x4(bh[p][0], bh[p][1], bh[p][2], bh[p][3], baseB + off);
            }
#pragma unroll
            for (int tm = 0; tm < 4; tm++) {
                uint32_t off = aoff + (uint32_t)((m0 + tm * 16) * ASTRIDE * 2) + kb;
                uint32_t ah[4];
                ldm_x4(ah[0], ah[1], ah[2], ah[3], baseA + off);
#pragma unroll
                for (int tn = 0; tn < 4; tn++) {
                    int p = tn >> 1, q = tn & 1;
                    mma16816(acc[tm][tn], ah, bh[p][q * 2], bh[p][q * 2 + 1]);
                }
            }
        }
        __syncthreads();
    }

    // epilogue: store C (+ optional fused attention partial dots)
    const int rit = lane >> 2;
    const int cq = (lane & 3) * 2;
#pragma unroll
    for (int tm = 0; tm < 4; tm++) {
        float s1a = 0.f, s2a = 0.f, s1b = 0.f, s2b = 0.f;
#pragma unroll
        for (int tn = 0; tn < 4; tn++) {
            size_t row = (size_t)(bm + m0 + tm * 16 + rit);
            int col = bn + n0 + tn * 8 + cq;
            if (HALF_OUT) {
                __half2 v0 = __floats2half2_rn(acc[tm][tn][0], acc[tm][tn][1]);
                __half2 v1 = __floats2half2_rn(acc[tm][tn][2], acc[tm][tn][3]);
                *(__half2*)&Ch[row * CN + col] = v0;
                *(__half2*)&Ch[(row + 8) * CN + col] = v1;
            } else {
                *(float2*)&Cf[row * CN + col] = make_float2(acc[tm][tn][0], acc[tm][tn][1]);
                *(float2*)&Cf[(row + 8) * CN + col] = make_float2(acc[tm][tn][2], acc[tm][tn][3]);
            }
            if (DO_ATT) {
                float a0 = __ldg(att_s + col), a1 = __ldg(att_s + col + 1);
                float d0 = __ldg(att_d + col), d1 = __ldg(att_d + col + 1);
                s1a += acc[tm][tn][0] * a0 + acc[tm][tn][1] * a1;
                s2a += acc[tm][tn][0] * d0 + acc[tm][tn][1] * d1;
                s1b += acc[tm][tn][2] * a0 + acc[tm][tn][3] * a1;
                s2b += acc[tm][tn][2] * d0 + acc[tm][tn][3] * d1;
            }
        }
        if (DO_ATT) {
#pragma unroll
            for (int off = 1; off < 4; off <<= 1) {
                s1a += __shfl_xor_sync(0xffffffffu, s1a, off);
                s2a += __shfl_xor_sync(0xffffffffu, s2a, off);
                s1b += __shfl_xor_sync(0xffffffffu, s1b, off);
                s2b += __shfl_xor_sync(0xffffffffu, s2b, off);
            }
            if ((lane & 3) == 0) {
                int rowA = bm + m0 + tm * 16 + rit;
                atomicAdd(&g_asrc[rowA], s1a);
                atomicAdd(&g_adst[rowA], s2a);
                atomicAdd(&g_asrc[rowA + 8], s1b);
                atomicAdd(&g_adst[rowA + 8], s2b);
            }
        }
    }
}

__global__ void __launch_bounds__(256, 2) k_gemm1(const float* __restrict__ att_s,
                                                  const float* __restrict__ att_d) {
    mma_gemm_body<GATD, GATD, 12, true, true>(g_A1, g_W1, nullptr, g_hh, att_s, att_d);
}
__global__ void __launch_bounds__(256, 2) k_gemm2() {
    mma_gemm_body<PD, XDP, 13, false, false>(g_X, g_W2, g_P, nullptr, nullptr, nullptr);
}

// ---------------- node init (after gemm1: asrc/adst final) ----------------
__global__ void k_init_node() {
    int i = blockIdx.x * blockDim.x + threadIdx.x;
    if (i >= NNODE) return;
    float al = lrelu(g_asrc[i] + g_adst[i]);   // self-loop alpha
    g_amax[i] = f2o(al);
    g_deg[i] = 0;
}

__global__ void k_edge_alpha(const int* __restrict__ ei) {
    int e = blockIdx.x * blockDim.x + threadIdx.x;
    if (e >= NEDGE) return;
    int s = ei[e], d = ei[NEDGE + e];
    float al = lrelu(g_asrc[s] + g_adst[d]);
    g_alphaE[e] = al;
    atomicMax(&g_amax[d], f2o(al));
    atomicAdd(&g_deg[d], 1);
}

// exclusive scan of deg -> rowstart/pos; phase 2: denom self-loop init
__global__ void k_scan() {
    __shared__ int sh[1024];
    __shared__ int s_carry;
    int tid = threadIdx.x;
    if (tid == 0) s_carry = 0;
    __syncthreads();
    for (int base = 0; base < NNODE; base += 1024) {
        int i = base + tid;
        int v = (i < NNODE) ? g_deg[i] : 0;
        sh[tid] = v;
        __syncthreads();
        for (int off = 1; off < 1024; off <<= 1) {
            int t = (tid >= off) ? sh[tid - off] : 0;
            __syncthreads();
            sh[tid] += t;
            __syncthreads();
        }
        int incl = sh[tid];
        int carry = s_carry;
        if (i < NNODE) {
            int excl = carry + incl - v;
            g_rowstart[i] = excl;
            g_pos[i] = excl;
        }
        __syncthreads();
        if (tid == 1023) s_carry = carry + incl;
        __syncthreads();
    }
    for (int i = tid; i < NNODE; i += 1024) {
        float al = lrelu(g_asrc[i] + g_adst[i]);
        g_denom[i] = expf(al - o2f(g_amax[i]));
    }
}

// fused CSR fill + exp + denom accumulate
__global__ void k_edge_build(const int* __restrict__ ei) {
    int e = blockIdx.x * blockDim.x + threadIdx.x;
    if (e >= NEDGE) return;
    int s = ei[e], d = ei[NEDGE + e];
    int p = atomicAdd(&g_pos[d], 1);
    g_csr_src[p] = s;
    g_csr_eid[p] = e;
    float ex = expf(g_alphaE[e] - o2f(g_amax[d]));
    g_csr_ex[p] = ex;
    atomicAdd(&g_denom[d], ex);
}

// ---------------- GAT gather-aggregation: warp per node (fp16 h rows) ----------------
__global__ void k_gat_aggr(const float* __restrict__ b_gat) {
    int warp = (blockIdx.x * blockDim.x + threadIdx.x) >> 5;
    int lane = threadIdx.x & 31;
    if (warp >= NNODE) return;
    int i = warp;
    float amaxv = o2f(g_amax[i]);
    float als = lrelu(g_asrc[i] + g_adst[i]);
    float inv_den = 1.0f / g_denom[i];
    float cs = expf(als - amaxv) * inv_den;

    const uint4* hrow = (const uint4*)(g_hh + (size_t)i * GATD);
    const float4* bg = (const float4*)b_gat;
    float acc[3][8];
#pragma unroll
    for (int t = 0; t < 3; t++) {
        float f[8];
        unpack8(hrow[lane + 32 * t], f);
        float4 b0 = bg[2 * (lane + 32 * t)];
        float4 b1 = bg[2 * (lane + 32 * t) + 1];
        acc[t][0] = cs * f[0] + b0.x; acc[t][1] = cs * f[1] + b0.y;
        acc[t][2] = cs * f[2] + b0.z; acc[t][3] = cs * f[3] + b0.w;
        acc[t][4] = cs * f[4] + b1.x; acc[t][5] = cs * f[5] + b1.y;
        acc[t][6] = cs * f[6] + b1.z; acc[t][7] = cs * f[7] + b1.w;
    }
    int rs = g_rowstart[i], d = g_deg[i];
    for (int base = 0; base < d; base += 32) {
        int cnt = min(32, d - base);
        int sj = 0;
        float cj = 0.f;
        if (lane < cnt) {
            sj = g_csr_src[rs + base + lane];
            cj = g_csr_ex[rs + base + lane] * inv_den;
        }
        for (int k = 0; k < cnt; k++) {
            int s = __shfl_sync(0xffffffffu, sj, k);
            float coef = __shfl_sync(0xffffffffu, cj, k);
            const uint4* hs = (const uint4*)(g_hh + (size_t)s * GATD);
#pragma unroll
            for (int t = 0; t < 3; t++) {
                float f[8];
                unpack8(__ldg(&hs[lane + 32 * t]), f);
#pragma unroll
                for (int q = 0; q < 8; q++) acc[t][q] += coef * f[q];
            }
        }
    }
    size_t xbase = (size_t)i * XDP;
#pragma unroll
    for (int t = 0; t < 3; t++) {
        *(uint4*)(g_X + xbase + 8 * (lane + 32 * t)) = pack8(acc[t]);
    }
}

// ---------------- final aggregation (fused edge learner + ea@We): warp per node ----------------
__global__ void k_meta(float* __restrict__ out, const float* __restrict__ b_nbr,
                       const float* __restrict__ b_self, const float* __restrict__ W_nbr,
                       const float* __restrict__ W_edge, const float* __restrict__ b_edge,
                       const float* __restrict__ edge_attr) {
    __shared__ float sWe[16 * 128];
    __shared__ float sWE[16 * 16];
    __shared__ float sBN[128];
    for (int t = threadIdx.x; t < 2048; t += blockDim.x)
        sWe[t] = W_nbr[1600 * 128 + t];
    for (int t = threadIdx.x; t < 256; t += blockDim.x)
        sWE[t] = W_edge[t];
    __syncthreads();
    if (threadIdx.x < 128) {
        int c = threadIdx.x;
        float s = b_nbr[c];
#pragma unroll
        for (int k = 0; k < 16; k++) s += b_edge[k] * sWe[k * 128 + c];
        sBN[c] = s;
    }
    __syncthreads();

    int warp = (blockIdx.x * blockDim.x + threadIdx.x) >> 5;
    int lane = threadIdx.x & 31;
    if (warp >= NNODE) return;
    int i = warp;
    const float4* Pr = (const float4*)(g_P + (size_t)i * PD);
    float4 p1 = Pr[lane];        // dst-part
    float4 xs = Pr[64 + lane];   // self-part
    float4 bs = ((const float4*)b_self)[lane];
    float4 bn4 = *(const float4*)&sBN[lane * 4];
    float degf = (float)g_deg[i];
    float4 acc;
    acc.x = xs.x + bs.x + degf * (p1.x + bn4.x);
    acc.y = xs.y + bs.y + degf * (p1.y + bn4.y);
    acc.z = xs.z + bs.z + degf * (p1.z + bn4.z);
    acc.w = xs.w + bs.w + degf * (p1.w + bn4.w);

    float eas[16];
#pragma unroll
    for (int k = 0; k < 16; k++) eas[k] = 0.f;

    int rs = g_rowstart[i], d = g_deg[i];
    for (int base = 0; base < d; base += 32) {
        int cnt = min(32, d - base);
        int sj = 0, ej = 0;
        if (lane < cnt) {
            sj = g_csr_src[rs + base + lane];
            ej = g_csr_eid[rs + base + lane];
        }
        for (int k = 0; k < cnt; k++) {
            int s = __shfl_sync(0xffffffffu, sj, k);
            int e = __shfl_sync(0xffffffffu, ej, k);
            float4 p2 = __ldg(&((const float4*)(g_P + (size_t)s * PD))[32 + lane]);
            acc.x += p2.x;
            acc.y += p2.y;
            acc.z += p2.z;
            acc.w += p2.w;
            const float4* ear = (const float4*)(edge_attr + (size_t)e * 16);
            float4 e0 = __ldg(ear), e1 = __ldg(ear + 1), e2 = __ldg(ear + 2), e3 = __ldg(ear + 3);
            eas[0] += e0.x;  eas[1] += e0.y;  eas[2] += e0.z;  eas[3] += e0.w;
            eas[4] += e1.x;  eas[5] += e1.y;  eas[6] += e1.z;  eas[7] += e1.w;
            eas[8] += e2.x;  eas[9] += e2.y;  eas[10] += e2.z; eas[11] += e2.w;
            eas[12] += e3.x; eas[13] += e3.y; eas[14] += e3.z; eas[15] += e3.w;
        }
    }

    float tv[16];
#pragma unroll
    for (int kk = 0; kk < 16; kk++) {
        float s = 0.f;
#pragma unroll
        for (int j = 0; j < 16; j++) s += eas[j] * sWE[j * 16 + kk];
        tv[kk] = s;
    }
    int col = lane * 4;
#pragma unroll
    for (int kk = 0; kk < 16; kk++) {
        float4 wv = *(const float4*)&sWe[kk * 128 + col];
        float ev = tv[kk];
        acc.x += ev * wv.x;
        acc.y += ev * wv.y;
        acc.z += ev * wv.z;
        acc.w += ev * wv.w;
    }
    ((float4*)(out + (size_t)i * MD))[lane] = acc;
}

// ---------------- launch ----------------
extern "C" void kernel_launch(void* const* d_in, const int* in_sizes, int n_in,
                              void* d_out, int out_size) {
    const float* node_feature    = (const float*)d_in[0];
    const float* edge_attr       = (const float*)d_in[1];
    const float* message_feature = (const float*)d_in[2];
    const int*   edge_index      = (const int*)d_in[3];
    const float* W_node = (const float*)d_in[4];
    const float* b_node = (const float*)d_in[5];
    const float* W_edge = (const float*)d_in[6];
    const float* b_edge = (const float*)d_in[7];
    const float* W_gat  = (const float*)d_in[8];
    const float* att_src = (const float*)d_in[9];
    const float* att_dst = (const float*)d_in[10];
    const float* b_gat  = (const float*)d_in[11];
    const float* W_nbr  = (const float*)d_in[12];
    const float* b_nbr  = (const float*)d_in[13];
    const float* W_self = (const float*)d_in[14];
    const float* b_self = (const float*)d_in[15];
    float* out = (float*)d_out;

    const int GEMM_SMEM = 3 * STAGE_BYTES;   // 110592 (3 stages x A|B, K chunk 64)
    cudaFuncSetAttribute(k_gemm1, cudaFuncAttributeMaxDynamicSharedMemorySize, GEMM_SMEM);
    cudaFuncSetAttribute(k_gemm2, cudaFuncAttributeMaxDynamicSharedMemorySize, GEMM_SMEM);

    // prep
    k_nodeL<<<(NNODE * 32 + 255) / 256, 256>>>(node_feature, W_node, b_node);
    k_cvtA1<<<(NNODE * GATD / 2 + 255) / 256, 256>>>(message_feature);
    k_cvtW1<<<dim3(GATD / 32, GATD / 32), dim3(32, 8)>>>(W_gat);

    // h = mf @ W_gat  (fp16 out, + fused attention scalar partial dots)
    k_gemm1<<<dim3(GATD / 128, NNODE / 128), 256, GEMM_SMEM>>>(att_src, att_dst);

    // softmax structure
    k_init_node<<<(NNODE + 255) / 256, 256>>>();
    k_edge_alpha<<<(NEDGE + 255) / 256, 256>>>(edge_index);
    k_scan<<<1, 1024>>>();
    k_edge_build<<<(NEDGE + 255) / 256, 256>>>(edge_index);

    // GAT aggregation -> X cols 0:768 (fp16 h rows)
    k_gat_aggr<<<(NNODE * 32 + 255) / 256, 256>>>(b_gat);

    // P = x @ Wcat  (fp16)
    k_cvtW2<<<(PD * XDP + 255) / 256, 256>>>(W_nbr, W_self);
    k_gemm2<<<dim3(PD / 128, NNODE / 128), 256, GEMM_SMEM>>>();

    // final per-node aggregation (fused edge learner) -> out
    k_meta<<<(NNODE * 32 + 255) / 256, 256>>>(out, b_nbr, b_self, W_nbr,
                                              W_edge, b_edge, edge_attr);
}

// round 11
// speedup vs baseline: 1.8344x; 1.0017x over previous
#include <cuda_runtime.h>
#include <cuda_fp16.h>
#include <cstdint>

// ---------------- problem constants ----------------
#define NNODE 16000
#define NEDGE 128000
#define GATD 768          // GAT dim
#define XD 800            // meta-in dim (768 gat + 32 node)
#define XDP 832           // padded K for GEMM2 (13 x 64)
#define MD 128            // meta out dim
#define PD 384            // P1(dst part) | P2(src part) | Xself

// ---------------- device scratch (no allocs allowed) ----------------
__device__ __half   g_hh[NNODE * GATD];      // h in fp16 (only consumer: gather)
__device__ float    g_P[NNODE * PD];         // 24.6 MB
__device__ float    g_asrc[NNODE];
__device__ float    g_adst[NNODE];
__device__ unsigned g_amax[NNODE];           // ordered-float bits
__device__ float    g_denom[NNODE];
__device__ float    g_alphaE[NEDGE];
__device__ int      g_deg[NNODE];
__device__ int      g_rowstart[NNODE];
__device__ int      g_pos[NNODE];
__device__ int      g_csr_src[NEDGE];
__device__ int      g_csr_eid[NEDGE];
__device__ float    g_csr_ex[NEDGE];
// fp16 operands
__device__ __half g_A1[NNODE * GATD];
__device__ __half g_X[NNODE * XDP];
__device__ __half g_W1[GATD * GATD];   // W_gat^T  [n,k]
__device__ __half g_W2[PD * XDP];      // Wcat^T   [n,k]

// ---------------- helpers ----------------
__device__ __forceinline__ float lrelu(float x) { return x >= 0.f ? x : 0.2f * x; }
__device__ __forceinline__ unsigned f2o(float f) {
    unsigned b = __float_as_uint(f);
    return (b & 0x80000000u) ? ~b : (b | 0x80000000u);
}
__device__ __forceinline__ float o2f(unsigned b) {
    b = (b & 0x80000000u) ? (b & 0x7fffffffu) : ~b;
    return __uint_as_float(b);
}
__device__ __forceinline__ uint32_t smem_u32(const void* p) {
    uint32_t a;
    asm("{ .reg .u64 t; cvta.to.shared.u64 t, %1; cvt.u32.u64 %0, t; }" : "=r"(a) : "l"(p));
    return a;
}
__device__ __forceinline__ void ldm_x4(uint32_t& r0, uint32_t& r1, uint32_t& r2, uint32_t& r3,
                                       uint32_t addr) {
    asm volatile("ldmatrix.sync.aligned.m8n8.x4.shared.b16 {%0,%1,%2,%3}, [%4];"
                 : "=r"(r0), "=r"(r1), "=r"(r2), "=r"(r3) : "r"(addr));
}
__device__ __forceinline__ void mma16816(float* c, const uint32_t* a, uint32_t b0, uint32_t b1) {
    asm volatile(
        "mma.sync.aligned.m16n8k16.row.col.f32.f16.f16.f32 "
        "{%0,%1,%2,%3}, {%4,%5,%6,%7}, {%8,%9}, {%0,%1,%2,%3};"
        : "+f"(c[0]), "+f"(c[1]), "+f"(c[2]), "+f"(c[3])
        : "r"(a[0]), "r"(a[1]), "r"(a[2]), "r"(a[3]), "r"(b0), "r"(b1));
}
__device__ __forceinline__ void cp16(uint32_t dst, const void* src) {
    asm volatile("cp.async.cg.shared.global [%0], [%1], 16;" :: "r"(dst), "l"(src));
}
#define CP_COMMIT() asm volatile("cp.async.commit_group;" ::: "memory")
#define CP_WAIT2()  asm volatile("cp.async.wait_group 2;" ::: "memory")
#define CP_WAIT1()  asm volatile("cp.async.wait_group 1;" ::: "memory")
#define CP_WAIT0()  asm volatile("cp.async.wait_group 0;" ::: "memory")

__device__ __forceinline__ void unpack8(uint4 v, float* f) {
    float2 a = __half22float2(*(__half2*)&v.x);
    float2 b = __half22float2(*(__half2*)&v.y);
    float2 c = __half22float2(*(__half2*)&v.z);
    float2 d = __half22float2(*(__half2*)&v.w);
    f[0] = a.x; f[1] = a.y; f[2] = b.x; f[3] = b.y;
    f[4] = c.x; f[5] = c.y; f[6] = d.x; f[7] = d.y;
}
__device__ __forceinline__ uint4 pack8(const float* f) {
    uint4 o;
    __half2 h0 = __floats2half2_rn(f[0], f[1]);
    __half2 h1 = __floats2half2_rn(f[2], f[3]);
    __half2 h2 = __floats2half2_rn(f[4], f[5]);
    __half2 h3 = __floats2half2_rn(f[6], f[7]);
    o.x = *(uint32_t*)&h0; o.y = *(uint32_t*)&h1;
    o.z = *(uint32_t*)&h2; o.w = *(uint32_t*)&h3;
    return o;
}

// ---------------- node learner (writes fp16 x cols 768:832) ----------------
__global__ void k_nodeL(const float* __restrict__ nf, const float* __restrict__ W,
                        const float* __restrict__ b) {
    int idx = blockIdx.x * blockDim.x + threadIdx.x;
    if (idx >= NNODE * 32) return;
    int i = idx >> 5, j = idx & 31;
    const float* r = nf + i * 32;
    float s = b[j];
#pragma unroll
    for (int k = 0; k < 32; k++) s += r[k] * W[k * 32 + j];
    size_t base = (size_t)i * XDP;
    g_X[base + 768 + j] = __float2half_rn(s);
    g_X[base + 800 + j] = __float2half(0.f);
}

// ---------------- prep kernels ----------------
__global__ void k_cvtA1(const float* __restrict__ src) {
    int idx = blockIdx.x * blockDim.x + threadIdx.x;
    if (idx < NNODE) { g_asrc[idx] = 0.f; g_adst[idx] = 0.f; }
    if (idx >= NNODE * GATD / 2) return;
    float2 v = ((const float2*)src)[idx];
    __half2 h = __floats2half2_rn(v.x, v.y);
    ((__half2*)g_A1)[idx] = h;
}
// coalesced 32x32 tiled transpose of W_gat -> fp16
__global__ void k_cvtW1(const float* __restrict__ Wg) {
    __shared__ float tile[32][33];
    int tx = threadIdx.x, ty = threadIdx.y;       // block 32x8
    int n0 = blockIdx.x * 32, k0 = blockIdx.y * 32;
#pragma unroll
    for (int i = 0; i < 4; i++)
        tile[ty + i * 8][tx] = Wg[(size_t)(k0 + ty + i * 8) * GATD + n0 + tx];
    __syncthreads();
#pragma unroll
    for (int i = 0; i < 4; i++) {
        size_t o = (size_t)(n0 + ty + i * 8) * GATD + k0 + tx;
        g_W1[o] = __float2half_rn(tile[tx][ty + i * 8]);
    }
}
__global__ void k_cvtW2(const float* __restrict__ Wn, const float* __restrict__ Ws) {
    int idx = blockIdx.x * blockDim.x + threadIdx.x;
    if (idx >= PD * XDP) return;
    int n = idx / XDP, k = idx % XDP;
    float v = 0.f;
    if (k < XD) {
        if (n < 128)      v = Wn[k * 128 + n];
        else if (n < 256) v = Wn[(800 + k) * 128 + (n - 128)];
        else              v = Ws[k * 128 + (n - 256)];
    }
    g_W2[idx] = __float2half_rn(v);
}

// ---------------- warp-MMA fp16 GEMM (cp.async 3-stage, K chunk 64) ----------------
// C[M,CN] = A @ B^T.  Block tile 128x128, 8 warps (2x4).
#define ASTRIDE 72
#define TILE_BYTES 18432                  // 128*72*2
#define STAGE_BYTES (2 * TILE_BYTES)      // A|B

template <int CN, int KPAD, int NCH, bool DO_ATT, bool HALF_OUT>
__device__ __forceinline__ void mma_gemm_body(const __half* __restrict__ A,
                                              const __half* __restrict__ B,
                                              float* __restrict__ Cf,
                                              __half* __restrict__ Ch,
                                              const float* __restrict__ att_s,
                                              const float* __restrict__ att_d) {
    extern __shared__ char smem[];
    const uint32_t sb = smem_u32(smem);

    const int t = threadIdx.x;
    const int lane = t & 31;
    const int wid = t >> 5;
    const int m0 = (wid >> 2) * 64;
    const int n0 = (wid & 3) * 32;
    const int bm = blockIdx.y * 128;
    const int bn = blockIdx.x * 128;

    const uint32_t aoff = (uint32_t)(((lane & 15) * ASTRIDE + (lane >> 4) * 8) * 2);
    const uint32_t boff = (uint32_t)((((lane & 7) + ((lane >> 4) << 3)) * ASTRIDE +
                                     (((lane >> 3) & 1) << 3)) * 2);

    float acc[4][4][4];
#pragma unroll
    for (int i = 0; i < 4; i++)
#pragma unroll
        for (int j = 0; j < 4; j++)
#pragma unroll
            for (int q = 0; q < 4; q++) acc[i][j][q] = 0.f;

    auto issue_chunk = [&](int c, int s) {
        const int c0 = c * 64;
        const uint32_t dst = sb + (uint32_t)s * STAGE_BYTES;
#pragma unroll
        for (int it = 0; it < 4; it++) {
            int idx = it * 256 + t;
            int r = idx >> 3, j = idx & 7;            // 128 rows x 8 16B segs
            size_t ga = (size_t)(bm + r) * KPAD + c0 + j * 8;
            size_t gb = (size_t)(bn + r) * KPAD + c0 + j * 8;
            uint32_t doff = (uint32_t)((r * ASTRIDE + j * 8) * 2);
            cp16(dst + doff, A + ga);
            cp16(dst + TILE_BYTES + doff, B + gb);
        }
    };

    issue_chunk(0, 0);
    CP_COMMIT();
    issue_chunk(1, 1);
    CP_COMMIT();

    for (int c = 0; c < NCH; c++) {
        const int s = c % 3;
        if (c + 2 < NCH) {
            issue_chunk(c + 2, (c + 2) % 3);
            CP_COMMIT();
            CP_WAIT2();
        } else if (c + 1 < NCH) {
            CP_WAIT1();
        } else {
            CP_WAIT0();
        }
        __syncthreads();

        const uint32_t baseA = sb + (uint32_t)s * STAGE_BYTES;
        const uint32_t baseB = baseA + TILE_BYTES;

#pragma unroll
        for (int ks = 0; ks < 4; ks++) {
            const uint32_t kb = (uint32_t)(ks * 16 * 2);
            uint32_t bh[2][4];
#pragma unroll
            for (int p = 0; p < 2; p++) {
                uint32_t off = boff + (uint32_t)((n0 + p * 16) * ASTRIDE * 2) + kb;
                ldm_x4(bh[p][0], bh[p][1], bh[p][2], bh[p][3], baseB + off);
            }
#pragma unroll
            for (int tm = 0; tm < 4; tm++) {
                uint32_t off = aoff + (uint32_t)((m0 + tm * 16) * ASTRIDE * 2) + kb;
                uint32_t ah[4];
                ldm_x4(ah[0], ah[1], ah[2], ah[3], baseA + off);
#pragma unroll
                for (int tn = 0; tn < 4; tn++) {
                    int p = tn >> 1, q = tn & 1;
                    mma16816(acc[tm][tn], ah, bh[p][q * 2], bh[p][q * 2 + 1]);
                }
            }
        }
        __syncthreads();
    }

    // epilogue: store C (+ optional fused attention partial dots)
    const int rit = lane >> 2;
    const int cq = (lane & 3) * 2;
#pragma unroll
    for (int tm = 0; tm < 4; tm++) {
        float s1a = 0.f, s2a = 0.f, s1b = 0.f, s2b = 0.f;
#pragma unroll
        for (int tn = 0; tn < 4; tn++) {
            size_t row = (size_t)(bm + m0 + tm * 16 + rit);
            int col = bn + n0 + tn * 8 + cq;
            if (HALF_OUT) {
                __half2 v0 = __floats2half2_rn(acc[tm][tn][0], acc[tm][tn][1]);
                __half2 v1 = __floats2half2_rn(acc[tm][tn][2], acc[tm][tn][3]);
                *(__half2*)&Ch[row * CN + col] = v0;
                *(__half2*)&Ch[(row + 8) * CN + col] = v1;
            } else {
                *(float2*)&Cf[row * CN + col] = make_float2(acc[tm][tn][0], acc[tm][tn][1]);
                *(float2*)&Cf[(row + 8) * CN + col] = make_float2(acc[tm][tn][2], acc[tm][tn][3]);
            }
            if (DO_ATT) {
                float a0 = __ldg(att_s + col), a1 = __ldg(att_s + col + 1);
                float d0 = __ldg(att_d + col), d1 = __ldg(att_d + col + 1);
                s1a += acc[tm][tn][0] * a0 + acc[tm][tn][1] * a1;
                s2a += acc[tm][tn][0] * d0 + acc[tm][tn][1] * d1;
                s1b += acc[tm][tn][2] * a0 + acc[tm][tn][3] * a1;
                s2b += acc[tm][tn][2] * d0 + acc[tm][tn][3] * d1;
            }
        }
        if (DO_ATT) {
#pragma unroll
            for (int off = 1; off < 4; off <<= 1) {
                s1a += __shfl_xor_sync(0xffffffffu, s1a, off);
                s2a += __shfl_xor_sync(0xffffffffu, s2a, off);
                s1b += __shfl_xor_sync(0xffffffffu, s1b, off);
                s2b += __shfl_xor_sync(0xffffffffu, s2b, off);
            }
            if ((lane & 3) == 0) {
                int rowA = bm + m0 + tm * 16 + rit;
                atomicAdd(&g_asrc[rowA], s1a);
                atomicAdd(&g_adst[rowA], s2a);
                atomicAdd(&g_asrc[rowA + 8], s1b);
                atomicAdd(&g_adst[rowA + 8], s2b);
            }
        }
    }
}

__global__ void __launch_bounds__(256, 2) k_gemm1(const float* __restrict__ att_s,
                                                  const float* __restrict__ att_d) {
    mma_gemm_body<GATD, GATD, 12, true, true>(g_A1, g_W1, nullptr, g_hh, att_s, att_d);
}
__global__ void __launch_bounds__(256, 2) k_gemm2() {
    mma_gemm_body<PD, XDP, 13, false, false>(g_X, g_W2, g_P, nullptr, nullptr, nullptr);
}

// ---------------- node init (after gemm1: asrc/adst final) ----------------
__global__ void k_init_node() {
    int i = blockIdx.x * blockDim.x + threadIdx.x;
    if (i >= NNODE) return;
    float al = lrelu(g_asrc[i] + g_adst[i]);   // self-loop alpha
    g_amax[i] = f2o(al);
    g_deg[i] = 0;
}

__global__ void k_edge_alpha(const int* __restrict__ ei) {
    int e = blockIdx.x * blockDim.x + threadIdx.x;
    if (e >= NEDGE) return;
    int s = ei[e], d = ei[NEDGE + e];
    float al = lrelu(g_asrc[s] + g_adst[d]);
    g_alphaE[e] = al;
    atomicMax(&g_amax[d], f2o(al));
    atomicAdd(&g_deg[d], 1);
}

// exclusive scan of deg -> rowstart/pos; phase 2: denom self-loop init
__global__ void k_scan() {
    __shared__ int sh[1024];
    __shared__ int s_carry;
    int tid = threadIdx.x;
    if (tid == 0) s_carry = 0;
    __syncthreads();
    for (int base = 0; base < NNODE; base += 1024) {
        int i = base + tid;
        int v = (i < NNODE) ? g_deg[i] : 0;
        sh[tid] = v;
        __syncthreads();
        for (int off = 1; off < 1024; off <<= 1) {
            int t = (tid >= off) ? sh[tid - off] : 0;
            __syncthreads();
            sh[tid] += t;
            __syncthreads();
        }
        int incl = sh[tid];
        int carry = s_carry;
        if (i < NNODE) {
            int excl = carry + incl - v;
            g_rowstart[i] = excl;
            g_pos[i] = excl;
        }
        __syncthreads();
        if (tid == 1023) s_carry = carry + incl;
        __syncthreads();
    }
    for (int i = tid; i < NNODE; i += 1024) {
        float al = lrelu(g_asrc[i] + g_adst[i]);
        g_denom[i] = expf(al - o2f(g_amax[i]));
    }
}

// fused CSR fill + exp + denom accumulate
__global__ void k_edge_build(const int* __restrict__ ei) {
    int e = blockIdx.x * blockDim.x + threadIdx.x;
    if (e >= NEDGE) return;
    int s = ei[e], d = ei[NEDGE + e];
    int p = atomicAdd(&g_pos[d], 1);
    g_csr_src[p] = s;
    g_csr_eid[p] = e;
    float ex = expf(g_alphaE[e] - o2f(g_amax[d]));
    g_csr_ex[p] = ex;
    atomicAdd(&g_denom[d], ex);
}

// ---------------- GAT gather-aggregation: warp per node (fp16 h rows) ----------------
__global__ void k_gat_aggr(const float* __restrict__ b_gat) {
    int warp = (blockIdx.x * blockDim.x + threadIdx.x) >> 5;
    int lane = threadIdx.x & 31;
    if (warp >= NNODE) return;
    int i = warp;
    float amaxv = o2f(g_amax[i]);
    float als = lrelu(g_asrc[i] + g_adst[i]);
    float inv_den = 1.0f / g_denom[i];
    float cs = expf(als - amaxv) * inv_den;

    const uint4* hrow = (const uint4*)(g_hh + (size_t)i * GATD);
    const float4* bg = (const float4*)b_gat;
    float acc[3][8];
#pragma unroll
    for (int t = 0; t < 3; t++) {
        float f[8];
        unpack8(hrow[lane + 32 * t], f);
        float4 b0 = bg[2 * (lane + 32 * t)];
        float4 b1 = bg[2 * (lane + 32 * t) + 1];
        acc[t][0] = cs * f[0] + b0.x; acc[t][1] = cs * f[1] + b0.y;
        acc[t][2] = cs * f[2] + b0.z; acc[t][3] = cs * f[3] + b0.w;
        acc[t][4] = cs * f[4] + b1.x; acc[t][5] = cs * f[5] + b1.y;
        acc[t][6] = cs * f[6] + b1.z; acc[t][7] = cs * f[7] + b1.w;
    }
    int rs = g_rowstart[i], d = g_deg[i];
    for (int base = 0; base < d; base += 32) {
        int cnt = min(32, d - base);
        int sj = 0;
        float cj = 0.f;
        if (lane < cnt) {
            sj = g_csr_src[rs + base + lane];
            cj = g_csr_ex[rs + base + lane] * inv_den;
        }
        for (int k = 0; k < cnt; k++) {
            int s = __shfl_sync(0xffffffffu, sj, k);
            float coef = __shfl_sync(0xffffffffu, cj, k);
            const uint4* hs = (const uint4*)(g_hh + (size_t)s * GATD);
#pragma unroll
            for (int t = 0; t < 3; t++) {
                float f[8];
                unpack8(__ldg(&hs[lane + 32 * t]), f);
#pragma unroll
                for (int q = 0; q < 8; q++) acc[t][q] += coef * f[q];
            }
        }
    }
    size_t xbase = (size_t)i * XDP;
#pragma unroll
    for (int t = 0; t < 3; t++) {
        *(uint4*)(g_X + xbase + 8 * (lane + 32 * t)) = pack8(acc[t]);
    }
}

// ---------------- final aggregation (fused edge learner + ea@We): warp per node ----------------
__global__ void k_meta(float* __restrict__ out, const float* __restrict__ b_nbr,
                       const float* __restrict__ b_self, const float* __restrict__ W_nbr,
                       const float* __restrict__ W_edge, const float* __restrict__ b_edge,
                       const float* __restrict__ edge_attr) {
    __shared__ float sWe[16 * 128];
    __shared__ float sWE[16 * 16];
    __shared__ float sBN[128];
    for (int t = threadIdx.x; t < 2048; t += blockDim.x)
        sWe[t] = W_nbr[1600 * 128 + t];
    for (int t = threadIdx.x; t < 256; t += blockDim.x)
        sWE[t] = W_edge[t];
    __syncthreads();
    if (threadIdx.x < 128) {
        int c = threadIdx.x;
        float s = b_nbr[c];
#pragma unroll
        for (int k = 0; k < 16; k++) s += b_edge[k] * sWe[k * 128 + c];
        sBN[c] = s;
    }
    __syncthreads();

    int warp = (blockIdx.x * blockDim.x + threadIdx.x) >> 5;
    int lane = threadIdx.x & 31;
    if (warp >= NNODE) return;
    int i = warp;
    const float4* Pr = (const float4*)(g_P + (size_t)i * PD);
    float4 p1 = Pr[lane];        // dst-part
    float4 xs = Pr[64 + lane];   // self-part
    float4 bs = ((const float4*)b_self)[lane];
    float4 bn4 = *(const float4*)&sBN[lane * 4];
    float degf = (float)g_deg[i];
    float4 acc;
    acc.x = xs.x + bs.x + degf * (p1.x + bn4.x);
    acc.y = xs.y + bs.y + degf * (p1.y + bn4.y);
    acc.z = xs.z + bs.z + degf * (p1.z + bn4.z);
    acc.w = xs.w + bs.w + degf * (p1.w + bn4.w);

    float eas[16];
#pragma unroll
    for (int k = 0; k < 16; k++) eas[k] = 0.f;

    int rs = g_rowstart[i], d = g_deg[i];
    for (int base = 0; base < d; base += 32) {
        int cnt = min(32, d - base);
        int sj = 0, ej = 0;
        if (lane < cnt) {
            sj = g_csr_src[rs + base + lane];
            ej = g_csr_eid[rs + base + lane];
        }
        for (int k = 0; k < cnt; k++) {
            int s = __shfl_sync(0xffffffffu, sj, k);
            int e = __shfl_sync(0xffffffffu, ej, k);
            float4 p2 = __ldg(&((const float4*)(g_P + (size_t)s * PD))[32 + lane]);
            acc.x += p2.x;
            acc.y += p2.y;
            acc.z += p2.z;
            acc.w += p2.w;
            const float4* ear = (const float4*)(edge_attr + (size_t)e * 16);
            float4 e0 = __ldg(ear), e1 = __ldg(ear + 1), e2 = __ldg(ear + 2), e3 = __ldg(ear + 3);
            eas[0] += e0.x;  eas[1] += e0.y;  eas[2] += e0.z;  eas[3] += e0.w;
            eas[4] += e1.x;  eas[5] += e1.y;  eas[6] += e1.z;  eas[7] += e1.w;
            eas[8] += e2.x;  eas[9] += e2.y;  eas[10] += e2.z; eas[11] += e2.w;
            eas[12] += e3.x; eas[13] += e3.y; eas[14] += e3.z; eas[15] += e3.w;
        }
    }

    float tv[16];
#pragma unroll
    for (int kk = 0; kk < 16; kk++) {
        float s = 0.f;
#pragma unroll
        for (int j = 0; j < 16; j++) s += eas[j] * sWE[j * 16 + kk];
        tv[kk] = s;
    }
    int col = lane * 4;
#pragma unroll
    for (int kk = 0; kk < 16; kk++) {
        float4 wv = *(const float4*)&sWe[kk * 128 + col];
        float ev = tv[kk];
        acc.x += ev * wv.x;
        acc.y += ev * wv.y;
        acc.z += ev * wv.z;
        acc.w += ev * wv.w;
    }
    ((float4*)(out + (size_t)i * MD))[lane] = acc;
}

// ---------------- launch ----------------
extern "C" void kernel_launch(void* const* d_in, const int* in_sizes, int n_in,
                              void* d_out, int out_size) {
    const float* node_feature    = (const float*)d_in[0];
    const float* edge_attr       = (const float*)d_in[1];
    const float* message_feature = (const float*)d_in[2];
    const int*   edge_index      = (const int*)d_in[3];
    const float* W_node = (const float*)d_in[4];
    const float* b_node = (const float*)d_in[5];
    const float* W_edge = (const float*)d_in[6];
    const float* b_edge = (const float*)d_in[7];
    const float* W_gat  = (const float*)d_in[8];
    const float* att_src = (const float*)d_in[9];
    const float* att_dst = (const float*)d_in[10];
    const float* b_gat  = (const float*)d_in[11];
    const float* W_nbr  = (const float*)d_in[12];
    const float* b_nbr  = (const float*)d_in[13];
    const float* W_self = (const float*)d_in[14];
    const float* b_self = (const float*)d_in[15];
    float* out = (float*)d_out;

    const int GEMM_SMEM = 3 * STAGE_BYTES;   // 110592 (3 stages x A|B, K chunk 64)
    cudaFuncSetAttribute(k_gemm1, cudaFuncAttributeMaxDynamicSharedMemorySize, GEMM_SMEM);
    cudaFuncSetAttribute(k_gemm2, cudaFuncAttributeMaxDynamicSharedMemorySize, GEMM_SMEM);

    // prep
    k_nodeL<<<(NNODE * 32 + 255) / 256, 256>>>(node_feature, W_node, b_node);
    k_cvtA1<<<(NNODE * GATD / 2 + 255) / 256, 256>>>(message_feature);
    k_cvtW1<<<dim3(GATD / 32, GATD / 32), dim3(32, 8)>>>(W_gat);

    // h = mf @ W_gat  (fp16 out, + fused attention scalar partial dots)
    k_gemm1<<<dim3(GATD / 128, NNODE / 128), 256, GEMM_SMEM>>>(att_src, att_dst);

    // softmax structure
    k_init_node<<<(NNODE + 255) / 256, 256>>>();
    k_edge_alpha<<<(NEDGE + 255) / 256, 256>>>(edge_index);
    k_scan<<<1, 1024>>>();
    k_edge_build<<<(NEDGE + 255) / 256, 256>>>(edge_index);

    // GAT aggregation -> X cols 0:768 (fp16 h rows)
    k_gat_aggr<<<(NNODE * 32 + 255) / 256, 256>>>(b_gat);

    // P = x @ Wcat  (fp16)
    k_cvtW2<<<(PD * XDP + 255) / 256, 256>>>(W_nbr, W_self);
    k_gemm2<<<dim3(PD / 128, NNODE / 128), 256, GEMM_SMEM>>>();

    // final per-node aggregation (fused edge learner) -> out
    k_meta<<<(NNODE * 32 + 255) / 256, 256>>>(out, b_nbr, b_self, W_nbr,
                                              W_edge, b_edge, edge_attr);
}

// round 12
// speedup vs baseline: 1.9920x; 1.0859x over previous
#include <cuda_runtime.h>
#include <cuda_fp16.h>
#include <cstdint>

// ---------------- problem constants ----------------
#define NNODE 16000
#define NEDGE 128000
#define GATD 768          // GAT dim
#define XD 800            // meta-in dim (768 gat + 32 node)
#define XDP 832           // padded K for GEMM2 (13 x 64)
#define MD 128            // meta out dim
#define PD 384            // P1(dst part) | P2(src part) | Xself

// ---------------- device scratch (no allocs allowed) ----------------
__device__ __half   g_hh[NNODE * GATD];      // h in fp16 (only consumer: gather)
__device__ float    g_P[NNODE * PD];         // 24.6 MB
__device__ float    g_asrc[NNODE];
__device__ float    g_adst[NNODE];
__device__ unsigned g_amax[NNODE];           // ordered-float bits (0 = -inf sentinel)
__device__ float    g_denom[NNODE];
__device__ float    g_alphaE[NEDGE];
__device__ int      g_deg[NNODE];
__device__ int      g_rowstart[NNODE];
__device__ int      g_pos[NNODE];
__device__ int      g_csr_src[NEDGE];
__device__ int      g_csr_eid[NEDGE];
__device__ float    g_csr_ex[NEDGE];
// fp16 operands
__device__ __half g_A1[NNODE * GATD];
__device__ __half g_X[NNODE * XDP];
__device__ __half g_W1[GATD * GATD];   // W_gat^T  [n,k]
__device__ __half g_W2[PD * XDP];      // Wcat^T   [n,k]

// ---------------- helpers ----------------
__device__ __forceinline__ float lrelu(float x) { return x >= 0.f ? x : 0.2f * x; }
__device__ __forceinline__ unsigned f2o(float f) {
    unsigned b = __float_as_uint(f);
    return (b & 0x80000000u) ? ~b : (b | 0x80000000u);
}
__device__ __forceinline__ float o2f(unsigned b) {
    b = (b & 0x80000000u) ? (b & 0x7fffffffu) : ~b;
    return __uint_as_float(b);
}
__device__ __forceinline__ uint32_t smem_u32(const void* p) {
    uint32_t a;
    asm("{ .reg .u64 t; cvta.to.shared.u64 t, %1; cvt.u32.u64 %0, t; }" : "=r"(a) : "l"(p));
    return a;
}
__device__ __forceinline__ void ldm_x4(uint32_t& r0, uint32_t& r1, uint32_t& r2, uint32_t& r3,
                                       uint32_t addr) {
    asm volatile("ldmatrix.sync.aligned.m8n8.x4.shared.b16 {%0,%1,%2,%3}, [%4];"
                 : "=r"(r0), "=r"(r1), "=r"(r2), "=r"(r3) : "r"(addr));
}
__device__ __forceinline__ void mma16816(float* c, const uint32_t* a, uint32_t b0, uint32_t b1) {
    asm volatile(
        "mma.sync.aligned.m16n8k16.row.col.f32.f16.f16.f32 "
        "{%0,%1,%2,%3}, {%4,%5,%6,%7}, {%8,%9}, {%0,%1,%2,%3};"
        : "+f"(c[0]), "+f"(c[1]), "+f"(c[2]), "+f"(c[3])
        : "r"(a[0]), "r"(a[1]), "r"(a[2]), "r"(a[3]), "r"(b0), "r"(b1));
}
__device__ __forceinline__ void cp16(uint32_t dst, const void* src) {
    asm volatile("cp.async.cg.shared.global [%0], [%1], 16;" :: "r"(dst), "l"(src));
}
#define CP_COMMIT() asm volatile("cp.async.commit_group;" ::: "memory")
#define CP_WAIT2()  asm volatile("cp.async.wait_group 2;" ::: "memory")
#define CP_WAIT1()  asm volatile("cp.async.wait_group 1;" ::: "memory")
#define CP_WAIT0()  asm volatile("cp.async.wait_group 0;" ::: "memory")

__device__ __forceinline__ void unpack8(uint4 v, float* f) {
    float2 a = __half22float2(*(__half2*)&v.x);
    float2 b = __half22float2(*(__half2*)&v.y);
    float2 c = __half22float2(*(__half2*)&v.z);
    float2 d = __half22float2(*(__half2*)&v.w);
    f[0] = a.x; f[1] = a.y; f[2] = b.x; f[3] = b.y;
    f[4] = c.x; f[5] = c.y; f[6] = d.x; f[7] = d.y;
}
__device__ __forceinline__ uint4 pack8(const float* f) {
    uint4 o;
    __half2 h0 = __floats2half2_rn(f[0], f[1]);
    __half2 h1 = __floats2half2_rn(f[2], f[3]);
    __half2 h2 = __floats2half2_rn(f[4], f[5]);
    __half2 h3 = __floats2half2_rn(f[6], f[7]);
    o.x = *(uint32_t*)&h0; o.y = *(uint32_t*)&h1;
    o.z = *(uint32_t*)&h2; o.w = *(uint32_t*)&h3;
    return o;
}

// ---------------- fused prep kernel (block-range dispatch) ----------------
#define PREP_B_A1  24000    // cvtA1: NNODE*GATD/2 half2 / 256
#define PREP_B_NL  2000     // nodeL: NNODE*32 / 256
#define PREP_B_W2  1248     // cvtW2: PD*XDP / 256
#define PREP_B_W1  576      // cvtW1: (768/32)^2 tiles
#define PREP_B_Z   63       // zero init: ceil(16000/256)
#define PREP_BLOCKS (PREP_B_A1 + PREP_B_NL + PREP_B_W2 + PREP_B_W1 + PREP_B_Z)

__global__ void k_prep(const float* __restrict__ mf, const float* __restrict__ nf,
                       const float* __restrict__ Wnode, const float* __restrict__ bnode,
                       const float* __restrict__ Wg,
                       const float* __restrict__ Wnbr, const float* __restrict__ Wself) {
    __shared__ float tile[32][33];
    int b = blockIdx.x;
    int t = threadIdx.x;
    if (b < PREP_B_A1) {                       // A1 convert (half2)
        int idx = b * 256 + t;
        float2 v = ((const float2*)mf)[idx];
        ((__half2*)g_A1)[idx] = __floats2half2_rn(v.x, v.y);
        return;
    }
    b -= PREP_B_A1;
    if (b < PREP_B_NL) {                       // node learner -> X cols 768:832
        int idx = b * 256 + t;
        int i = idx >> 5, j = idx & 31;
        const float* r = nf + i * 32;
        float s = bnode[j];
#pragma unroll
        for (int k = 0; k < 32; k++) s += r[k] * Wnode[k * 32 + j];
        size_t base = (size_t)i * XDP;
        g_X[base + 768 + j] = __float2half_rn(s);
        g_X[base + 800 + j] = __float2half(0.f);
        return;
    }
    b -= PREP_B_NL;
    if (b < PREP_B_W2) {                       // W2 build
        int idx = b * 256 + t;
        int n = idx / XDP, k = idx % XDP;
        float v = 0.f;
        if (k < XD) {
            if (n < 128)      v = Wnbr[k * 128 + n];
            else if (n < 256) v = Wnbr[(800 + k) * 128 + (n - 128)];
            else              v = Wself[k * 128 + (n - 256)];
        }
        g_W2[idx] = __float2half_rn(v);
        return;
    }
    b -= PREP_B_W2;
    if (b < PREP_B_W1) {                       // W1 transpose (32x32 tile)
        int tx = t & 31, ty = t >> 5;          // 32 x 8
        int n0 = (b % 24) * 32, k0 = (b / 24) * 32;
#pragma unroll
        for (int i = 0; i < 4; i++)
            tile[ty + i * 8][tx] = Wg[(size_t)(k0 + ty + i * 8) * GATD + n0 + tx];
        __syncthreads();
#pragma unroll
        for (int i = 0; i < 4; i++) {
            size_t o = (size_t)(n0 + ty + i * 8) * GATD + k0 + tx;
            g_W1[o] = __float2half_rn(tile[tx][ty + i * 8]);
        }
        return;
    }
    b -= PREP_B_W1;
    {                                          // zero init
        int i = b * 256 + t;
        if (i < NNODE) {
            g_asrc[i] = 0.f;
            g_adst[i] = 0.f;
            g_amax[i] = 0u;    // below every ordered-float
            g_deg[i] = 0;
        }
    }
}

// ---------------- warp-MMA fp16 GEMM (cp.async 3-stage, K chunk 64) ----------------
#define ASTRIDE 72
#define TILE_BYTES 18432                  // 128*72*2
#define STAGE_BYTES (2 * TILE_BYTES)      // A|B

template <int CN, int KPAD, int NCH, bool DO_ATT, bool HALF_OUT>
__device__ __forceinline__ void mma_gemm_body(const __half* __restrict__ A,
                                              const __half* __restrict__ B,
                                              float* __restrict__ Cf,
                                              __half* __restrict__ Ch,
                                              const float* __restrict__ att_s,
                                              const float* __restrict__ att_d) {
    extern __shared__ char smem[];
    const uint32_t sb = smem_u32(smem);

    const int t = threadIdx.x;
    const int lane = t & 31;
    const int wid = t >> 5;
    const int m0 = (wid >> 2) * 64;
    const int n0 = (wid & 3) * 32;
    const int bm = blockIdx.y * 128;
    const int bn = blockIdx.x * 128;

    const uint32_t aoff = (uint32_t)(((lane & 15) * ASTRIDE + (lane >> 4) * 8) * 2);
    const uint32_t boff = (uint32_t)((((lane & 7) + ((lane >> 4) << 3)) * ASTRIDE +
                                     (((lane >> 3) & 1) << 3)) * 2);

    float acc[4][4][4];
#pragma unroll
    for (int i = 0; i < 4; i++)
#pragma unroll
        for (int j = 0; j < 4; j++)
#pragma unroll
            for (int q = 0; q < 4; q++) acc[i][j][q] = 0.f;

    auto issue_chunk = [&](int c, int s) {
        const int c0 = c * 64;
        const uint32_t dst = sb + (uint32_t)s * STAGE_BYTES;
#pragma unroll
        for (int it = 0; it < 4; it++) {
            int idx = it * 256 + t;
            int r = idx >> 3, j = idx & 7;
            size_t ga = (size_t)(bm + r) * KPAD + c0 + j * 8;
            size_t gb = (size_t)(bn + r) * KPAD + c0 + j * 8;
            uint32_t doff = (uint32_t)((r * ASTRIDE + j * 8) * 2);
            cp16(dst + doff, A + ga);
            cp16(dst + TILE_BYTES + doff, B + gb);
        }
    };

    issue_chunk(0, 0);
    CP_COMMIT();
    issue_chunk(1, 1);
    CP_COMMIT();

    for (int c = 0; c < NCH; c++) {
        const int s = c % 3;
        if (c + 2 < NCH) {
            issue_chunk(c + 2, (c + 2) % 3);
            CP_COMMIT();
            CP_WAIT2();
        } else if (c + 1 < NCH) {
            CP_WAIT1();
        } else {
            CP_WAIT0();
        }
        __syncthreads();

        const uint32_t baseA = sb + (uint32_t)s * STAGE_BYTES;
        const uint32_t baseB = baseA + TILE_BYTES;

#pragma unroll
        for (int ks = 0; ks < 4; ks++) {
            const uint32_t kb = (uint32_t)(ks * 16 * 2);
            uint32_t bh[2][4];
#pragma unroll
            for (int p = 0; p < 2; p++) {
                uint32_t off = boff + (uint32_t)((n0 + p * 16) * ASTRIDE * 2) + kb;
                ldm_x4(bh[p][0], bh[p][1], bh[p][2], bh[p][3], baseB + off);
            }
#pragma unroll
            for (int tm = 0; tm < 4; tm++) {
                uint32_t off = aoff + (uint32_t)((m0 + tm * 16) * ASTRIDE * 2) + kb;
                uint32_t ah[4];
                ldm_x4(ah[0], ah[1], ah[2], ah[3], baseA + off);
#pragma unroll
                for (int tn = 0; tn < 4; tn++) {
                    int p = tn >> 1, q = tn & 1;
                    mma16816(acc[tm][tn], ah, bh[p][q * 2], bh[p][q * 2 + 1]);
                }
            }
        }
        __syncthreads();
    }

    const int rit = lane >> 2;
    const int cq = (lane & 3) * 2;
#pragma unroll
    for (int tm = 0; tm < 4; tm++) {
        float s1a = 0.f, s2a = 0.f, s1b = 0.f, s2b = 0.f;
#pragma unroll
        for (int tn = 0; tn < 4; tn++) {
            size_t row = (size_t)(bm + m0 + tm * 16 + rit);
            int col = bn + n0 + tn * 8 + cq;
            if (HALF_OUT) {
                __half2 v0 = __floats2half2_rn(acc[tm][tn][0], acc[tm][tn][1]);
                __half2 v1 = __floats2half2_rn(acc[tm][tn][2], acc[tm][tn][3]);
                *(__half2*)&Ch[row * CN + col] = v0;
                *(__half2*)&Ch[(row + 8) * CN + col] = v1;
            } else {
                *(float2*)&Cf[row * CN + col] = make_float2(acc[tm][tn][0], acc[tm][tn][1]);
                *(float2*)&Cf[(row + 8) * CN + col] = make_float2(acc[tm][tn][2], acc[tm][tn][3]);
            }
            if (DO_ATT) {
                float a0 = __ldg(att_s + col), a1 = __ldg(att_s + col + 1);
                float d0 = __ldg(att_d + col), d1 = __ldg(att_d + col + 1);
                s1a += acc[tm][tn][0] * a0 + acc[tm][tn][1] * a1;
                s2a += acc[tm][tn][0] * d0 + acc[tm][tn][1] * d1;
                s1b += acc[tm][tn][2] * a0 + acc[tm][tn][3] * a1;
                s2b += acc[tm][tn][2] * d0 + acc[tm][tn][3] * d1;
            }
        }
        if (DO_ATT) {
#pragma unroll
            for (int off = 1; off < 4; off <<= 1) {
                s1a += __shfl_xor_sync(0xffffffffu, s1a, off);
                s2a += __shfl_xor_sync(0xffffffffu, s2a, off);
                s1b += __shfl_xor_sync(0xffffffffu, s1b, off);
                s2b += __shfl_xor_sync(0xffffffffu, s2b, off);
            }
            if ((lane & 3) == 0) {
                int rowA = bm + m0 + tm * 16 + rit;
                atomicAdd(&g_asrc[rowA], s1a);
                atomicAdd(&g_adst[rowA], s2a);
                atomicAdd(&g_asrc[rowA + 8], s1b);
                atomicAdd(&g_adst[rowA + 8], s2b);
            }
        }
    }
}

__global__ void __launch_bounds__(256, 2) k_gemm1(const float* __restrict__ att_s,
                                                  const float* __restrict__ att_d) {
    mma_gemm_body<GATD, GATD, 12, true, true>(g_A1, g_W1, nullptr, g_hh, att_s, att_d);
}
__global__ void __launch_bounds__(256, 2) k_gemm2() {
    mma_gemm_body<PD, XDP, 13, false, false>(g_X, g_W2, g_P, nullptr, nullptr, nullptr);
}

// ---------------- edge alpha pass (deg + amax) ----------------
__global__ void k_edge_alpha(const int* __restrict__ ei) {
    int e = blockIdx.x * blockDim.x + threadIdx.x;
    if (e >= NEDGE) return;
    int s = ei[e], d = ei[NEDGE + e];
    float al = lrelu(g_asrc[s] + g_adst[d]);
    g_alphaE[e] = al;
    atomicMax(&g_amax[d], f2o(al));
    atomicAdd(&g_deg[d], 1);
}

// warp-shuffle scan of deg -> rowstart/pos; phase 2: fold self into amax, denom init
__global__ void k_scan() {
    __shared__ int wsum[32];
    __shared__ int s_carry;
    int tid = threadIdx.x, lane = tid & 31, wid = tid >> 5;
    if (tid == 0) s_carry = 0;
    __syncthreads();
    for (int base = 0; base < NNODE; base += 1024) {
        int i = base + tid;
        int v = (i < NNODE) ? g_deg[i] : 0;
        int incl = v;
#pragma unroll
        for (int o = 1; o < 32; o <<= 1) {
            int n = __shfl_up_sync(0xffffffffu, incl, o);
            if (lane >= o) incl += n;
        }
        if (lane == 31) wsum[wid] = incl;
        __syncthreads();
        if (wid == 0) {
            int w = wsum[lane];
            int ws = w;
#pragma unroll
            for (int o = 1; o < 32; o <<= 1) {
                int n = __shfl_up_sync(0xffffffffu, ws, o);
                if (lane >= o) ws += n;
            }
            wsum[lane] = ws - w;   // exclusive across warps
        }
        __syncthreads();
        int excl = s_carry + wsum[wid] + incl - v;
        if (i < NNODE) { g_rowstart[i] = excl; g_pos[i] = excl; }
        __syncthreads();
        if (tid == 1023) s_carry = excl + v;
        __syncthreads();
    }
    // phase 2: amax includes self; denom = exp(self - amax)
    for (int i = tid; i < NNODE; i += 1024) {
        float al = lrelu(g_asrc[i] + g_adst[i]);
        float am = fmaxf(o2f(g_amax[i]), al);   // o2f(0)=NaN -> fmaxf returns al
        g_amax[i] = f2o(am);
        g_denom[i] = expf(al - am);
    }
}

// fused CSR fill + exp + denom accumulate
__global__ void k_edge_build(const int* __restrict__ ei) {
    int e = blockIdx.x * blockDim.x + threadIdx.x;
    if (e >= NEDGE) return;
    int s = ei[e], d = ei[NEDGE + e];
    int p = atomicAdd(&g_pos[d], 1);
    g_csr_src[p] = s;
    g_csr_eid[p] = e;
    float ex = expf(g_alphaE[e] - o2f(g_amax[d]));
    g_csr_ex[p] = ex;
    atomicAdd(&g_denom[d], ex);
}

// ---------------- GAT gather-aggregation: warp per node (unroll-2 edges) ----------------
__global__ void k_gat_aggr(const float* __restrict__ b_gat) {
    int warp = (blockIdx.x * blockDim.x + threadIdx.x) >> 5;
    int lane = threadIdx.x & 31;
    if (warp >= NNODE) return;
    int i = warp;
    float amaxv = o2f(g_amax[i]);
    float als = lrelu(g_asrc[i] + g_adst[i]);
    float inv_den = 1.0f / g_denom[i];
    float cs = expf(als - amaxv) * inv_den;

    const uint4* hrow = (const uint4*)(g_hh + (size_t)i * GATD);
    const float4* bg = (const float4*)b_gat;
    float acc[3][8];
#pragma unroll
    for (int t = 0; t < 3; t++) {
        float f[8];
        unpack8(hrow[lane + 32 * t], f);
        float4 b0 = bg[2 * (lane + 32 * t)];
        float4 b1 = bg[2 * (lane + 32 * t) + 1];
        acc[t][0] = cs * f[0] + b0.x; acc[t][1] = cs * f[1] + b0.y;
        acc[t][2] = cs * f[2] + b0.z; acc[t][3] = cs * f[3] + b0.w;
        acc[t][4] = cs * f[4] + b1.x; acc[t][5] = cs * f[5] + b1.y;
        acc[t][6] = cs * f[6] + b1.z; acc[t][7] = cs * f[7] + b1.w;
    }
    int rs = g_rowstart[i], d = g_deg[i];
    for (int base = 0; base < d; base += 32) {
        int cnt = min(32, d - base);
        int sj = 0;
        float cj = 0.f;
        if (lane < cnt) {
            sj = g_csr_src[rs + base + lane];
            cj = g_csr_ex[rs + base + lane] * inv_den;
        }
        int k = 0;
        for (; k + 1 < cnt; k += 2) {
            int s0 = __shfl_sync(0xffffffffu, sj, k);
            int s1 = __shfl_sync(0xffffffffu, sj, k + 1);
            float c0 = __shfl_sync(0xffffffffu, cj, k);
            float c1 = __shfl_sync(0xffffffffu, cj, k + 1);
            const uint4* h0 = (const uint4*)(g_hh + (size_t)s0 * GATD);
            const uint4* h1 = (const uint4*)(g_hh + (size_t)s1 * GATD);
            uint4 r0[3], r1[3];
#pragma unroll
            for (int t = 0; t < 3; t++) {
                r0[t] = __ldg(&h0[lane + 32 * t]);
                r1[t] = __ldg(&h1[lane + 32 * t]);
            }
#pragma unroll
            for (int t = 0; t < 3; t++) {
                float f0[8], f1[8];
                unpack8(r0[t], f0);
                unpack8(r1[t], f1);
#pragma unroll
                for (int q = 0; q < 8; q++) acc[t][q] += c0 * f0[q] + c1 * f1[q];
            }
        }
        if (k < cnt) {
            int s0 = __shfl_sync(0xffffffffu, sj, k);
            float c0 = __shfl_sync(0xffffffffu, cj, k);
            const uint4* h0 = (const uint4*)(g_hh + (size_t)s0 * GATD);
#pragma unroll
            for (int t = 0; t < 3; t++) {
                float f0[8];
                unpack8(__ldg(&h0[lane + 32 * t]), f0);
#pragma unroll
                for (int q = 0; q < 8; q++) acc[t][q] += c0 * f0[q];
            }
        }
    }
    size_t xbase = (size_t)i * XDP;
#pragma unroll
    for (int t = 0; t < 3; t++) {
        *(uint4*)(g_X + xbase + 8 * (lane + 32 * t)) = pack8(acc[t]);
    }
}

// ---------------- final aggregation (fused edge learner + ea@We, unroll-2) ----------------
__global__ void k_meta(float* __restrict__ out, const float* __restrict__ b_nbr,
                       const float* __restrict__ b_self, const float* __restrict__ W_nbr,
                       const float* __restrict__ W_edge, const float* __restrict__ b_edge,
                       const float* __restrict__ edge_attr) {
    __shared__ float sWe[16 * 128];
    __shared__ float sWE[16 * 16];
    __shared__ float sBN[128];
    for (int t = threadIdx.x; t < 2048; t += blockDim.x)
        sWe[t] = W_nbr[1600 * 128 + t];
    for (int t = threadIdx.x; t < 256; t += blockDim.x)
        sWE[t] = W_edge[t];
    __syncthreads();
    if (threadIdx.x < 128) {
        int c = threadIdx.x;
        float s = b_nbr[c];
#pragma unroll
        for (int k = 0; k < 16; k++) s += b_edge[k] * sWe[k * 128 + c];
        sBN[c] = s;
    }
    __syncthreads();

    int warp = (blockIdx.x * blockDim.x + threadIdx.x) >> 5;
    int lane = threadIdx.x & 31;
    if (warp >= NNODE) return;
    int i = warp;
    const float4* Pr = (const float4*)(g_P + (size_t)i * PD);
    float4 p1 = Pr[lane];        // dst-part
    float4 xs = Pr[64 + lane];   // self-part
    float4 bs = ((const float4*)b_self)[lane];
    float4 bn4 = *(const float4*)&sBN[lane * 4];
    float degf = (float)g_deg[i];
    float4 acc;
    acc.x = xs.x + bs.x + degf * (p1.x + bn4.x);
    acc.y = xs.y + bs.y + degf * (p1.y + bn4.y);
    acc.z = xs.z + bs.z + degf * (p1.z + bn4.z);
    acc.w = xs.w + bs.w + degf * (p1.w + bn4.w);

    float eas[16];
#pragma unroll
    for (int k = 0; k < 16; k++) eas[k] = 0.f;

    int rs = g_rowstart[i], d = g_deg[i];
    for (int base = 0; base < d; base += 32) {
        int cnt = min(32, d - base);
        int sj = 0, ej = 0;
        if (lane < cnt) {
            sj = g_csr_src[rs + base + lane];
            ej = g_csr_eid[rs + base + lane];
        }
        int k = 0;
        for (; k + 1 < cnt; k += 2) {
            int s0 = __shfl_sync(0xffffffffu, sj, k);
            int s1 = __shfl_sync(0xffffffffu, sj, k + 1);
            int e0i = __shfl_sync(0xffffffffu, ej, k);
            int e1i = __shfl_sync(0xffffffffu, ej, k + 1);
            float4 p2a = __ldg(&((const float4*)(g_P + (size_t)s0 * PD))[32 + lane]);
            float4 p2b = __ldg(&((const float4*)(g_P + (size_t)s1 * PD))[32 + lane]);
            const float4* ea0 = (const float4*)(edge_attr + (size_t)e0i * 16);
            const float4* ea1 = (const float4*)(edge_attr + (size_t)e1i * 16);
            float4 a0 = __ldg(ea0), a1 = __ldg(ea0 + 1), a2 = __ldg(ea0 + 2), a3 = __ldg(ea0 + 3);
            float4 c0 = __ldg(ea1), c1 = __ldg(ea1 + 1), c2 = __ldg(ea1 + 2), c3 = __ldg(ea1 + 3);
            acc.x += p2a.x + p2b.x;
            acc.y += p2a.y + p2b.y;
            acc.z += p2a.z + p2b.z;
            acc.w += p2a.w + p2b.w;
            eas[0] += a0.x + c0.x;  eas[1] += a0.y + c0.y;  eas[2] += a0.z + c0.z;  eas[3] += a0.w + c0.w;
            eas[4] += a1.x + c1.x;  eas[5] += a1.y + c1.y;  eas[6] += a1.z + c1.z;  eas[7] += a1.w + c1.w;
            eas[8] += a2.x + c2.x;  eas[9] += a2.y + c2.y;  eas[10] += a2.z + c2.z; eas[11] += a2.w + c2.w;
            eas[12] += a3.x + c3.x; eas[13] += a3.y + c3.y; eas[14] += a3.z + c3.z; eas[15] += a3.w + c3.w;
        }
        if (k < cnt) {
            int s0 = __shfl_sync(0xffffffffu, sj, k);
            int e0i = __shfl_sync(0xffffffffu, ej, k);
            float4 p2 = __ldg(&((const float4*)(g_P + (size_t)s0 * PD))[32 + lane]);
            acc.x += p2.x;
            acc.y += p2.y;
            acc.z += p2.z;
            acc.w += p2.w;
            const float4* ear = (const float4*)(edge_attr + (size_t)e0i * 16);
            float4 e0 = __ldg(ear), e1 = __ldg(ear + 1), e2 = __ldg(ear + 2), e3 = __ldg(ear + 3);
            eas[0] += e0.x;  eas[1] += e0.y;  eas[2] += e0.z;  eas[3] += e0.w;
            eas[4] += e1.x;  eas[5] += e1.y;  eas[6] += e1.z;  eas[7] += e1.w;
            eas[8] += e2.x;  eas[9] += e2.y;  eas[10] += e2.z; eas[11] += e2.w;
            eas[12] += e3.x; eas[13] += e3.y; eas[14] += e3.z; eas[15] += e3.w;
        }
    }

    float tv[16];
#pragma unroll
    for (int kk = 0; kk < 16; kk++) {
        float s = 0.f;
#pragma unroll
        for (int j = 0; j < 16; j++) s += eas[j] * sWE[j * 16 + kk];
        tv[kk] = s;
    }
    int col = lane * 4;
#pragma unroll
    for (int kk = 0; kk < 16; kk++) {
        float4 wv = *(const float4*)&sWe[kk * 128 + col];
        float ev = tv[kk];
        acc.x += ev * wv.x;
        acc.y += ev * wv.y;
        acc.z += ev * wv.z;
        acc.w += ev * wv.w;
    }
    ((float4*)(out + (size_t)i * MD))[lane] = acc;
}

// ---------------- launch ----------------
extern "C" void kernel_launch(void* const* d_in, const int* in_sizes, int n_in,
                              void* d_out, int out_size) {
    const float* node_feature    = (const float*)d_in[0];
    const float* edge_attr       = (const float*)d_in[1];
    const float* message_feature = (const float*)d_in[2];
    const int*   edge_index      = (const int*)d_in[3];
    const float* W_node = (const float*)d_in[4];
    const float* b_node = (const float*)d_in[5];
    const float* W_edge = (const float*)d_in[6];
    const float* b_edge = (const float*)d_in[7];
    const float* W_gat  = (const float*)d_in[8];
    const float* att_src = (const float*)d_in[9];
    const float* att_dst = (const float*)d_in[10];
    const float* b_gat  = (const float*)d_in[11];
    const float* W_nbr  = (const float*)d_in[12];
    const float* b_nbr  = (const float*)d_in[13];
    const float* W_self = (const float*)d_in[14];
    const float* b_self = (const float*)d_in[15];
    float* out = (float*)d_out;

    const int GEMM_SMEM = 3 * STAGE_BYTES;   // 110592
    cudaFuncSetAttribute(k_gemm1, cudaFuncAttributeMaxDynamicSharedMemorySize, GEMM_SMEM);
    cudaFuncSetAttribute(k_gemm2, cudaFuncAttributeMaxDynamicSharedMemorySize, GEMM_SMEM);

    // fused prep (A1 convert | node learner | W2 | W1 transpose | zero init)
    k_prep<<<PREP_BLOCKS, 256>>>(message_feature, node_feature, W_node, b_node,
                                 W_gat, W_nbr, W_self);

    // h = mf @ W_gat  (fp16 out, + fused attention scalar partial dots)
    k_gemm1<<<dim3(GATD / 128, NNODE / 128), 256, GEMM_SMEM>>>(att_src, att_dst);

    // softmax structure
    k_edge_alpha<<<(NEDGE + 255) / 256, 256>>>(edge_index);
    k_scan<<<1, 1024>>>();
    k_edge_build<<<(NEDGE + 255) / 256, 256>>>(edge_index);

    // GAT aggregation -> X cols 0:768 (fp16 h rows)
    k_gat_aggr<<<(NNODE * 32 + 255) / 256, 256>>>(b_gat);

    // P = x @ Wcat  (fp16)
    k_gemm2<<<dim3(PD / 128, NNODE / 128), 256, GEMM_SMEM>>>();

    // final per-node aggregation (fused edge learner) -> out
    k_meta<<<(NNODE * 32 + 255) / 256, 256>>>(out, b_nbr, b_self, W_nbr,
                                              W_edge, b_edge, edge_attr);
}

// round 13
// speedup vs baseline: 2.1128x; 1.0606x over previous
#include <cuda_runtime.h>
#include <cuda_fp16.h>
#include <cstdint>

// ---------------- problem constants ----------------
#define NNODE 16000
#define NEDGE 128000
#define GATD 768          // GAT dim
#define XD 800            // meta-in dim (768 gat + 32 node)
#define XDP 832           // padded K for GEMM2 (13 x 64)
#define MD 128            // meta out dim
#define PD 384            // P1(dst part) | P2(src part) | Xself
#define SCAN_BLOCKS 63    // ceil(NNODE/256)

// ---------------- device scratch (no allocs allowed) ----------------
__device__ __half   g_hh[NNODE * GATD];      // h in fp16 (only consumer: gather)
__device__ float    g_P[NNODE * PD];         // 24.6 MB
__device__ float    g_asrc[NNODE];
__device__ float    g_adst[NNODE];
__device__ unsigned g_amax[NNODE];           // ordered-float bits (0 = -inf sentinel)
__device__ float    g_denom[NNODE];
__device__ float    g_alphaE[NEDGE];
__device__ int      g_deg[NNODE];
__device__ int      g_rowstart[NNODE];
__device__ int      g_pos[NNODE];
__device__ int      g_csr_src[NEDGE];
__device__ int      g_csr_eid[NEDGE];
__device__ float    g_csr_ex[NEDGE];
__device__ int      g_bsum[64];
__device__ int      g_bofs[64];
// fp16 operands
__device__ __half g_A1[NNODE * GATD];
__device__ __half g_X[NNODE * XDP];
__device__ __half g_W1[GATD * GATD];   // W_gat^T  [n,k]
__device__ __half g_W2[PD * XDP];      // Wcat^T   [n,k]

// ---------------- helpers ----------------
__device__ __forceinline__ float lrelu(float x) { return x >= 0.f ? x : 0.2f * x; }
__device__ __forceinline__ unsigned f2o(float f) {
    unsigned b = __float_as_uint(f);
    return (b & 0x80000000u) ? ~b : (b | 0x80000000u);
}
__device__ __forceinline__ float o2f(unsigned b) {
    b = (b & 0x80000000u) ? (b & 0x7fffffffu) : ~b;
    return __uint_as_float(b);
}
__device__ __forceinline__ uint32_t smem_u32(const void* p) {
    uint32_t a;
    asm("{ .reg .u64 t; cvta.to.shared.u64 t, %1; cvt.u32.u64 %0, t; }" : "=r"(a) : "l"(p));
    return a;
}
__device__ __forceinline__ void ldm_x4(uint32_t& r0, uint32_t& r1, uint32_t& r2, uint32_t& r3,
                                       uint32_t addr) {
    asm volatile("ldmatrix.sync.aligned.m8n8.x4.shared.b16 {%0,%1,%2,%3}, [%4];"
                 : "=r"(r0), "=r"(r1), "=r"(r2), "=r"(r3) : "r"(addr));
}
__device__ __forceinline__ void mma16816(float* c, const uint32_t* a, uint32_t b0, uint32_t b1) {
    asm volatile(
        "mma.sync.aligned.m16n8k16.row.col.f32.f16.f16.f32 "
        "{%0,%1,%2,%3}, {%4,%5,%6,%7}, {%8,%9}, {%0,%1,%2,%3};"
        : "+f"(c[0]), "+f"(c[1]), "+f"(c[2]), "+f"(c[3])
        : "r"(a[0]), "r"(a[1]), "r"(a[2]), "r"(a[3]), "r"(b0), "r"(b1));
}
__device__ __forceinline__ void cp16(uint32_t dst, const void* src) {
    asm volatile("cp.async.cg.shared.global [%0], [%1], 16;" :: "r"(dst), "l"(src));
}
#define CP_COMMIT() asm volatile("cp.async.commit_group;" ::: "memory")
#define CP_WAIT2()  asm volatile("cp.async.wait_group 2;" ::: "memory")
#define CP_WAIT1()  asm volatile("cp.async.wait_group 1;" ::: "memory")
#define CP_WAIT0()  asm volatile("cp.async.wait_group 0;" ::: "memory")

__device__ __forceinline__ void unpack8(uint4 v, float* f) {
    float2 a = __half22float2(*(__half2*)&v.x);
    float2 b = __half22float2(*(__half2*)&v.y);
    float2 c = __half22float2(*(__half2*)&v.z);
    float2 d = __half22float2(*(__half2*)&v.w);
    f[0] = a.x; f[1] = a.y; f[2] = b.x; f[3] = b.y;
    f[4] = c.x; f[5] = c.y; f[6] = d.x; f[7] = d.y;
}
__device__ __forceinline__ uint4 pack8(const float* f) {
    uint4 o;
    __half2 h0 = __floats2half2_rn(f[0], f[1]);
    __half2 h1 = __floats2half2_rn(f[2], f[3]);
    __half2 h2 = __floats2half2_rn(f[4], f[5]);
    __half2 h3 = __floats2half2_rn(f[6], f[7]);
    o.x = *(uint32_t*)&h0; o.y = *(uint32_t*)&h1;
    o.z = *(uint32_t*)&h2; o.w = *(uint32_t*)&h3;
    return o;
}

// ---------------- fused prep kernel (block-range dispatch) ----------------
#define PREP_B_A1  24000    // cvtA1: NNODE*GATD/2 half2 / 256
#define PREP_B_NL  2000     // nodeL: NNODE*32 / 256
#define PREP_B_W2  1248     // cvtW2: PD*XDP / 256
#define PREP_B_W1  576      // cvtW1: (768/32)^2 tiles
#define PREP_B_Z   63       // zero init: ceil(16000/256)
#define PREP_BLOCKS (PREP_B_A1 + PREP_B_NL + PREP_B_W2 + PREP_B_W1 + PREP_B_Z)

__global__ void k_prep(const float* __restrict__ mf, const float* __restrict__ nf,
                       const float* __restrict__ Wnode, const float* __restrict__ bnode,
                       const float* __restrict__ Wg,
                       const float* __restrict__ Wnbr, const float* __restrict__ Wself) {
    __shared__ float tile[32][33];
    int b = blockIdx.x;
    int t = threadIdx.x;
    if (b < PREP_B_A1) {                       // A1 convert (half2)
        int idx = b * 256 + t;
        float2 v = ((const float2*)mf)[idx];
        ((__half2*)g_A1)[idx] = __floats2half2_rn(v.x, v.y);
        return;
    }
    b -= PREP_B_A1;
    if (b < PREP_B_NL) {                       // node learner -> X cols 768:832
        int idx = b * 256 + t;
        int i = idx >> 5, j = idx & 31;
        const float* r = nf + i * 32;
        float s = bnode[j];
#pragma unroll
        for (int k = 0; k < 32; k++) s += r[k] * Wnode[k * 32 + j];
        size_t base = (size_t)i * XDP;
        g_X[base + 768 + j] = __float2half_rn(s);
        g_X[base + 800 + j] = __float2half(0.f);
        return;
    }
    b -= PREP_B_NL;
    if (b < PREP_B_W2) {                       // W2 build
        int idx = b * 256 + t;
        int n = idx / XDP, k = idx % XDP;
        float v = 0.f;
        if (k < XD) {
            if (n < 128)      v = Wnbr[k * 128 + n];
            else if (n < 256) v = Wnbr[(800 + k) * 128 + (n - 128)];
            else              v = Wself[k * 128 + (n - 256)];
        }
        g_W2[idx] = __float2half_rn(v);
        return;
    }
    b -= PREP_B_W2;
    if (b < PREP_B_W1) {                       // W1 transpose (32x32 tile)
        int tx = t & 31, ty = t >> 5;          // 32 x 8
        int n0 = (b % 24) * 32, k0 = (b / 24) * 32;
#pragma unroll
        for (int i = 0; i < 4; i++)
            tile[ty + i * 8][tx] = Wg[(size_t)(k0 + ty + i * 8) * GATD + n0 + tx];
        __syncthreads();
#pragma unroll
        for (int i = 0; i < 4; i++) {
            size_t o = (size_t)(n0 + ty + i * 8) * GATD + k0 + tx;
            g_W1[o] = __float2half_rn(tile[tx][ty + i * 8]);
        }
        return;
    }
    b -= PREP_B_W1;
    {                                          // zero init
        int i = b * 256 + t;
        if (i < NNODE) {
            g_asrc[i] = 0.f;
            g_adst[i] = 0.f;
            g_amax[i] = 0u;    // below every ordered-float
            g_deg[i] = 0;
        }
    }
}

// ---------------- warp-MMA fp16 GEMM (cp.async 3-stage, K chunk 64) ----------------
#define ASTRIDE 72
#define TILE_BYTES 18432                  // 128*72*2
#define STAGE_BYTES (2 * TILE_BYTES)      // A|B

template <int CN, int KPAD, int NCH, bool DO_ATT, bool HALF_OUT>
__device__ __forceinline__ void mma_gemm_body(const __half* __restrict__ A,
                                              const __half* __restrict__ B,
                                              float* __restrict__ Cf,
                                              __half* __restrict__ Ch,
                                              const float* __restrict__ att_s,
                                              const float* __restrict__ att_d) {
    extern __shared__ char smem[];
    const uint32_t sb = smem_u32(smem);

    const int t = threadIdx.x;
    const int lane = t & 31;
    const int wid = t >> 5;
    const int m0 = (wid >> 2) * 64;
    const int n0 = (wid & 3) * 32;
    const int bm = blockIdx.y * 128;
    const int bn = blockIdx.x * 128;

    const uint32_t aoff = (uint32_t)(((lane & 15) * ASTRIDE + (lane >> 4) * 8) * 2);
    const uint32_t boff = (uint32_t)((((lane & 7) + ((lane >> 4) << 3)) * ASTRIDE +
                                     (((lane >> 3) & 1) << 3)) * 2);

    float acc[4][4][4];
#pragma unroll
    for (int i = 0; i < 4; i++)
#pragma unroll
        for (int j = 0; j < 4; j++)
#pragma unroll
            for (int q = 0; q < 4; q++) acc[i][j][q] = 0.f;

    auto issue_chunk = [&](int c, int s) {
        const int c0 = c * 64;
        const uint32_t dst = sb + (uint32_t)s * STAGE_BYTES;
#pragma unroll
        for (int it = 0; it < 4; it++) {
            int idx = it * 256 + t;
            int r = idx >> 3, j = idx & 7;
            size_t ga = (size_t)(bm + r) * KPAD + c0 + j * 8;
            size_t gb = (size_t)(bn + r) * KPAD + c0 + j * 8;
            uint32_t doff = (uint32_t)((r * ASTRIDE + j * 8) * 2);
            cp16(dst + doff, A + ga);
            cp16(dst + TILE_BYTES + doff, B + gb);
        }
    };

    issue_chunk(0, 0);
    CP_COMMIT();
    issue_chunk(1, 1);
    CP_COMMIT();

    for (int c = 0; c < NCH; c++) {
        const int s = c % 3;
        if (c + 2 < NCH) {
            issue_chunk(c + 2, (c + 2) % 3);
            CP_COMMIT();
            CP_WAIT2();
        } else if (c + 1 < NCH) {
            CP_WAIT1();
        } else {
            CP_WAIT0();
        }
        __syncthreads();

        const uint32_t baseA = sb + (uint32_t)s * STAGE_BYTES;
        const uint32_t baseB = baseA + TILE_BYTES;

#pragma unroll
        for (int ks = 0; ks < 4; ks++) {
            const uint32_t kb = (uint32_t)(ks * 16 * 2);
            uint32_t bh[2][4];
#pragma unroll
            for (int p = 0; p < 2; p++) {
                uint32_t off = boff + (uint32_t)((n0 + p * 16) * ASTRIDE * 2) + kb;
                ldm_x4(bh[p][0], bh[p][1], bh[p][2], bh[p][3], baseB + off);
            }
#pragma unroll
            for (int tm = 0; tm < 4; tm++) {
                uint32_t off = aoff + (uint32_t)((m0 + tm * 16) * ASTRIDE * 2) + kb;
                uint32_t ah[4];
                ldm_x4(ah[0], ah[1], ah[2], ah[3], baseA + off);
#pragma unroll
                for (int tn = 0; tn < 4; tn++) {
                    int p = tn >> 1, q = tn & 1;
                    mma16816(acc[tm][tn], ah, bh[p][q * 2], bh[p][q * 2 + 1]);
                }
            }
        }
        __syncthreads();
    }

    const int rit = lane >> 2;
    const int cq = (lane & 3) * 2;
#pragma unroll
    for (int tm = 0; tm < 4; tm++) {
        float s1a = 0.f, s2a = 0.f, s1b = 0.f, s2b = 0.f;
#pragma unroll
        for (int tn = 0; tn < 4; tn++) {
            size_t row = (size_t)(bm + m0 + tm * 16 + rit);
            int col = bn + n0 + tn * 8 + cq;
            if (HALF_OUT) {
                __half2 v0 = __floats2half2_rn(acc[tm][tn][0], acc[tm][tn][1]);
                __half2 v1 = __floats2half2_rn(acc[tm][tn][2], acc[tm][tn][3]);
                *(__half2*)&Ch[row * CN + col] = v0;
                *(__half2*)&Ch[(row + 8) * CN + col] = v1;
            } else {
                *(float2*)&Cf[row * CN + col] = make_float2(acc[tm][tn][0], acc[tm][tn][1]);
                *(float2*)&Cf[(row + 8) * CN + col] = make_float2(acc[tm][tn][2], acc[tm][tn][3]);
            }
            if (DO_ATT) {
                float a0 = __ldg(att_s + col), a1 = __ldg(att_s + col + 1);
                float d0 = __ldg(att_d + col), d1 = __ldg(att_d + col + 1);
                s1a += acc[tm][tn][0] * a0 + acc[tm][tn][1] * a1;
                s2a += acc[tm][tn][0] * d0 + acc[tm][tn][1] * d1;
                s1b += acc[tm][tn][2] * a0 + acc[tm][tn][3] * a1;
                s2b += acc[tm][tn][2] * d0 + acc[tm][tn][3] * d1;
            }
        }
        if (DO_ATT) {
#pragma unroll
            for (int off = 1; off < 4; off <<= 1) {
                s1a += __shfl_xor_sync(0xffffffffu, s1a, off);
                s2a += __shfl_xor_sync(0xffffffffu, s2a, off);
                s1b += __shfl_xor_sync(0xffffffffu, s1b, off);
                s2b += __shfl_xor_sync(0xffffffffu, s2b, off);
            }
            if ((lane & 3) == 0) {
                int rowA = bm + m0 + tm * 16 + rit;
                atomicAdd(&g_asrc[rowA], s1a);
                atomicAdd(&g_adst[rowA], s2a);
                atomicAdd(&g_asrc[rowA + 8], s1b);
                atomicAdd(&g_adst[rowA + 8], s2b);
            }
        }
    }
}

__global__ void __launch_bounds__(256, 2) k_gemm1(const float* __restrict__ att_s,
                                                  const float* __restrict__ att_d) {
    mma_gemm_body<GATD, GATD, 12, true, true>(g_A1, g_W1, nullptr, g_hh, att_s, att_d);
}
__global__ void __launch_bounds__(256, 2) k_gemm2() {
    mma_gemm_body<PD, XDP, 13, false, false>(g_X, g_W2, g_P, nullptr, nullptr, nullptr);
}

// ---------------- edge alpha pass (deg + amax) ----------------
__global__ void k_edge_alpha(const int* __restrict__ ei) {
    int e = blockIdx.x * blockDim.x + threadIdx.x;
    if (e >= NEDGE) return;
    int s = ei[e], d = ei[NEDGE + e];
    float al = lrelu(g_asrc[s] + g_adst[d]);
    g_alphaE[e] = al;
    atomicMax(&g_amax[d], f2o(al));
    atomicAdd(&g_deg[d], 1);
}

// ---- scan stage 1: per-block inclusive scan of deg + block sums; phase2 amax/denom ----
__global__ void k_scan1() {
    __shared__ int wsum[8];
    int t = threadIdx.x, lane = t & 31, wid = t >> 5;
    int i = blockIdx.x * 256 + t;
    int v = (i < NNODE) ? g_deg[i] : 0;
    int incl = v;
#pragma unroll
    for (int o = 1; o < 32; o <<= 1) {
        int n = __shfl_up_sync(0xffffffffu, incl, o);
        if (lane >= o) incl += n;
    }
    if (lane == 31) wsum[wid] = incl;
    __syncthreads();
    if (wid == 0 && lane < 8) {
        int w = wsum[lane];
        int ws = w;
#pragma unroll
        for (int o = 1; o < 8; o <<= 1) {
            int n = __shfl_up_sync(0xffu, ws, o);
            if (lane >= o) ws += n;
        }
        wsum[lane] = ws - w;   // exclusive across warps
    }
    __syncthreads();
    incl += wsum[wid];
    if (i < NNODE) g_rowstart[i] = incl;               // temp: block-local inclusive
    if (t == 255) g_bsum[blockIdx.x] = incl;
    // phase 2: amax includes self; denom = exp(self - amax)
    if (i < NNODE) {
        float al = lrelu(g_asrc[i] + g_adst[i]);
        float am = fmaxf(o2f(g_amax[i]), al);          // o2f(0)=NaN -> returns al
        g_amax[i] = f2o(am);
        g_denom[i] = expf(al - am);
    }
}

// ---- scan stage 2: exclusive scan of 63 block sums (one warp, 2 elems/lane) ----
__global__ void k_scan2() {
    int lane = threadIdx.x;
    int v0 = (2 * lane     < SCAN_BLOCKS) ? g_bsum[2 * lane]     : 0;
    int v1 = (2 * lane + 1 < SCAN_BLOCKS) ? g_bsum[2 * lane + 1] : 0;
    int p = v0 + v1;
    int incl = p;
#pragma unroll
    for (int o = 1; o < 32; o <<= 1) {
        int n = __shfl_up_sync(0xffffffffu, incl, o);
        if (lane >= o) incl += n;
    }
    int excl = incl - p;
    if (2 * lane < SCAN_BLOCKS)     g_bofs[2 * lane] = excl;
    if (2 * lane + 1 < SCAN_BLOCKS) g_bofs[2 * lane + 1] = excl + v0;
}

// ---- scan stage 3: finalize rowstart/pos ----
__global__ void k_scan3() {
    int i = blockIdx.x * 256 + threadIdx.x;
    if (i >= NNODE) return;
    int excl = g_bofs[blockIdx.x] + g_rowstart[i] - g_deg[i];
    g_rowstart[i] = excl;
    g_pos[i] = excl;
}

// fused CSR fill + exp + denom accumulate
__global__ void k_edge_build(const int* __restrict__ ei) {
    int e = blockIdx.x * blockDim.x + threadIdx.x;
    if (e >= NEDGE) return;
    int s = ei[e], d = ei[NEDGE + e];
    int p = atomicAdd(&g_pos[d], 1);
    g_csr_src[p] = s;
    g_csr_eid[p] = e;
    float ex = expf(g_alphaE[e] - o2f(g_amax[d]));
    g_csr_ex[p] = ex;
    atomicAdd(&g_denom[d], ex);
}

// ---------------- GAT gather-aggregation: warp per node (unroll-2 edges) ----------------
__global__ void k_gat_aggr(const float* __restrict__ b_gat) {
    int warp = (blockIdx.x * blockDim.x + threadIdx.x) >> 5;
    int lane = threadIdx.x & 31;
    if (warp >= NNODE) return;
    int i = warp;
    float amaxv = o2f(g_amax[i]);
    float als = lrelu(g_asrc[i] + g_adst[i]);
    float inv_den = 1.0f / g_denom[i];
    float cs = expf(als - amaxv) * inv_den;

    const uint4* hrow = (const uint4*)(g_hh + (size_t)i * GATD);
    const float4* bg = (const float4*)b_gat;
    float acc[3][8];
#pragma unroll
    for (int t = 0; t < 3; t++) {
        float f[8];
        unpack8(hrow[lane + 32 * t], f);
        float4 b0 = bg[2 * (lane + 32 * t)];
        float4 b1 = bg[2 * (lane + 32 * t) + 1];
        acc[t][0] = cs * f[0] + b0.x; acc[t][1] = cs * f[1] + b0.y;
        acc[t][2] = cs * f[2] + b0.z; acc[t][3] = cs * f[3] + b0.w;
        acc[t][4] = cs * f[4] + b1.x; acc[t][5] = cs * f[5] + b1.y;
        acc[t][6] = cs * f[6] + b1.z; acc[t][7] = cs * f[7] + b1.w;
    }
    int rs = g_rowstart[i], d = g_deg[i];
    for (int base = 0; base < d; base += 32) {
        int cnt = min(32, d - base);
        int sj = 0;
        float cj = 0.f;
        if (lane < cnt) {
            sj = g_csr_src[rs + base + lane];
            cj = g_csr_ex[rs + base + lane] * inv_den;
        }
        int k = 0;
        for (; k + 1 < cnt; k += 2) {
            int s0 = __shfl_sync(0xffffffffu, sj, k);
            int s1 = __shfl_sync(0xffffffffu, sj, k + 1);
            float c0 = __shfl_sync(0xffffffffu, cj, k);
            float c1 = __shfl_sync(0xffffffffu, cj, k + 1);
            const uint4* h0 = (const uint4*)(g_hh + (size_t)s0 * GATD);
            const uint4* h1 = (const uint4*)(g_hh + (size_t)s1 * GATD);
            uint4 r0[3], r1[3];
#pragma unroll
            for (int t = 0; t < 3; t++) {
                r0[t] = __ldg(&h0[lane + 32 * t]);
                r1[t] = __ldg(&h1[lane + 32 * t]);
            }
#pragma unroll
            for (int t = 0; t < 3; t++) {
                float f0[8], f1[8];
                unpack8(r0[t], f0);
                unpack8(r1[t], f1);
#pragma unroll
                for (int q = 0; q < 8; q++) acc[t][q] += c0 * f0[q] + c1 * f1[q];
            }
        }
        if (k < cnt) {
            int s0 = __shfl_sync(0xffffffffu, sj, k);
            float c0 = __shfl_sync(0xffffffffu, cj, k);
            const uint4* h0 = (const uint4*)(g_hh + (size_t)s0 * GATD);
#pragma unroll
            for (int t = 0; t < 3; t++) {
                float f0[8];
                unpack8(__ldg(&h0[lane + 32 * t]), f0);
#pragma unroll
                for (int q = 0; q < 8; q++) acc[t][q] += c0 * f0[q];
            }
        }
    }
    size_t xbase = (size_t)i * XDP;
#pragma unroll
    for (int t = 0; t < 3; t++) {
        *(uint4*)(g_X + xbase + 8 * (lane + 32 * t)) = pack8(acc[t]);
    }
}

// ---------------- final aggregation (fused edge learner + ea@We, unroll-2) ----------------
__global__ void k_meta(float* __restrict__ out, const float* __restrict__ b_nbr,
                       const float* __restrict__ b_self, const float* __restrict__ W_nbr,
                       const float* __restrict__ W_edge, const float* __restrict__ b_edge,
                       const float* __restrict__ edge_attr) {
    __shared__ float sWe[16 * 128];
    __shared__ float sWE[16 * 16];
    __shared__ float sBN[128];
    for (int t = threadIdx.x; t < 2048; t += blockDim.x)
        sWe[t] = W_nbr[1600 * 128 + t];
    for (int t = threadIdx.x; t < 256; t += blockDim.x)
        sWE[t] = W_edge[t];
    __syncthreads();
    if (threadIdx.x < 128) {
        int c = threadIdx.x;
        float s = b_nbr[c];
#pragma unroll
        for (int k = 0; k < 16; k++) s += b_edge[k] * sWe[k * 128 + c];
        sBN[c] = s;
    }
    __syncthreads();

    int warp = (blockIdx.x * blockDim.x + threadIdx.x) >> 5;
    int lane = threadIdx.x & 31;
    if (warp >= NNODE) return;
    int i = warp;
    const float4* Pr = (const float4*)(g_P + (size_t)i * PD);
    float4 p1 = Pr[lane];        // dst-part
    float4 xs = Pr[64 + lane];   // self-part
    float4 bs = ((const float4*)b_self)[lane];
    float4 bn4 = *(const float4*)&sBN[lane * 4];
    float degf = (float)g_deg[i];
    float4 acc;
    acc.x = xs.x + bs.x + degf * (p1.x + bn4.x);
    acc.y = xs.y + bs.y + degf * (p1.y + bn4.y);
    acc.z = xs.z + bs.z + degf * (p1.z + bn4.z);
    acc.w = xs.w + bs.w + degf * (p1.w + bn4.w);

    float eas[16];
#pragma unroll
    for (int k = 0; k < 16; k++) eas[k] = 0.f;

    int rs = g_rowstart[i], d = g_deg[i];
    for (int base = 0; base < d; base += 32) {
        int cnt = min(32, d - base);
        int sj = 0, ej = 0;
        if (lane < cnt) {
            sj = g_csr_src[rs + base + lane];
            ej = g_csr_eid[rs + base + lane];
        }
        int k = 0;
        for (; k + 1 < cnt; k += 2) {
            int s0 = __shfl_sync(0xffffffffu, sj, k);
            int s1 = __shfl_sync(0xffffffffu, sj, k + 1);
            int e0i = __shfl_sync(0xffffffffu, ej, k);
            int e1i = __shfl_sync(0xffffffffu, ej, k + 1);
            float4 p2a = __ldg(&((const float4*)(g_P + (size_t)s0 * PD))[32 + lane]);
            float4 p2b = __ldg(&((const float4*)(g_P + (size_t)s1 * PD))[32 + lane]);
            const float4* ea0 = (const float4*)(edge_attr + (size_t)e0i * 16);
            const float4* ea1 = (const float4*)(edge_attr + (size_t)e1i * 16);
            float4 a0 = __ldg(ea0), a1 = __ldg(ea0 + 1), a2 = __ldg(ea0 + 2), a3 = __ldg(ea0 + 3);
            float4 c0 = __ldg(ea1), c1 = __ldg(ea1 + 1), c2 = __ldg(ea1 + 2), c3 = __ldg(ea1 + 3);
            acc.x += p2a.x + p2b.x;
            acc.y += p2a.y + p2b.y;
            acc.z += p2a.z + p2b.z;
            acc.w += p2a.w + p2b.w;
            eas[0] += a0.x + c0.x;  eas[1] += a0.y + c0.y;  eas[2] += a0.z + c0.z;  eas[3] += a0.w + c0.w;
            eas[4] += a1.x + c1.x;  eas[5] += a1.y + c1.y;  eas[6] += a1.z + c1.z;  eas[7] += a1.w + c1.w;
            eas[8] += a2.x + c2.x;  eas[9] += a2.y + c2.y;  eas[10] += a2.z + c2.z; eas[11] += a2.w + c2.w;
            eas[12] += a3.x + c3.x; eas[13] += a3.y + c3.y; eas[14] += a3.z + c3.z; eas[15] += a3.w + c3.w;
        }
        if (k < cnt) {
            int s0 = __shfl_sync(0xffffffffu, sj, k);
            int e0i = __shfl_sync(0xffffffffu, ej, k);
            float4 p2 = __ldg(&((const float4*)(g_P + (size_t)s0 * PD))[32 + lane]);
            acc.x += p2.x;
            acc.y += p2.y;
            acc.z += p2.z;
            acc.w += p2.w;
            const float4* ear = (const float4*)(edge_attr + (size_t)e0i * 16);
            float4 e0 = __ldg(ear), e1 = __ldg(ear + 1), e2 = __ldg(ear + 2), e3 = __ldg(ear + 3);
            eas[0] += e0.x;  eas[1] += e0.y;  eas[2] += e0.z;  eas[3] += e0.w;
            eas[4] += e1.x;  eas[5] += e1.y;  eas[6] += e1.z;  eas[7] += e1.w;
            eas[8] += e2.x;  eas[9] += e2.y;  eas[10] += e2.z; eas[11] += e2.w;
            eas[12] += e3.x; eas[13] += e3.y; eas[14] += e3.z; eas[15] += e3.w;
        }
    }

    float tv[16];
#pragma unroll
    for (int kk = 0; kk < 16; kk++) {
        float s = 0.f;
#pragma unroll
        for (int j = 0; j < 16; j++) s += eas[j] * sWE[j * 16 + kk];
        tv[kk] = s;
    }
    int col = lane * 4;
#pragma unroll
    for (int kk = 0; kk < 16; kk++) {
        float4 wv = *(const float4*)&sWe[kk * 128 + col];
        float ev = tv[kk];
        acc.x += ev * wv.x;
        acc.y += ev * wv.y;
        acc.z += ev * wv.z;
        acc.w += ev * wv.w;
    }
    ((float4*)(out + (size_t)i * MD))[lane] = acc;
}

// ---------------- launch ----------------
extern "C" void kernel_launch(void* const* d_in, const int* in_sizes, int n_in,
                              void* d_out, int out_size) {
    const float* node_feature    = (const float*)d_in[0];
    const float* edge_attr       = (const float*)d_in[1];
    const float* message_feature = (const float*)d_in[2];
    const int*   edge_index      = (const int*)d_in[3];
    const float* W_node = (const float*)d_in[4];
    const float* b_node = (const float*)d_in[5];
    const float* W_edge = (const float*)d_in[6];
    const float* b_edge = (const float*)d_in[7];
    const float* W_gat  = (const float*)d_in[8];
    const float* att_src = (const float*)d_in[9];
    const float* att_dst = (const float*)d_in[10];
    const float* b_gat  = (const float*)d_in[11];
    const float* W_nbr  = (const float*)d_in[12];
    const float* b_nbr  = (const float*)d_in[13];
    const float* W_self = (const float*)d_in[14];
    const float* b_self = (const float*)d_in[15];
    float* out = (float*)d_out;

    const int GEMM_SMEM = 3 * STAGE_BYTES;   // 110592
    cudaFuncSetAttribute(k_gemm1, cudaFuncAttributeMaxDynamicSharedMemorySize, GEMM_SMEM);
    cudaFuncSetAttribute(k_gemm2, cudaFuncAttributeMaxDynamicSharedMemorySize, GEMM_SMEM);

    // fused prep (A1 convert | node learner | W2 | W1 transpose | zero init)
    k_prep<<<PREP_BLOCKS, 256>>>(message_feature, node_feature, W_node, b_node,
                                 W_gat, W_nbr, W_self);

    // h = mf @ W_gat  (fp16 out, + fused attention scalar partial dots)
    k_gemm1<<<dim3(GATD / 128, NNODE / 128), 256, GEMM_SMEM>>>(att_src, att_dst);

    // softmax structure (parallel 3-stage scan)
    k_edge_alpha<<<(NEDGE + 255) / 256, 256>>>(edge_index);
    k_scan1<<<SCAN_BLOCKS, 256>>>();
    k_scan2<<<1, 32>>>();
    k_scan3<<<SCAN_BLOCKS, 256>>>();
    k_edge_build<<<(NEDGE + 255) / 256, 256>>>(edge_index);

    // GAT aggregation -> X cols 0:768 (fp16 h rows)
    k_gat_aggr<<<(NNODE * 32 + 255) / 256, 256>>>(b_gat);

    // P = x @ Wcat  (fp16)
    k_gemm2<<<dim3(PD / 128, NNODE / 128), 256, GEMM_SMEM>>>();

    // final per-node aggregation (fused edge learner) -> out
    k_meta<<<(NNODE * 32 + 255) / 256, 256>>>(out, b_nbr, b_self, W_nbr,
                                              W_edge, b_edge, edge_attr);
}

// round 14
// speedup vs baseline: 2.2405x; 1.0604x over previous
#include <cuda_runtime.h>
#include <cuda_fp16.h>
#include <cstdint>

// ---------------- problem constants ----------------
#define NNODE 16000
#define NEDGE 128000
#define GATD 768          // GAT dim
#define XD 800            // meta-in dim (768 gat + 32 node)
#define XDP 832           // padded K for GEMM2 (13 x 64)
#define MD 128            // meta out dim
#define PD 384            // P1(dst part) | P2(src part) | Xself
#define SCAN_BLOCKS 63    // ceil(NNODE/256)

// ---------------- device scratch (no allocs allowed) ----------------
__device__ __half   g_hh[NNODE * GATD];      // h in fp16 (only consumer: gather)
__device__ float    g_P[NNODE * PD];         // 24.6 MB
__device__ float    g_asrc[NNODE];
__device__ float    g_adst[NNODE];
__device__ unsigned g_amax[NNODE];           // ordered-float bits (0 = -inf sentinel)
__device__ float    g_denom[NNODE];
__device__ float    g_alphaE[NEDGE];
__device__ int      g_deg[NNODE];
__device__ int      g_rowstart[NNODE];
__device__ int      g_pos[NNODE];
__device__ int      g_csr_src[NEDGE];
__device__ int      g_csr_eid[NEDGE];
__device__ float    g_csr_ex[NEDGE];
__device__ int      g_bsum[64];
__device__ int      g_bofs[64];
// fp16 operands
__device__ __half g_A1[NNODE * GATD];
__device__ __half g_X[NNODE * XDP];
__device__ __half g_W1[GATD * GATD];   // W_gat^T  [n,k]
__device__ __half g_W2[PD * XDP];      // Wcat^T   [n,k]

// ---------------- helpers ----------------
__device__ __forceinline__ float lrelu(float x) { return x >= 0.f ? x : 0.2f * x; }
__device__ __forceinline__ unsigned f2o(float f) {
    unsigned b = __float_as_uint(f);
    return (b & 0x80000000u) ? ~b : (b | 0x80000000u);
}
__device__ __forceinline__ float o2f(unsigned b) {
    b = (b & 0x80000000u) ? (b & 0x7fffffffu) : ~b;
    return __uint_as_float(b);
}
__device__ __forceinline__ uint32_t smem_u32(const void* p) {
    uint32_t a;
    asm("{ .reg .u64 t; cvta.to.shared.u64 t, %1; cvt.u32.u64 %0, t; }" : "=r"(a) : "l"(p));
    return a;
}
__device__ __forceinline__ void ldm_x4(uint32_t& r0, uint32_t& r1, uint32_t& r2, uint32_t& r3,
                                       uint32_t addr) {
    asm volatile("ldmatrix.sync.aligned.m8n8.x4.shared.b16 {%0,%1,%2,%3}, [%4];"
                 : "=r"(r0), "=r"(r1), "=r"(r2), "=r"(r3) : "r"(addr));
}
__device__ __forceinline__ void mma16816(float* c, const uint32_t* a, uint32_t b0, uint32_t b1) {
    asm volatile(
        "mma.sync.aligned.m16n8k16.row.col.f32.f16.f16.f32 "
        "{%0,%1,%2,%3}, {%4,%5,%6,%7}, {%8,%9}, {%0,%1,%2,%3};"
        : "+f"(c[0]), "+f"(c[1]), "+f"(c[2]), "+f"(c[3])
        : "r"(a[0]), "r"(a[1]), "r"(a[2]), "r"(a[3]), "r"(b0), "r"(b1));
}
__device__ __forceinline__ void cp16(uint32_t dst, const void* src) {
    asm volatile("cp.async.cg.shared.global [%0], [%1], 16;" :: "r"(dst), "l"(src));
}
#define CP_COMMIT() asm volatile("cp.async.commit_group;" ::: "memory")
#define CP_WAIT2()  asm volatile("cp.async.wait_group 2;" ::: "memory")
#define CP_WAIT1()  asm volatile("cp.async.wait_group 1;" ::: "memory")
#define CP_WAIT0()  asm volatile("cp.async.wait_group 0;" ::: "memory")

__device__ __forceinline__ void unpack8(uint4 v, float* f) {
    float2 a = __half22float2(*(__half2*)&v.x);
    float2 b = __half22float2(*(__half2*)&v.y);
    float2 c = __half22float2(*(__half2*)&v.z);
    float2 d = __half22float2(*(__half2*)&v.w);
    f[0] = a.x; f[1] = a.y; f[2] = b.x; f[3] = b.y;
    f[4] = c.x; f[5] = c.y; f[6] = d.x; f[7] = d.y;
}
__device__ __forceinline__ uint4 pack8(const float* f) {
    uint4 o;
    __half2 h0 = __floats2half2_rn(f[0], f[1]);
    __half2 h1 = __floats2half2_rn(f[2], f[3]);
    __half2 h2 = __floats2half2_rn(f[4], f[5]);
    __half2 h3 = __floats2half2_rn(f[6], f[7]);
    o.x = *(uint32_t*)&h0; o.y = *(uint32_t*)&h1;
    o.z = *(uint32_t*)&h2; o.w = *(uint32_t*)&h3;
    return o;
}

// ---------------- fused prep kernel (block-range dispatch) ----------------
#define PREP_B_A1  12000    // cvtA1: NNODE*GATD/4 float4 / 256
#define PREP_B_NL  2000     // nodeL: NNODE*32 / 256
#define PREP_B_W2  1248     // cvtW2: PD*XDP / 256
#define PREP_B_W1  576      // cvtW1: (768/32)^2 tiles
#define PREP_B_Z   63       // zero init: ceil(16000/256)
#define PREP_BLOCKS (PREP_B_A1 + PREP_B_NL + PREP_B_W2 + PREP_B_W1 + PREP_B_Z)

__global__ void k_prep(const float* __restrict__ mf, const float* __restrict__ nf,
                       const float* __restrict__ Wnode, const float* __restrict__ bnode,
                       const float* __restrict__ Wg,
                       const float* __restrict__ Wnbr, const float* __restrict__ Wself) {
    __shared__ float tile[32][33];
    int b = blockIdx.x;
    int t = threadIdx.x;
    if (b < PREP_B_A1) {                       // A1 convert (float4 -> half2x2)
        int idx = b * 256 + t;
        float4 v = ((const float4*)mf)[idx];
        __half2 h0 = __floats2half2_rn(v.x, v.y);
        __half2 h1 = __floats2half2_rn(v.z, v.w);
        uint2 o;
        o.x = *(uint32_t*)&h0;
        o.y = *(uint32_t*)&h1;
        ((uint2*)g_A1)[idx] = o;
        return;
    }
    b -= PREP_B_A1;
    if (b < PREP_B_NL) {                       // node learner -> X cols 768:832
        int idx = b * 256 + t;
        int i = idx >> 5, j = idx & 31;
        const float* r = nf + i * 32;
        float s = bnode[j];
#pragma unroll
        for (int k = 0; k < 32; k++) s += r[k] * Wnode[k * 32 + j];
        size_t base = (size_t)i * XDP;
        g_X[base + 768 + j] = __float2half_rn(s);
        g_X[base + 800 + j] = __float2half(0.f);
        return;
    }
    b -= PREP_B_NL;
    if (b < PREP_B_W2) {                       // W2 build
        int idx = b * 256 + t;
        int n = idx / XDP, k = idx % XDP;
        float v = 0.f;
        if (k < XD) {
            if (n < 128)      v = Wnbr[k * 128 + n];
            else if (n < 256) v = Wnbr[(800 + k) * 128 + (n - 128)];
            else              v = Wself[k * 128 + (n - 256)];
        }
        g_W2[idx] = __float2half_rn(v);
        return;
    }
    b -= PREP_B_W2;
    if (b < PREP_B_W1) {                       // W1 transpose (32x32 tile)
        int tx = t & 31, ty = t >> 5;          // 32 x 8
        int n0 = (b % 24) * 32, k0 = (b / 24) * 32;
#pragma unroll
        for (int i = 0; i < 4; i++)
            tile[ty + i * 8][tx] = Wg[(size_t)(k0 + ty + i * 8) * GATD + n0 + tx];
        __syncthreads();
#pragma unroll
        for (int i = 0; i < 4; i++) {
            size_t o = (size_t)(n0 + ty + i * 8) * GATD + k0 + tx;
            g_W1[o] = __float2half_rn(tile[tx][ty + i * 8]);
        }
        return;
    }
    b -= PREP_B_W1;
    {                                          // zero init
        int i = b * 256 + t;
        if (i < NNODE) {
            g_asrc[i] = 0.f;
            g_adst[i] = 0.f;
            g_amax[i] = 0u;    // below every ordered-float
            g_deg[i] = 0;
        }
    }
}

// ---------------- warp-MMA fp16 GEMM (cp.async 3-stage, K chunk 64) ----------------
#define ASTRIDE 72
#define TILE_BYTES 18432                  // 128*72*2
#define STAGE_BYTES (2 * TILE_BYTES)      // A|B

template <int CN, int KPAD, int NCH, bool DO_ATT, bool HALF_OUT>
__device__ __forceinline__ void mma_gemm_body(const __half* __restrict__ A,
                                              const __half* __restrict__ B,
                                              float* __restrict__ Cf,
                                              __half* __restrict__ Ch,
                                              const float* __restrict__ att_s,
                                              const float* __restrict__ att_d) {
    extern __shared__ char smem[];
    const uint32_t sb = smem_u32(smem);

    const int t = threadIdx.x;
    const int lane = t & 31;
    const int wid = t >> 5;
    const int m0 = (wid >> 2) * 64;
    const int n0 = (wid & 3) * 32;
    const int bm = blockIdx.y * 128;
    const int bn = blockIdx.x * 128;

    const uint32_t aoff = (uint32_t)(((lane & 15) * ASTRIDE + (lane >> 4) * 8) * 2);
    const uint32_t boff = (uint32_t)((((lane & 7) + ((lane >> 4) << 3)) * ASTRIDE +
                                     (((lane >> 3) & 1) << 3)) * 2);

    float acc[4][4][4];
#pragma unroll
    for (int i = 0; i < 4; i++)
#pragma unroll
        for (int j = 0; j < 4; j++)
#pragma unroll
            for (int q = 0; q < 4; q++) acc[i][j][q] = 0.f;

    auto issue_chunk = [&](int c, int s) {
        const int c0 = c * 64;
        const uint32_t dst = sb + (uint32_t)s * STAGE_BYTES;
#pragma unroll
        for (int it = 0; it < 4; it++) {
            int idx = it * 256 + t;
            int r = idx >> 3, j = idx & 7;
            size_t ga = (size_t)(bm + r) * KPAD + c0 + j * 8;
            size_t gb = (size_t)(bn + r) * KPAD + c0 + j * 8;
            uint32_t doff = (uint32_t)((r * ASTRIDE + j * 8) * 2);
            cp16(dst + doff, A + ga);
            cp16(dst + TILE_BYTES + doff, B + gb);
        }
    };

    issue_chunk(0, 0);
    CP_COMMIT();
    issue_chunk(1, 1);
    CP_COMMIT();

    for (int c = 0; c < NCH; c++) {
        const int s = c % 3;
        if (c + 2 < NCH) {
            issue_chunk(c + 2, (c + 2) % 3);
            CP_COMMIT();
            CP_WAIT2();
        } else if (c + 1 < NCH) {
            CP_WAIT1();
        } else {
            CP_WAIT0();
        }
        __syncthreads();

        const uint32_t baseA = sb + (uint32_t)s * STAGE_BYTES;
        const uint32_t baseB = baseA + TILE_BYTES;

#pragma unroll
        for (int ks = 0; ks < 4; ks++) {
            const uint32_t kb = (uint32_t)(ks * 16 * 2);
            uint32_t bh[2][4];
#pragma unroll
            for (int p = 0; p < 2; p++) {
                uint32_t off = boff + (uint32_t)((n0 + p * 16) * ASTRIDE * 2) + kb;
                ldm_x4(bh[p][0], bh[p][1], bh[p][2], bh[p][3], baseB + off);
            }
#pragma unroll
            for (int tm = 0; tm < 4; tm++) {
                uint32_t off = aoff + (uint32_t)((m0 + tm * 16) * ASTRIDE * 2) + kb;
                uint32_t ah[4];
                ldm_x4(ah[0], ah[1], ah[2], ah[3], baseA + off);
#pragma unroll
                for (int tn = 0; tn < 4; tn++) {
                    int p = tn >> 1, q = tn & 1;
                    mma16816(acc[tm][tn], ah, bh[p][q * 2], bh[p][q * 2 + 1]);
                }
            }
        }
        __syncthreads();
    }

    const int rit = lane >> 2;
    const int cq = (lane & 3) * 2;
#pragma unroll
    for (int tm = 0; tm < 4; tm++) {
        float s1a = 0.f, s2a = 0.f, s1b = 0.f, s2b = 0.f;
#pragma unroll
        for (int tn = 0; tn < 4; tn++) {
            size_t row = (size_t)(bm + m0 + tm * 16 + rit);
            int col = bn + n0 + tn * 8 + cq;
            if (HALF_OUT) {
                __half2 v0 = __floats2half2_rn(acc[tm][tn][0], acc[tm][tn][1]);
                __half2 v1 = __floats2half2_rn(acc[tm][tn][2], acc[tm][tn][3]);
                *(__half2*)&Ch[row * CN + col] = v0;
                *(__half2*)&Ch[(row + 8) * CN + col] = v1;
            } else {
                *(float2*)&Cf[row * CN + col] = make_float2(acc[tm][tn][0], acc[tm][tn][1]);
                *(float2*)&Cf[(row + 8) * CN + col] = make_float2(acc[tm][tn][2], acc[tm][tn][3]);
            }
            if (DO_ATT) {
                float a0 = __ldg(att_s + col), a1 = __ldg(att_s + col + 1);
                float d0 = __ldg(att_d + col), d1 = __ldg(att_d + col + 1);
                s1a += acc[tm][tn][0] * a0 + acc[tm][tn][1] * a1;
                s2a += acc[tm][tn][0] * d0 + acc[tm][tn][1] * d1;
                s1b += acc[tm][tn][2] * a0 + acc[tm][tn][3] * a1;
                s2b += acc[tm][tn][2] * d0 + acc[tm][tn][3] * d1;
            }
        }
        if (DO_ATT) {
#pragma unroll
            for (int off = 1; off < 4; off <<= 1) {
                s1a += __shfl_xor_sync(0xffffffffu, s1a, off);
                s2a += __shfl_xor_sync(0xffffffffu, s2a, off);
                s1b += __shfl_xor_sync(0xffffffffu, s1b, off);
                s2b += __shfl_xor_sync(0xffffffffu, s2b, off);
            }
            if ((lane & 3) == 0) {
                int rowA = bm + m0 + tm * 16 + rit;
                atomicAdd(&g_asrc[rowA], s1a);
                atomicAdd(&g_adst[rowA], s2a);
                atomicAdd(&g_asrc[rowA + 8], s1b);
                atomicAdd(&g_adst[rowA + 8], s2b);
            }
        }
    }
}

__global__ void __launch_bounds__(256, 2) k_gemm1(const float* __restrict__ att_s,
                                                  const float* __restrict__ att_d) {
    mma_gemm_body<GATD, GATD, 12, true, true>(g_A1, g_W1, nullptr, g_hh, att_s, att_d);
}
__global__ void __launch_bounds__(256, 2) k_gemm2() {
    mma_gemm_body<PD, XDP, 13, false, false>(g_X, g_W2, g_P, nullptr, nullptr, nullptr);
}

// ---------------- edge alpha pass (deg + amax) ----------------
__global__ void k_edge_alpha(const int* __restrict__ ei) {
    int e = blockIdx.x * blockDim.x + threadIdx.x;
    if (e >= NEDGE) return;
    int s = ei[e], d = ei[NEDGE + e];
    float al = lrelu(g_asrc[s] + g_adst[d]);
    g_alphaE[e] = al;
    atomicMax(&g_amax[d], f2o(al));
    atomicAdd(&g_deg[d], 1);
}

// ---- scan stage 1: per-block inclusive scan of deg + block sums; phase2 amax/denom ----
__global__ void k_scan1() {
    __shared__ int wsum[8];
    int t = threadIdx.x, lane = t & 31, wid = t >> 5;
    int i = blockIdx.x * 256 + t;
    int v = (i < NNODE) ? g_deg[i] : 0;
    int incl = v;
#pragma unroll
    for (int o = 1; o < 32; o <<= 1) {
        int n = __shfl_up_sync(0xffffffffu, incl, o);
        if (lane >= o) incl += n;
    }
    if (lane == 31) wsum[wid] = incl;
    __syncthreads();
    if (wid == 0 && lane < 8) {
        int w = wsum[lane];
        int ws = w;
#pragma unroll
        for (int o = 1; o < 8; o <<= 1) {
            int n = __shfl_up_sync(0xffu, ws, o);
            if (lane >= o) ws += n;
        }
        wsum[lane] = ws - w;   // exclusive across warps
    }
    __syncthreads();
    incl += wsum[wid];
    if (i < NNODE) g_rowstart[i] = incl;               // temp: block-local inclusive
    if (t == 255) g_bsum[blockIdx.x] = incl;
    // phase 2: amax includes self; denom = exp(self - amax)
    if (i < NNODE) {
        float al = lrelu(g_asrc[i] + g_adst[i]);
        float am = fmaxf(o2f(g_amax[i]), al);          // o2f(0)=NaN -> returns al
        g_amax[i] = f2o(am);
        g_denom[i] = expf(al - am);
    }
}

// ---- scan stage 2: exclusive scan of 63 block sums (one warp, 2 elems/lane) ----
__global__ void k_scan2() {
    int lane = threadIdx.x;
    int v0 = (2 * lane     < SCAN_BLOCKS) ? g_bsum[2 * lane]     : 0;
    int v1 = (2 * lane + 1 < SCAN_BLOCKS) ? g_bsum[2 * lane + 1] : 0;
    int p = v0 + v1;
    int incl = p;
#pragma unroll
    for (int o = 1; o < 32; o <<= 1) {
        int n = __shfl_up_sync(0xffffffffu, incl, o);
        if (lane >= o) incl += n;
    }
    int excl = incl - p;
    if (2 * lane < SCAN_BLOCKS)     g_bofs[2 * lane] = excl;
    if (2 * lane + 1 < SCAN_BLOCKS) g_bofs[2 * lane + 1] = excl + v0;
}

// ---- scan stage 3: finalize rowstart/pos ----
__global__ void k_scan3() {
    int i = blockIdx.x * 256 + threadIdx.x;
    if (i >= NNODE) return;
    int excl = g_bofs[blockIdx.x] + g_rowstart[i] - g_deg[i];
    g_rowstart[i] = excl;
    g_pos[i] = excl;
}

// fused CSR fill + exp + denom accumulate
__global__ void k_edge_build(const int* __restrict__ ei) {
    int e = blockIdx.x * blockDim.x + threadIdx.x;
    if (e >= NEDGE) return;
    int s = ei[e], d = ei[NEDGE + e];
    int p = atomicAdd(&g_pos[d], 1);
    g_csr_src[p] = s;
    g_csr_eid[p] = e;
    float ex = expf(g_alphaE[e] - o2f(g_amax[d]));
    g_csr_ex[p] = ex;
    atomicAdd(&g_denom[d], ex);
}

// ---------------- GAT gather-aggregation: warp per node (unroll-4 edges) ----------------
__global__ void k_gat_aggr(const float* __restrict__ b_gat) {
    int warp = (blockIdx.x * blockDim.x + threadIdx.x) >> 5;
    int lane = threadIdx.x & 31;
    if (warp >= NNODE) return;
    int i = warp;
    float amaxv = o2f(g_amax[i]);
    float als = lrelu(g_asrc[i] + g_adst[i]);
    float inv_den = 1.0f / g_denom[i];
    float cs = expf(als - amaxv) * inv_den;

    const uint4* hrow = (const uint4*)(g_hh + (size_t)i * GATD);
    const float4* bg = (const float4*)b_gat;
    float acc[3][8];
#pragma unroll
    for (int t = 0; t < 3; t++) {
        float f[8];
        unpack8(hrow[lane + 32 * t], f);
        float4 b0 = bg[2 * (lane + 32 * t)];
        float4 b1 = bg[2 * (lane + 32 * t) + 1];
        acc[t][0] = cs * f[0] + b0.x; acc[t][1] = cs * f[1] + b0.y;
        acc[t][2] = cs * f[2] + b0.z; acc[t][3] = cs * f[3] + b0.w;
        acc[t][4] = cs * f[4] + b1.x; acc[t][5] = cs * f[5] + b1.y;
        acc[t][6] = cs * f[6] + b1.z; acc[t][7] = cs * f[7] + b1.w;
    }
    int rs = g_rowstart[i], d = g_deg[i];
    for (int base = 0; base < d; base += 32) {
        int cnt = min(32, d - base);
        int sj = 0;
        float cj = 0.f;
        if (lane < cnt) {
            sj = g_csr_src[rs + base + lane];
            cj = g_csr_ex[rs + base + lane] * inv_den;
        }
        int k = 0;
        for (; k + 3 < cnt; k += 4) {
            int ss[4];
            float cc[4];
#pragma unroll
            for (int u = 0; u < 4; u++) {
                ss[u] = __shfl_sync(0xffffffffu, sj, k + u);
                cc[u] = __shfl_sync(0xffffffffu, cj, k + u);
            }
            uint4 r[4][3];
#pragma unroll
            for (int u = 0; u < 4; u++) {
                const uint4* hp = (const uint4*)(g_hh + (size_t)ss[u] * GATD);
#pragma unroll
                for (int t = 0; t < 3; t++) r[u][t] = __ldg(&hp[lane + 32 * t]);
            }
#pragma unroll
            for (int u = 0; u < 4; u++)
#pragma unroll
                for (int t = 0; t < 3; t++) {
                    float f[8];
                    unpack8(r[u][t], f);
#pragma unroll
                    for (int q = 0; q < 8; q++) acc[t][q] += cc[u] * f[q];
                }
        }
        for (; k < cnt; k++) {
            int s0 = __shfl_sync(0xffffffffu, sj, k);
            float c0 = __shfl_sync(0xffffffffu, cj, k);
            const uint4* h0 = (const uint4*)(g_hh + (size_t)s0 * GATD);
#pragma unroll
            for (int t = 0; t < 3; t++) {
                float f0[8];
                unpack8(__ldg(&h0[lane + 32 * t]), f0);
#pragma unroll
                for (int q = 0; q < 8; q++) acc[t][q] += c0 * f0[q];
            }
        }
    }
    size_t xbase = (size_t)i * XDP;
#pragma unroll
    for (int t = 0; t < 3; t++) {
        *(uint4*)(g_X + xbase + 8 * (lane + 32 * t)) = pack8(acc[t]);
    }
}

// ---------------- final aggregation: per-lane ea accumulation + unroll-4 P2 gather ----------------
__global__ void k_meta(float* __restrict__ out, const float* __restrict__ b_nbr,
                       const float* __restrict__ b_self, const float* __restrict__ W_nbr,
                       const float* __restrict__ W_edge, const float* __restrict__ b_edge,
                       const float* __restrict__ edge_attr) {
    __shared__ float sWe[16 * 128];
    __shared__ float sWE[16 * 16];
    __shared__ float sBN[128];
    for (int t = threadIdx.x; t < 2048; t += blockDim.x)
        sWe[t] = W_nbr[1600 * 128 + t];
    for (int t = threadIdx.x; t < 256; t += blockDim.x)
        sWE[t] = W_edge[t];
    __syncthreads();
    if (threadIdx.x < 128) {
        int c = threadIdx.x;
        float s = b_nbr[c];
#pragma unroll
        for (int k = 0; k < 16; k++) s += b_edge[k] * sWe[k * 128 + c];
        sBN[c] = s;
    }
    __syncthreads();

    int warp = (blockIdx.x * blockDim.x + threadIdx.x) >> 5;
    int lane = threadIdx.x & 31;
    if (warp >= NNODE) return;
    int i = warp;
    const float4* Pr = (const float4*)(g_P + (size_t)i * PD);
    float4 p1 = Pr[lane];        // dst-part
    float4 xs = Pr[64 + lane];   // self-part
    float4 bs = ((const float4*)b_self)[lane];
    float4 bn4 = *(const float4*)&sBN[lane * 4];
    float degf = (float)g_deg[i];
    float4 acc;
    acc.x = xs.x + bs.x + degf * (p1.x + bn4.x);
    acc.y = xs.y + bs.y + degf * (p1.y + bn4.y);
    acc.z = xs.z + bs.z + degf * (p1.z + bn4.z);
    acc.w = xs.w + bs.w + degf * (p1.w + bn4.w);

    float eas[16];
#pragma unroll
    for (int k = 0; k < 16; k++) eas[k] = 0.f;

    int rs = g_rowstart[i], d = g_deg[i];
    for (int base = 0; base < d; base += 32) {
        int cnt = min(32, d - base);
        int sj = 0;
        if (lane < cnt) {
            sj = g_csr_src[rs + base + lane];
            // per-lane ea accumulation (own edge only)
            int ej = g_csr_eid[rs + base + lane];
            const float4* ear = (const float4*)(edge_attr + (size_t)ej * 16);
            float4 e0 = __ldg(ear), e1 = __ldg(ear + 1), e2 = __ldg(ear + 2), e3 = __ldg(ear + 3);
            eas[0] += e0.x;  eas[1] += e0.y;  eas[2] += e0.z;  eas[3] += e0.w;
            eas[4] += e1.x;  eas[5] += e1.y;  eas[6] += e1.z;  eas[7] += e1.w;
            eas[8] += e2.x;  eas[9] += e2.y;  eas[10] += e2.z; eas[11] += e2.w;
            eas[12] += e3.x; eas[13] += e3.y; eas[14] += e3.z; eas[15] += e3.w;
        }
        int k = 0;
        for (; k + 3 < cnt; k += 4) {
            int ss[4];
#pragma unroll
            for (int u = 0; u < 4; u++) ss[u] = __shfl_sync(0xffffffffu, sj, k + u);
            float4 p2[4];
#pragma unroll
            for (int u = 0; u < 4; u++)
                p2[u] = __ldg(&((const float4*)(g_P + (size_t)ss[u] * PD))[32 + lane]);
#pragma unroll
            for (int u = 0; u < 4; u++) {
                acc.x += p2[u].x;
                acc.y += p2[u].y;
                acc.z += p2[u].z;
                acc.w += p2[u].w;
            }
        }
        for (; k < cnt; k++) {
            int s0 = __shfl_sync(0xffffffffu, sj, k);
            float4 p2 = __ldg(&((const float4*)(g_P + (size_t)s0 * PD))[32 + lane]);
            acc.x += p2.x;
            acc.y += p2.y;
            acc.z += p2.z;
            acc.w += p2.w;
        }
    }

    // reduce per-lane ea partials across the warp (all lanes end with full sum)
#pragma unroll
    for (int o = 16; o > 0; o >>= 1)
#pragma unroll
        for (int kk = 0; kk < 16; kk++)
            eas[kk] += __shfl_xor_sync(0xffffffffu, eas[kk], o);

    float tv[16];
#pragma unroll
    for (int kk = 0; kk < 16; kk++) {
        float s = 0.f;
#pragma unroll
        for (int j = 0; j < 16; j++) s += eas[j] * sWE[j * 16 + kk];
        tv[kk] = s;
    }
    int col = lane * 4;
#pragma unroll
    for (int kk = 0; kk < 16; kk++) {
        float4 wv = *(const float4*)&sWe[kk * 128 + col];
        float ev = tv[kk];
        acc.x += ev * wv.x;
        acc.y += ev * wv.y;
        acc.z += ev * wv.z;
        acc.w += ev * wv.w;
    }
    ((float4*)(out + (size_t)i * MD))[lane] = acc;
}

// ---------------- launch ----------------
extern "C" void kernel_launch(void* const* d_in, const int* in_sizes, int n_in,
                              void* d_out, int out_size) {
    const float* node_feature    = (const float*)d_in[0];
    const float* edge_attr       = (const float*)d_in[1];
    const float* message_feature = (const float*)d_in[2];
    const int*   edge_index      = (const int*)d_in[3];
    const float* W_node = (const float*)d_in[4];
    const float* b_node = (const float*)d_in[5];
    const float* W_edge = (const float*)d_in[6];
    const float* b_edge = (const float*)d_in[7];
    const float* W_gat  = (const float*)d_in[8];
    const float* att_src = (const float*)d_in[9];
    const float* att_dst = (const float*)d_in[10];
    const float* b_gat  = (const float*)d_in[11];
    const float* W_nbr  = (const float*)d_in[12];
    const float* b_nbr  = (const float*)d_in[13];
    const float* W_self = (const float*)d_in[14];
    const float* b_self = (const float*)d_in[15];
    float* out = (float*)d_out;

    const int GEMM_SMEM = 3 * STAGE_BYTES;   // 110592
    cudaFuncSetAttribute(k_gemm1, cudaFuncAttributeMaxDynamicSharedMemorySize, GEMM_SMEM);
    cudaFuncSetAttribute(k_gemm2, cudaFuncAttributeMaxDynamicSharedMemorySize, GEMM_SMEM);

    // fused prep (A1 convert | node learner | W2 | W1 transpose | zero init)
    k_prep<<<PREP_BLOCKS, 256>>>(message_feature, node_feature, W_node, b_node,
                                 W_gat, W_nbr, W_self);

    // h = mf @ W_gat  (fp16 out, + fused attention scalar partial dots)
    k_gemm1<<<dim3(GATD / 128, NNODE / 128), 256, GEMM_SMEM>>>(att_src, att_dst);

    // softmax structure (parallel 3-stage scan)
    k_edge_alpha<<<(NEDGE + 255) / 256, 256>>>(edge_index);
    k_scan1<<<SCAN_BLOCKS, 256>>>();
    k_scan2<<<1, 32>>>();
    k_scan3<<<SCAN_BLOCKS, 256>>>();
    k_edge_build<<<(NEDGE + 255) / 256, 256>>>(edge_index);

    // GAT aggregation -> X cols 0:768 (fp16 h rows)
    k_gat_aggr<<<(NNODE * 32 + 255) / 256, 256>>>(b_gat);

    // P = x @ Wcat  (fp16)
    k_gemm2<<<dim3(PD / 128, NNODE / 128), 256, GEMM_SMEM>>>();

    // final per-node aggregation (fused edge learner) -> out
    k_meta<<<(NNODE * 32 + 255) / 256, 256>>>(out, b_nbr, b_self, W_nbr,
                                              W_edge, b_edge, edge_attr);
}